// round 4
// baseline (speedup 1.0000x reference)
#include <cuda_runtime.h>
#include <math.h>

#define BB 32
#define NN 8192
#define NC 256
#define NP 32
#define MTOT (BB * NC)          // 8192 patches

// ---------------- scratch (device globals; no allocation allowed) ----------
__device__ float    g_centers[BB * NC * 3];
__device__ float    g_local  [MTOT * NP * 3];
__device__ float    g_cmean  [MTOT * 3];
__device__ unsigned g_scale_bits;
__device__ float    g_codeT [256 * MTOT];      // code transposed [c][m]
__device__ float    g_base1 [MTOT * 256];      // [m][c]
__device__ float    g_base2 [MTOT * 256];      // [m][c]

// ---------------- packed fp32x2 helpers (sm_100+) ---------------------------
__device__ __forceinline__ unsigned long long pack2(float w) {
    unsigned long long r;
    asm("mov.b64 %0, {%1, %1};" : "=l"(r) : "f"(w));
    return r;
}
__device__ __forceinline__ void fma2(unsigned long long& acc,
                                     unsigned long long a, unsigned long long b) {
    asm("fma.rn.f32x2 %0, %1, %2, %0;" : "+l"(acc) : "l"(a), "l"(b));
}
__device__ __forceinline__ float2 unpack2(unsigned long long v) {
    float2 r;
    asm("mov.b64 {%0, %1}, %2;" : "=f"(r.x), "=f"(r.y) : "l"(v));
    return r;
}

// ============================================================================
// K1: Farthest Point Sampling — one block per batch, points/mind in registers.
// Block argmax: per-warp shfl reduce on packed 64-bit keys -> 32 smem slots ->
// warp0 shfl reduce. NO atomics (the round-3 smem atomicMax chain serialized
// 32 warps x 32cyc per iteration). Exact jnp.argmax tie semantics via key =
// (value_bits << 32) | (NN-1-idx). Distance arithmetic replicates reference.
// ============================================================================
__global__ __launch_bounds__(1024, 1)
void fps_kernel(const float* __restrict__ data)
{
    extern __shared__ float sm[];
    float* sx = sm;
    float* sy = sm + NN;
    float* sz = sm + 2 * NN;
    __shared__ unsigned long long skeys[32];
    __shared__ unsigned long long sres;

    const int b = blockIdx.x;
    const int t = threadIdx.x;
    const int wid = t >> 5, lane = t & 31;
    if (b == 0 && t == 0) g_scale_bits = 0u;   // reset every launch (graph replay safe)

    const float* dp = data + (size_t)b * 3 * NN;
    for (int n = t; n < NN; n += 1024) {
        sx[n] = dp[n];
        sy[n] = dp[NN + n];
        sz[n] = dp[2 * NN + n];
    }
    __syncthreads();

    float rx[8], ry[8], rz[8], md[8];
    const int base = t * 8;
    #pragma unroll
    for (int j = 0; j < 8; j++) {
        rx[j] = sx[base + j];
        ry[j] = sy[base + j];
        rz[j] = sz[base + j];
        md[j] = 3.4e38f;
    }

    float px = sx[0], py = sy[0], pz = sz[0];
    if (t == 0) {
        float* c = g_centers + (size_t)(b * NC) * 3;
        c[0] = px; c[1] = py; c[2] = pz;
    }

    for (int i = 1; i < NC; i++) {
        float bv = -1.0f; int bi = base;
        #pragma unroll
        for (int j = 0; j < 8; j++) {
            float dx = __fadd_rn(rx[j], -px);
            float dy = __fadd_rn(ry[j], -py);
            float dz = __fadd_rn(rz[j], -pz);
            float d  = __fadd_rn(__fadd_rn(__fmul_rn(dx, dx), __fmul_rn(dy, dy)),
                                 __fmul_rn(dz, dz));
            float m  = fminf(md[j], d);
            md[j] = m;
            if (m > bv) { bv = m; bi = base + j; }
        }
        unsigned long long key =
            ((unsigned long long)__float_as_uint(bv) << 32) | (unsigned)(NN - 1 - bi);
        #pragma unroll
        for (int off = 16; off; off >>= 1) {
            unsigned long long o = __shfl_down_sync(0xFFFFFFFFu, key, off);
            if (o > key) key = o;
        }
        if (lane == 0) skeys[wid] = key;
        __syncthreads();
        if (t < 32) {
            unsigned long long k2 = skeys[t];
            #pragma unroll
            for (int off = 16; off; off >>= 1) {
                unsigned long long o = __shfl_down_sync(0xFFFFFFFFu, k2, off);
                if (o > k2) k2 = o;
            }
            if (t == 0) sres = k2;
        }
        __syncthreads();
        const unsigned long long kk = sres;
        const int sel = NN - 1 - (int)(kk & 0xFFFFFFFFull);
        px = sx[sel]; py = sy[sel]; pz = sz[sel];
        if (t == 0) {
            float* c = g_centers + (size_t)(b * NC + i) * 3;
            c[0] = px; c[1] = py; c[2] = pz;
        }
    }
}

// ============================================================================
// K2: kNN set of 32 — one warp per center, 8 centers/block, points in smem.
// ============================================================================
__global__ __launch_bounds__(256, 2)
void knn_kernel(const float* __restrict__ data, const int* __restrict__ perm)
{
    extern __shared__ float sp[];                    // [3*NN]
    const int warp = threadIdx.x >> 5;
    const int lane = threadIdx.x & 31;
    const int w  = blockIdx.x * 8 + warp;
    const int b  = w >> 8;
    const int ci = w & 255;
    const int p  = perm[ci];

    const float* dp = data + (size_t)b * 3 * NN;
    for (int i = threadIdx.x; i < 3 * NN / 4; i += 256)
        ((float4*)sp)[i] = ((const float4*)dp)[i];
    __syncthreads();
    const float* sx = sp, *sy = sp + NN, *sz = sp + 2 * NN;

    const float* cc = g_centers + (size_t)(b * NC + p) * 3;
    const float cx = cc[0], cy = cc[1], cz = cc[2];
    const float cs = (cx * cx + cy * cy) + cz * cz;

    float px = sx[lane], py = sy[lane], pz = sz[lane];
    float ps  = (px * px + py * py) + pz * pz;
    float dot = (cx * px + cy * py) + cz * pz;
    float kd  = (cs + ps) - 2.0f * dot;
    int   ki  = lane;
    float cm = kd;
    #pragma unroll
    for (int off = 16; off; off >>= 1) cm = fmaxf(cm, __shfl_xor_sync(0xFFFFFFFFu, cm, off));

    for (int bse = 32; bse < NN; bse += 32) {
        const int n = bse + lane;
        px = sx[n]; py = sy[n]; pz = sz[n];
        ps  = (px * px + py * py) + pz * pz;
        dot = (cx * px + cy * py) + cz * pz;
        const float d = (cs + ps) - 2.0f * dot;

        unsigned m = __ballot_sync(0xFFFFFFFFu, d < cm);
        while (m) {
            const int src = __ffs(m) - 1; m &= m - 1;
            const float dc = __shfl_sync(0xFFFFFFFFu, d, src);
            if (dc < cm) {
                float mv = kd; int mi = ki, ml = lane;
                #pragma unroll
                for (int off = 16; off; off >>= 1) {
                    float ov = __shfl_down_sync(0xFFFFFFFFu, mv, off);
                    int   oi = __shfl_down_sync(0xFFFFFFFFu, mi, off);
                    int   ol = __shfl_down_sync(0xFFFFFFFFu, ml, off);
                    if (ov > mv || (ov == mv && oi > mi)) { mv = ov; mi = oi; ml = ol; }
                }
                ml = __shfl_sync(0xFFFFFFFFu, ml, 0);
                if (lane == ml) { kd = dc; ki = bse + src; }
                float q = kd;
                #pragma unroll
                for (int off = 16; off; off >>= 1) q = fmaxf(q, __shfl_xor_sync(0xFFFFFFFFu, q, off));
                cm = q;
            }
        }
    }

    const float nx = sx[ki], ny = sy[ki], nz = sz[ki];
    float sxx = nx, syy = ny, szz = nz;
    #pragma unroll
    for (int off = 16; off; off >>= 1) {
        sxx += __shfl_xor_sync(0xFFFFFFFFu, sxx, off);
        syy += __shfl_xor_sync(0xFFFFFFFFu, syy, off);
        szz += __shfl_xor_sync(0xFFFFFFFFu, szz, off);
    }
    const float mx = sxx * (1.0f / 32.0f);
    const float my = syy * (1.0f / 32.0f);
    const float mz = szz * (1.0f / 32.0f);
    const float lx = nx - mx, ly = ny - my, lz = nz - mz;
    const float ns = (lx * lx + ly * ly) + lz * lz;
    float wm = ns;
    #pragma unroll
    for (int off = 16; off; off >>= 1) wm = fmaxf(wm, __shfl_xor_sync(0xFFFFFFFFu, wm, off));
    if (lane == 0) atomicMax(&g_scale_bits, __float_as_uint(wm));

    float* lp = g_local + ((size_t)w * NP + lane) * 3;
    lp[0] = lx; lp[1] = ly; lp[2] = lz;
    if (lane < 3) g_cmean[(size_t)w * 3 + lane] = (lane == 0) ? mx : ((lane == 1) ? my : mz);
}

// ============================================================================
// K3a enc: 2 patches/block (64 rows). We2 staged in 16-k smem slices with
// register double-buffer (prefetch next slice during compute).
// ============================================================================
__global__ __launch_bounds__(256, 2)
void enc_kernel(const float* __restrict__ We1, const float* __restrict__ be1,
                const float* __restrict__ We2, const float* __restrict__ be2)
{
    extern __shared__ float s[];
    float* h1T   = s;            // [128][64]   8192
    float* stage = s + 8192;     // [16][256]   4096
    float* xs    = s + 12288;    // [64][3]      192
    float* codep = s + 12480;    // [8][256]    2048  -> total 14528 fl

    const int t  = threadIdx.x;
    const int m0 = blockIdx.x * 2;
    const float scale = sqrtf(__uint_as_float(g_scale_bits));

    if (t < 192) xs[t] = g_local[(size_t)blockIdx.x * 192 + t] / scale;
    __syncthreads();

    // enc1: h1T[k][r] = relu(xs[r]·We1[:,k] + be1[k])
    #pragma unroll
    for (int i = 0; i < 32; i++) {
        const int o = i * 256 + t;
        const int k = o >> 6, r = o & 63;
        float v = xs[r * 3] * We1[k] + xs[r * 3 + 1] * We1[128 + k]
                + xs[r * 3 + 2] * We1[256 + k] + be1[k];
        h1T[k * 64 + r] = fmaxf(v, 0.0f);
    }

    const int rg = t & 7, cg = t >> 3;
    const int r0 = rg * 8, c0 = cg * 8;
    unsigned long long acc2[4][8];
    #pragma unroll
    for (int i = 0; i < 4; i++)
        #pragma unroll
        for (int j = 0; j < 8; j++) acc2[i][j] = 0ull;

    float4 pf[4];
    {
        const float4* src = (const float4*)We2;
        #pragma unroll
        for (int i = 0; i < 4; i++) pf[i] = src[t + 256 * i];
    }
    for (int sl = 0; sl < 8; sl++) {
        __syncthreads();
        #pragma unroll
        for (int i = 0; i < 4; i++) ((float4*)stage)[t + 256 * i] = pf[i];
        __syncthreads();
        if (sl < 7) {
            const float4* src = (const float4*)(We2 + (sl + 1) * 16 * 256);
            #pragma unroll
            for (int i = 0; i < 4; i++) pf[i] = src[t + 256 * i];
        }
        #pragma unroll 4
        for (int k = 0; k < 16; k++) {
            const int kk = sl * 16 + k;
            const ulonglong2 a0 = *(const ulonglong2*)(h1T + kk * 64 + r0);
            const ulonglong2 a1 = *(const ulonglong2*)(h1T + kk * 64 + r0 + 4);
            const unsigned long long ap[4] = {a0.x, a0.y, a1.x, a1.y};
            const float4 w0 = *(const float4*)(stage + k * 256 + c0);
            const float4 w1 = *(const float4*)(stage + k * 256 + c0 + 4);
            const unsigned long long wp[8] = {pack2(w0.x), pack2(w0.y), pack2(w0.z), pack2(w0.w),
                                              pack2(w1.x), pack2(w1.y), pack2(w1.z), pack2(w1.w)};
            #pragma unroll
            for (int i = 0; i < 4; i++)
                #pragma unroll
                for (int j = 0; j < 8; j++) fma2(acc2[i][j], ap[i], wp[j]);
        }
    }
    #pragma unroll
    for (int j = 0; j < 8; j++) {
        const float bb = be2[c0 + j];
        float mj = 0.0f;
        #pragma unroll
        for (int i = 0; i < 4; i++) {
            const float2 v = unpack2(acc2[i][j]);
            mj = fmaxf(mj, fmaxf(fmaxf(v.x + bb, 0.0f), fmaxf(v.y + bb, 0.0f)));
        }
        codep[rg * 256 + c0 + j] = mj;
    }
    __syncthreads();
    {
        const int c = t;
        const float v0 = fmaxf(fmaxf(codep[c], codep[256 + c]),
                               fmaxf(codep[512 + c], codep[768 + c]));
        const float v1 = fmaxf(fmaxf(codep[1024 + c], codep[1280 + c]),
                               fmaxf(codep[1536 + c], codep[1792 + c]));
        *(float2*)(g_codeT + (size_t)c * MTOT + m0) = make_float2(v0, v1);
    }
}

// ============================================================================
// K3b base: base{1,2}[m][c] = code[m]·Wf{1,2}a[:256,c] + b.
// 2D grid: blockIdx.y selects matrix (fills all 148 SMs). 16-k slices with
// register double-buffer.
// ============================================================================
__global__ __launch_bounds__(256, 2)
void base_kernel(const float* __restrict__ Wf1a, const float* __restrict__ bf1a,
                 const float* __restrict__ Wf2a, const float* __restrict__ bf2a)
{
    extern __shared__ float s[];
    float* ct    = s;            // [256 k][64 m]  16384
    float* stage = s + 16384;    // [16 k][256 c]   4096  -> 20480 fl

    const int t  = threadIdx.x;
    const int m0 = blockIdx.x * 64;
    const int mat = blockIdx.y;
    const float* W  = mat ? Wf2a : Wf1a;
    const float* bv = mat ? bf2a : bf1a;
    float* dst = mat ? g_base2 : g_base1;

    for (int i = t; i < 4096; i += 256) {
        const int k = i >> 4, mq = i & 15;
        *(float4*)(ct + k * 64 + mq * 4) =
            *(const float4*)(g_codeT + (size_t)k * MTOT + m0 + mq * 4);
    }

    const int rg = t & 7, cg = t >> 3;
    const int r0 = rg * 8, c0 = cg * 8;

    unsigned long long acc2[4][8];
    #pragma unroll
    for (int i = 0; i < 4; i++)
        #pragma unroll
        for (int j = 0; j < 8; j++) acc2[i][j] = 0ull;

    float4 pf[4];
    {
        const float4* src = (const float4*)W;
        #pragma unroll
        for (int i = 0; i < 4; i++) pf[i] = src[t + 256 * i];
    }
    for (int sl = 0; sl < 16; sl++) {
        __syncthreads();
        #pragma unroll
        for (int i = 0; i < 4; i++) ((float4*)stage)[t + 256 * i] = pf[i];
        __syncthreads();
        if (sl < 15) {
            const float4* src = (const float4*)(W + (sl + 1) * 16 * 256);
            #pragma unroll
            for (int i = 0; i < 4; i++) pf[i] = src[t + 256 * i];
        }
        #pragma unroll 4
        for (int k = 0; k < 16; k++) {
            const int kk = sl * 16 + k;
            const ulonglong2 a0 = *(const ulonglong2*)(ct + kk * 64 + r0);
            const ulonglong2 a1 = *(const ulonglong2*)(ct + kk * 64 + r0 + 4);
            const unsigned long long ap[4] = {a0.x, a0.y, a1.x, a1.y};
            const float4 w0 = *(const float4*)(stage + k * 256 + c0);
            const float4 w1 = *(const float4*)(stage + k * 256 + c0 + 4);
            const unsigned long long wp[8] = {pack2(w0.x), pack2(w0.y), pack2(w0.z), pack2(w0.w),
                                              pack2(w1.x), pack2(w1.y), pack2(w1.z), pack2(w1.w)};
            #pragma unroll
            for (int i = 0; i < 4; i++)
                #pragma unroll
                for (int j = 0; j < 8; j++) fma2(acc2[i][j], ap[i], wp[j]);
        }
    }
    #pragma unroll
    for (int i = 0; i < 4; i++) {
        float4 lo0, lo1, hi0, hi1;
        float* l0 = (float*)&lo0; float* l1 = (float*)&lo1;
        float* h0 = (float*)&hi0; float* h1 = (float*)&hi1;
        #pragma unroll
        for (int j = 0; j < 8; j++) {
            const float bb = bv[c0 + j];
            const float2 v = unpack2(acc2[i][j]);
            if (j < 4) { l0[j] = v.x + bb; h0[j] = v.y + bb; }
            else       { l1[j - 4] = v.x + bb; h1[j - 4] = v.y + bb; }
        }
        float* d0 = dst + (size_t)(m0 + r0 + 2 * i) * 256 + c0;
        float* d1 = dst + (size_t)(m0 + r0 + 2 * i + 1) * 256 + c0;
        *(float4*)d0 = lo0; *(float4*)(d0 + 4) = lo1;
        *(float4*)d1 = hi0; *(float4*)(d1 + 4) = hi1;
    }
}

// ============================================================================
// K3c fold: 2 patches/block (M=64 rows), 8r x 4c thread tiles, weight slices
// double-buffered through registers. 4096 blocks.
// ============================================================================
__global__ __launch_bounds__(256, 1)
void fold_kernel(const float* __restrict__ grid_,
                 const float* __restrict__ Wf1a,
                 const float* __restrict__ Wf1b, const float* __restrict__ bf1b,
                 const float* __restrict__ Wf1c, const float* __restrict__ bf1c,
                 const float* __restrict__ Wf2a,
                 const float* __restrict__ Wf2b, const float* __restrict__ bf2b,
                 const float* __restrict__ Wf2c, const float* __restrict__ bf2c,
                 float* __restrict__ out)
{
    extern __shared__ float s[];
    float* hfT   = s;            // [256 k][64 r]  16384
    float* hf2T  = s + 16384;    // [128 k][64 r]   8192
    float* stage = s + 24576;    // [32 k][128 c]   4096
    float* b1    = s + 28672;    // [2][256]         512
    float* b2    = s + 29184;    //                  512
    float* wg    = s + 29696;    // [2][256]         512
    float* wf    = s + 30208;    // [3][256]         768
    float* Wc1   = s + 30976;    // [384]
    float* Wc2   = s + 31360;    // [384]
    float* gx    = s + 31744;    // [32]
    float* gy    = s + 31776;    // [32]
    float* fv    = s + 31808;    // [192]
    float* cm    = s + 32000;    // [8]   -> total 32008 fl = 128032 B

    const int t = threadIdx.x;
    const int m0 = blockIdx.x * 2;
    const float scale = sqrtf(__uint_as_float(g_scale_bits));

    b1[t]       = g_base1[(size_t)m0 * 256 + t];
    b1[256 + t] = g_base1[(size_t)(m0 + 1) * 256 + t];
    b2[t]       = g_base2[(size_t)m0 * 256 + t];
    b2[256 + t] = g_base2[(size_t)(m0 + 1) * 256 + t];
    wg[t]       = Wf1a[256 * 256 + t];
    wg[256 + t] = Wf1a[257 * 256 + t];
    wf[t]       = Wf2a[256 * 256 + t];
    wf[256 + t] = Wf2a[257 * 256 + t];
    wf[512 + t] = Wf2a[258 * 256 + t];
    for (int i = t; i < 384; i += 256) { Wc1[i] = Wf1c[i]; Wc2[i] = Wf2c[i]; }
    if (t < 32) { gx[t] = grid_[2 * t]; gy[t] = grid_[2 * t + 1]; }
    if (t < 6)  cm[t] = g_cmean[(size_t)m0 * 3 + t];
    __syncthreads();

    // hfT[k][r]: r = p*32 + rr (2 patches)
    #pragma unroll 8
    for (int i = 0; i < 64; i++) {
        const int o = i * 256 + t;
        const int k = o >> 6, r = o & 63;
        const int p = r >> 5, rr = r & 31;
        hfT[o] = fmaxf(b1[p * 256 + k] + gx[rr] * wg[k] + gy[rr] * wg[256 + k], 0.0f);
    }

    const int rg = t & 7, cg = t >> 3;
    const int r0 = rg * 8, c0 = cg * 4;

    #pragma unroll
    for (int stagei = 0; stagei < 2; stagei++) {
        const float* W  = stagei ? Wf2b : Wf1b;
        const float* bv = stagei ? bf2b : bf1b;

        unsigned long long acc2[4][4];
        #pragma unroll
        for (int i = 0; i < 4; i++)
            #pragma unroll
            for (int j = 0; j < 4; j++) acc2[i][j] = 0ull;

        float4 pf[4];
        {
            const float4* src = (const float4*)W;
            #pragma unroll
            for (int i = 0; i < 4; i++) pf[i] = src[t + 256 * i];
        }
        for (int sl = 0; sl < 8; sl++) {
            __syncthreads();
            #pragma unroll
            for (int i = 0; i < 4; i++) ((float4*)stage)[t + 256 * i] = pf[i];
            __syncthreads();
            if (sl < 7) {
                const float4* src = (const float4*)(W + (sl + 1) * 32 * 128);
                #pragma unroll
                for (int i = 0; i < 4; i++) pf[i] = src[t + 256 * i];
            }
            #pragma unroll 8
            for (int k = 0; k < 32; k++) {
                const int kk = sl * 32 + k;
                const ulonglong2 a0 = *(const ulonglong2*)(hfT + kk * 64 + r0);
                const ulonglong2 a1 = *(const ulonglong2*)(hfT + kk * 64 + r0 + 4);
                const unsigned long long ap[4] = {a0.x, a0.y, a1.x, a1.y};
                const float4 w = *(const float4*)(stage + k * 128 + c0);
                const unsigned long long wp[4] = {pack2(w.x), pack2(w.y),
                                                  pack2(w.z), pack2(w.w)};
                #pragma unroll
                for (int i = 0; i < 4; i++)
                    #pragma unroll
                    for (int j = 0; j < 4; j++) fma2(acc2[i][j], ap[i], wp[j]);
            }
        }
        #pragma unroll
        for (int j = 0; j < 4; j++) {
            const float bb = bv[c0 + j];
            #pragma unroll
            for (int i = 0; i < 4; i++) {
                const float2 v = unpack2(acc2[i][j]);
                hf2T[(c0 + j) * 64 + r0 + 2 * i]     = fmaxf(v.x + bb, 0.0f);
                hf2T[(c0 + j) * 64 + r0 + 2 * i + 1] = fmaxf(v.y + bb, 0.0f);
            }
        }
        __syncthreads();

        if (stagei == 0) {
            // fold1c: fv[p][rr][q] = hf2[p*32+rr]·Wf1c[:,q] + bf1c[q]
            if (t < 192) {
                const int p = t / 96, rem = t - p * 96;
                const int rr = rem / 3, q = rem - rr * 3;
                const int r = p * 32 + rr;
                float acc = bf1c[q];
                #pragma unroll 8
                for (int k = 0; k < 128; k++) acc += hf2T[k * 64 + r] * Wc1[k * 3 + q];
                fv[t] = acc;
            }
            __syncthreads();
            // rebuild hfT for fold2
            #pragma unroll 8
            for (int i = 0; i < 64; i++) {
                const int o = i * 256 + t;
                const int k = o >> 6, r = o & 63;
                const int p = r >> 5, rr = r & 31;
                const int fb = (p * 32 + rr) * 3;
                hfT[o] = fmaxf(b2[p * 256 + k] + fv[fb] * wf[k]
                               + fv[fb + 1] * wf[256 + k]
                               + fv[fb + 2] * wf[512 + k], 0.0f);
            }
            __syncthreads();
        } else {
            // fold2c + output
            if (t < 192) {
                const int p = t / 96, rem = t - p * 96;
                const int rr = rem / 3, q = rem - rr * 3;
                const int r = p * 32 + rr;
                float acc = bf2c[q];
                #pragma unroll 8
                for (int k = 0; k < 128; k++) acc += hf2T[k * 64 + r] * Wc2[k * 3 + q];
                out[(size_t)(m0 + p) * 96 + rem] = acc * scale + cm[p * 3 + q];
            }
        }
    }
}

// ============================================================================
extern "C" void kernel_launch(void* const* d_in, const int* in_sizes, int n_in,
                              void* d_out, int out_size)
{
    (void)in_sizes; (void)n_in; (void)out_size;
    const float* data = (const float*)d_in[0];
    const int*   perm = (const int*)  d_in[1];
    const float* grid = (const float*)d_in[2];
    const float* We1  = (const float*)d_in[3];
    const float* be1  = (const float*)d_in[4];
    const float* We2  = (const float*)d_in[5];
    const float* be2  = (const float*)d_in[6];
    const float* Wf1a = (const float*)d_in[7];
    const float* bf1a = (const float*)d_in[8];
    const float* Wf1b = (const float*)d_in[9];
    const float* bf1b = (const float*)d_in[10];
    const float* Wf1c = (const float*)d_in[11];
    const float* bf1c = (const float*)d_in[12];
    const float* Wf2a = (const float*)d_in[13];
    const float* bf2a = (const float*)d_in[14];
    const float* Wf2b = (const float*)d_in[15];
    const float* bf2b = (const float*)d_in[16];
    const float* Wf2c = (const float*)d_in[17];
    const float* bf2c = (const float*)d_in[18];
    float* out = (float*)d_out;

    const int fps_smem  = 3 * NN * sizeof(float);      // 98304
    const int knn_smem  = 3 * NN * sizeof(float);      // 98304
    const int enc_smem  = 14528 * sizeof(float);       // 58112
    const int base_smem = 20480 * sizeof(float);       // 81920
    const int fold_smem = 32008 * sizeof(float);       // 128032
    cudaFuncSetAttribute(fps_kernel,  cudaFuncAttributeMaxDynamicSharedMemorySize, fps_smem);
    cudaFuncSetAttribute(knn_kernel,  cudaFuncAttributeMaxDynamicSharedMemorySize, knn_smem);
    cudaFuncSetAttribute(enc_kernel,  cudaFuncAttributeMaxDynamicSharedMemorySize, enc_smem);
    cudaFuncSetAttribute(base_kernel, cudaFuncAttributeMaxDynamicSharedMemorySize, base_smem);
    cudaFuncSetAttribute(fold_kernel, cudaFuncAttributeMaxDynamicSharedMemorySize, fold_smem);

    fps_kernel <<<BB, 1024, fps_smem>>>(data);
    knn_kernel <<<(BB * NC) / 8, 256, knn_smem>>>(data, perm);
    enc_kernel <<<MTOT / 2, 256, enc_smem>>>(We1, be1, We2, be2);
    base_kernel<<<dim3(MTOT / 64, 2), 256, base_smem>>>(Wf1a, bf1a, Wf2a, bf2a);
    fold_kernel<<<MTOT / 2, 256, fold_smem>>>(grid, Wf1a, Wf1b, bf1b, Wf1c, bf1c,
                                              Wf2a, Wf2b, bf2b, Wf2c, bf2c, out);
}

// round 5
// speedup vs baseline: 1.1462x; 1.1462x over previous
#include <cuda_runtime.h>
#include <math.h>

#define BB 32
#define NN 8192
#define NC 256
#define NP 32
#define MTOT (BB * NC)          // 8192 patches

// ---------------- scratch (device globals; no allocation allowed) ----------
__device__ float    g_centers[BB * NC * 3];
__device__ float    g_local  [MTOT * NP * 3];
__device__ float    g_cmean  [MTOT * 3];
__device__ unsigned g_scale_bits;
__device__ float    g_codeT [256 * MTOT];      // code transposed [c][m]
__device__ float    g_base1 [MTOT * 256];      // [m][c]
__device__ float    g_base2 [MTOT * 256];      // [m][c]

// ---------------- packed fp32x2 helpers (sm_100+) ---------------------------
__device__ __forceinline__ unsigned long long pack2(float w) {
    unsigned long long r;
    asm("mov.b64 %0, {%1, %1};" : "=l"(r) : "f"(w));
    return r;
}
__device__ __forceinline__ void fma2(unsigned long long& acc,
                                     unsigned long long a, unsigned long long b) {
    asm("fma.rn.f32x2 %0, %1, %2, %0;" : "+l"(acc) : "l"(a), "l"(b));
}
__device__ __forceinline__ float2 unpack2(unsigned long long v) {
    float2 r;
    asm("mov.b64 {%0, %1}, %2;" : "=f"(r.x), "=f"(r.y) : "l"(v));
    return r;
}

// ============================================================================
// K1: FPS — one block per batch, points/mind in registers, atomic-free block
// argmax (per-warp shfl reduce -> 32 smem slots -> warp0 shfl reduce).
// Exact jnp.argmax tie semantics via key = (value_bits << 32) | (NN-1-idx).
// Distance arithmetic replicates the reference exactly (no FMA contraction).
// ============================================================================
__global__ __launch_bounds__(1024, 1)
void fps_kernel(const float* __restrict__ data)
{
    extern __shared__ float sm[];
    float* sx = sm;
    float* sy = sm + NN;
    float* sz = sm + 2 * NN;
    __shared__ unsigned long long skeys[32];
    __shared__ unsigned long long sres;

    const int b = blockIdx.x;
    const int t = threadIdx.x;
    const int wid = t >> 5, lane = t & 31;
    if (b == 0 && t == 0) g_scale_bits = 0u;   // reset every launch (graph replay safe)

    const float* dp = data + (size_t)b * 3 * NN;
    for (int n = t; n < NN; n += 1024) {
        sx[n] = dp[n];
        sy[n] = dp[NN + n];
        sz[n] = dp[2 * NN + n];
    }
    __syncthreads();

    float rx[8], ry[8], rz[8], md[8];
    const int base = t * 8;
    #pragma unroll
    for (int j = 0; j < 8; j++) {
        rx[j] = sx[base + j];
        ry[j] = sy[base + j];
        rz[j] = sz[base + j];
        md[j] = 3.4e38f;
    }

    float px = sx[0], py = sy[0], pz = sz[0];
    if (t == 0) {
        float* c = g_centers + (size_t)(b * NC) * 3;
        c[0] = px; c[1] = py; c[2] = pz;
    }

    for (int i = 1; i < NC; i++) {
        float bv = -1.0f; int bi = base;
        #pragma unroll
        for (int j = 0; j < 8; j++) {
            float dx = __fadd_rn(rx[j], -px);
            float dy = __fadd_rn(ry[j], -py);
            float dz = __fadd_rn(rz[j], -pz);
            float d  = __fadd_rn(__fadd_rn(__fmul_rn(dx, dx), __fmul_rn(dy, dy)),
                                 __fmul_rn(dz, dz));
            float m  = fminf(md[j], d);
            md[j] = m;
            if (m > bv) { bv = m; bi = base + j; }
        }
        unsigned long long key =
            ((unsigned long long)__float_as_uint(bv) << 32) | (unsigned)(NN - 1 - bi);
        #pragma unroll
        for (int off = 16; off; off >>= 1) {
            unsigned long long o = __shfl_down_sync(0xFFFFFFFFu, key, off);
            if (o > key) key = o;
        }
        if (lane == 0) skeys[wid] = key;
        __syncthreads();
        if (t < 32) {
            unsigned long long k2 = skeys[t];
            #pragma unroll
            for (int off = 16; off; off >>= 1) {
                unsigned long long o = __shfl_down_sync(0xFFFFFFFFu, k2, off);
                if (o > k2) k2 = o;
            }
            if (t == 0) sres = k2;
        }
        __syncthreads();
        const unsigned long long kk = sres;
        const int sel = NN - 1 - (int)(kk & 0xFFFFFFFFull);
        px = sx[sel]; py = sy[sel]; pz = sz[sel];
        if (t == 0) {
            float* c = g_centers + (size_t)(b * NC + i) * 3;
            c[0] = px; c[1] = py; c[2] = pz;
        }
    }
}

// ============================================================================
// K2: kNN set of 32 — one warp per center, 8 centers/block, points in smem.
// ============================================================================
__global__ __launch_bounds__(256, 2)
void knn_kernel(const float* __restrict__ data, const int* __restrict__ perm)
{
    extern __shared__ float sp[];                    // [3*NN]
    const int warp = threadIdx.x >> 5;
    const int lane = threadIdx.x & 31;
    const int w  = blockIdx.x * 8 + warp;
    const int b  = w >> 8;
    const int ci = w & 255;
    const int p  = perm[ci];

    const float* dp = data + (size_t)b * 3 * NN;
    for (int i = threadIdx.x; i < 3 * NN / 4; i += 256)
        ((float4*)sp)[i] = ((const float4*)dp)[i];
    __syncthreads();
    const float* sx = sp, *sy = sp + NN, *sz = sp + 2 * NN;

    const float* cc = g_centers + (size_t)(b * NC + p) * 3;
    const float cx = cc[0], cy = cc[1], cz = cc[2];
    const float cs = (cx * cx + cy * cy) + cz * cz;

    float px = sx[lane], py = sy[lane], pz = sz[lane];
    float ps  = (px * px + py * py) + pz * pz;
    float dot = (cx * px + cy * py) + cz * pz;
    float kd  = (cs + ps) - 2.0f * dot;
    int   ki  = lane;
    float cm = kd;
    #pragma unroll
    for (int off = 16; off; off >>= 1) cm = fmaxf(cm, __shfl_xor_sync(0xFFFFFFFFu, cm, off));

    for (int bse = 32; bse < NN; bse += 32) {
        const int n = bse + lane;
        px = sx[n]; py = sy[n]; pz = sz[n];
        ps  = (px * px + py * py) + pz * pz;
        dot = (cx * px + cy * py) + cz * pz;
        const float d = (cs + ps) - 2.0f * dot;

        unsigned m = __ballot_sync(0xFFFFFFFFu, d < cm);
        while (m) {
            const int src = __ffs(m) - 1; m &= m - 1;
            const float dc = __shfl_sync(0xFFFFFFFFu, d, src);
            if (dc < cm) {
                float mv = kd; int mi = ki, ml = lane;
                #pragma unroll
                for (int off = 16; off; off >>= 1) {
                    float ov = __shfl_down_sync(0xFFFFFFFFu, mv, off);
                    int   oi = __shfl_down_sync(0xFFFFFFFFu, mi, off);
                    int   ol = __shfl_down_sync(0xFFFFFFFFu, ml, off);
                    if (ov > mv || (ov == mv && oi > mi)) { mv = ov; mi = oi; ml = ol; }
                }
                ml = __shfl_sync(0xFFFFFFFFu, ml, 0);
                if (lane == ml) { kd = dc; ki = bse + src; }
                float q = kd;
                #pragma unroll
                for (int off = 16; off; off >>= 1) q = fmaxf(q, __shfl_xor_sync(0xFFFFFFFFu, q, off));
                cm = q;
            }
        }
    }

    const float nx = sx[ki], ny = sy[ki], nz = sz[ki];
    float sxx = nx, syy = ny, szz = nz;
    #pragma unroll
    for (int off = 16; off; off >>= 1) {
        sxx += __shfl_xor_sync(0xFFFFFFFFu, sxx, off);
        syy += __shfl_xor_sync(0xFFFFFFFFu, syy, off);
        szz += __shfl_xor_sync(0xFFFFFFFFu, szz, off);
    }
    const float mx = sxx * (1.0f / 32.0f);
    const float my = syy * (1.0f / 32.0f);
    const float mz = szz * (1.0f / 32.0f);
    const float lx = nx - mx, ly = ny - my, lz = nz - mz;
    const float ns = (lx * lx + ly * ly) + lz * lz;
    float wm = ns;
    #pragma unroll
    for (int off = 16; off; off >>= 1) wm = fmaxf(wm, __shfl_xor_sync(0xFFFFFFFFu, wm, off));
    if (lane == 0) atomicMax(&g_scale_bits, __float_as_uint(wm));

    float* lp = g_local + ((size_t)w * NP + lane) * 3;
    lp[0] = lx; lp[1] = ly; lp[2] = lz;
    if (lane < 3) g_cmean[(size_t)w * 3 + lane] = (lane == 0) ? mx : ((lane == 1) ? my : mz);
}

// ============================================================================
// K3a enc: 2 patches/block (64 rows). We2 staged in 16-k smem slices with
// register double-buffer (prefetch next slice during compute).
// ============================================================================
__global__ __launch_bounds__(256, 2)
void enc_kernel(const float* __restrict__ We1, const float* __restrict__ be1,
                const float* __restrict__ We2, const float* __restrict__ be2)
{
    extern __shared__ float s[];
    float* h1T   = s;            // [128][64]   8192
    float* stage = s + 8192;     // [16][256]   4096
    float* xs    = s + 12288;    // [64][3]      192
    float* codep = s + 12480;    // [8][256]    2048  -> total 14528 fl

    const int t  = threadIdx.x;
    const int m0 = blockIdx.x * 2;
    const float scale = sqrtf(__uint_as_float(g_scale_bits));

    if (t < 192) xs[t] = g_local[(size_t)blockIdx.x * 192 + t] / scale;
    __syncthreads();

    // enc1: h1T[k][r] = relu(xs[r]·We1[:,k] + be1[k])
    #pragma unroll
    for (int i = 0; i < 32; i++) {
        const int o = i * 256 + t;
        const int k = o >> 6, r = o & 63;
        float v = xs[r * 3] * We1[k] + xs[r * 3 + 1] * We1[128 + k]
                + xs[r * 3 + 2] * We1[256 + k] + be1[k];
        h1T[k * 64 + r] = fmaxf(v, 0.0f);
    }

    const int rg = t & 7, cg = t >> 3;
    const int r0 = rg * 8, c0 = cg * 8;
    unsigned long long acc2[4][8];
    #pragma unroll
    for (int i = 0; i < 4; i++)
        #pragma unroll
        for (int j = 0; j < 8; j++) acc2[i][j] = 0ull;

    float4 pf[4];
    {
        const float4* src = (const float4*)We2;
        #pragma unroll
        for (int i = 0; i < 4; i++) pf[i] = src[t + 256 * i];
    }
    for (int sl = 0; sl < 8; sl++) {
        __syncthreads();
        #pragma unroll
        for (int i = 0; i < 4; i++) ((float4*)stage)[t + 256 * i] = pf[i];
        __syncthreads();
        if (sl < 7) {
            const float4* src = (const float4*)(We2 + (sl + 1) * 16 * 256);
            #pragma unroll
            for (int i = 0; i < 4; i++) pf[i] = src[t + 256 * i];
        }
        #pragma unroll 4
        for (int k = 0; k < 16; k++) {
            const int kk = sl * 16 + k;
            const ulonglong2 a0 = *(const ulonglong2*)(h1T + kk * 64 + r0);
            const ulonglong2 a1 = *(const ulonglong2*)(h1T + kk * 64 + r0 + 4);
            const unsigned long long ap[4] = {a0.x, a0.y, a1.x, a1.y};
            const float4 w0 = *(const float4*)(stage + k * 256 + c0);
            const float4 w1 = *(const float4*)(stage + k * 256 + c0 + 4);
            const unsigned long long wp[8] = {pack2(w0.x), pack2(w0.y), pack2(w0.z), pack2(w0.w),
                                              pack2(w1.x), pack2(w1.y), pack2(w1.z), pack2(w1.w)};
            #pragma unroll
            for (int i = 0; i < 4; i++)
                #pragma unroll
                for (int j = 0; j < 8; j++) fma2(acc2[i][j], ap[i], wp[j]);
        }
    }
    #pragma unroll
    for (int j = 0; j < 8; j++) {
        const float bb = be2[c0 + j];
        float mj = 0.0f;
        #pragma unroll
        for (int i = 0; i < 4; i++) {
            const float2 v = unpack2(acc2[i][j]);
            mj = fmaxf(mj, fmaxf(fmaxf(v.x + bb, 0.0f), fmaxf(v.y + bb, 0.0f)));
        }
        codep[rg * 256 + c0 + j] = mj;
    }
    __syncthreads();
    {
        const int c = t;
        const float v0 = fmaxf(fmaxf(codep[c], codep[256 + c]),
                               fmaxf(codep[512 + c], codep[768 + c]));
        const float v1 = fmaxf(fmaxf(codep[1024 + c], codep[1280 + c]),
                               fmaxf(codep[1536 + c], codep[1792 + c]));
        *(float2*)(g_codeT + (size_t)c * MTOT + m0) = make_float2(v0, v1);
    }
}

// ============================================================================
// K3b base: base{1,2}[m][c] = code[m]·Wf{1,2}a[:256,c] + b.
// 2D grid (matrix on blockIdx.y), 16-k slices, register double-buffer.
// ============================================================================
__global__ __launch_bounds__(256, 2)
void base_kernel(const float* __restrict__ Wf1a, const float* __restrict__ bf1a,
                 const float* __restrict__ Wf2a, const float* __restrict__ bf2a)
{
    extern __shared__ float s[];
    float* ct    = s;            // [256 k][64 m]  16384
    float* stage = s + 16384;    // [16 k][256 c]   4096  -> 20480 fl

    const int t  = threadIdx.x;
    const int m0 = blockIdx.x * 64;
    const int mat = blockIdx.y;
    const float* W  = mat ? Wf2a : Wf1a;
    const float* bv = mat ? bf2a : bf1a;
    float* dst = mat ? g_base2 : g_base1;

    for (int i = t; i < 4096; i += 256) {
        const int k = i >> 4, mq = i & 15;
        *(float4*)(ct + k * 64 + mq * 4) =
            *(const float4*)(g_codeT + (size_t)k * MTOT + m0 + mq * 4);
    }

    const int rg = t & 7, cg = t >> 3;
    const int r0 = rg * 8, c0 = cg * 8;

    unsigned long long acc2[4][8];
    #pragma unroll
    for (int i = 0; i < 4; i++)
        #pragma unroll
        for (int j = 0; j < 8; j++) acc2[i][j] = 0ull;

    float4 pf[4];
    {
        const float4* src = (const float4*)W;
        #pragma unroll
        for (int i = 0; i < 4; i++) pf[i] = src[t + 256 * i];
    }
    for (int sl = 0; sl < 16; sl++) {
        __syncthreads();
        #pragma unroll
        for (int i = 0; i < 4; i++) ((float4*)stage)[t + 256 * i] = pf[i];
        __syncthreads();
        if (sl < 15) {
            const float4* src = (const float4*)(W + (sl + 1) * 16 * 256);
            #pragma unroll
            for (int i = 0; i < 4; i++) pf[i] = src[t + 256 * i];
        }
        #pragma unroll 4
        for (int k = 0; k < 16; k++) {
            const int kk = sl * 16 + k;
            const ulonglong2 a0 = *(const ulonglong2*)(ct + kk * 64 + r0);
            const ulonglong2 a1 = *(const ulonglong2*)(ct + kk * 64 + r0 + 4);
            const unsigned long long ap[4] = {a0.x, a0.y, a1.x, a1.y};
            const float4 w0 = *(const float4*)(stage + k * 256 + c0);
            const float4 w1 = *(const float4*)(stage + k * 256 + c0 + 4);
            const unsigned long long wp[8] = {pack2(w0.x), pack2(w0.y), pack2(w0.z), pack2(w0.w),
                                              pack2(w1.x), pack2(w1.y), pack2(w1.z), pack2(w1.w)};
            #pragma unroll
            for (int i = 0; i < 4; i++)
                #pragma unroll
                for (int j = 0; j < 8; j++) fma2(acc2[i][j], ap[i], wp[j]);
        }
    }
    #pragma unroll
    for (int i = 0; i < 4; i++) {
        float4 lo0, lo1, hi0, hi1;
        float* l0 = (float*)&lo0; float* l1 = (float*)&lo1;
        float* h0 = (float*)&hi0; float* h1 = (float*)&hi1;
        #pragma unroll
        for (int j = 0; j < 8; j++) {
            const float bb = bv[c0 + j];
            const float2 v = unpack2(acc2[i][j]);
            if (j < 4) { l0[j] = v.x + bb; h0[j] = v.y + bb; }
            else       { l1[j - 4] = v.x + bb; h1[j - 4] = v.y + bb; }
        }
        float* d0 = dst + (size_t)(m0 + r0 + 2 * i) * 256 + c0;
        float* d1 = dst + (size_t)(m0 + r0 + 2 * i + 1) * 256 + c0;
        *(float4*)d0 = lo0; *(float4*)(d0 + 4) = lo1;
        *(float4*)d1 = hi0; *(float4*)(d1 + 4) = hi1;
    }
}

// ============================================================================
// K3c fold: 1 patch/block (round-3 shape: 76 KB smem, occupancy 2 -> 16
// warps/SM) + register double-buffered weight staging (the round-4 idea that
// was sound; the round-4 regression was the occupancy-1 restructure).
// ============================================================================
__global__ __launch_bounds__(256, 2)
void fold_kernel(const float* __restrict__ grid_,
                 const float* __restrict__ Wf1a,
                 const float* __restrict__ Wf1b, const float* __restrict__ bf1b,
                 const float* __restrict__ Wf1c, const float* __restrict__ bf1c,
                 const float* __restrict__ Wf2a,
                 const float* __restrict__ Wf2b, const float* __restrict__ bf2b,
                 const float* __restrict__ Wf2c, const float* __restrict__ bf2c,
                 float* __restrict__ out)
{
    extern __shared__ float s[];
    float* hfT   = s;            // [256 k][32 r]  8192
    float* hf2T  = s + 8192;     // [128 k][32 r]  4096
    float* stage = s + 12288;    // [32 k][128 c]  4096
    float* b1    = s + 16384;    // [256]
    float* b2    = s + 16640;    // [256]
    float* wg    = s + 16896;    // [2][256]
    float* wf    = s + 17408;    // [3][256]
    float* Wc1   = s + 18176;    // [384]
    float* Wc2   = s + 18560;    // [384]
    float* gx    = s + 18944;    // [32]
    float* gy    = s + 18976;    // [32]
    float* fv    = s + 19008;    // [96]
    float* cm    = s + 19104;    // [4]   -> total 19108 fl = 76432 B

    const int t = threadIdx.x;
    const int m = blockIdx.x;
    const float scale = sqrtf(__uint_as_float(g_scale_bits));

    b1[t] = g_base1[(size_t)m * 256 + t];
    b2[t] = g_base2[(size_t)m * 256 + t];
    wg[t]       = Wf1a[256 * 256 + t];
    wg[256 + t] = Wf1a[257 * 256 + t];
    wf[t]       = Wf2a[256 * 256 + t];
    wf[256 + t] = Wf2a[257 * 256 + t];
    wf[512 + t] = Wf2a[258 * 256 + t];
    for (int i = t; i < 384; i += 256) { Wc1[i] = Wf1c[i]; Wc2[i] = Wf2c[i]; }
    if (t < 32) { gx[t] = grid_[2 * t]; gy[t] = grid_[2 * t + 1]; }
    if (t < 3)  cm[t] = g_cmean[(size_t)m * 3 + t];
    __syncthreads();

    // hf: [256 k][32 r]
    #pragma unroll
    for (int i = 0; i < 32; i++) {
        const int o = i * 256 + t;
        const int k = o >> 5, r = o & 31;
        hfT[k * 32 + r] = fmaxf(b1[k] + gx[r] * wg[k] + gy[r] * wg[256 + k], 0.0f);
    }

    const int rg = t & 7, cg = t >> 3;
    const int r0 = rg * 4, c0 = cg * 4;

    #pragma unroll
    for (int stagei = 0; stagei < 2; stagei++) {
        const float* W  = stagei ? Wf2b : Wf1b;
        const float* bv = stagei ? bf2b : bf1b;

        unsigned long long acc2[2][4];
        #pragma unroll
        for (int i = 0; i < 2; i++)
            #pragma unroll
            for (int j = 0; j < 4; j++) acc2[i][j] = 0ull;

        float4 pf[4];
        {
            const float4* src = (const float4*)W;
            #pragma unroll
            for (int i = 0; i < 4; i++) pf[i] = src[t + 256 * i];
        }
        for (int sl = 0; sl < 8; sl++) {
            __syncthreads();
            #pragma unroll
            for (int i = 0; i < 4; i++) ((float4*)stage)[t + 256 * i] = pf[i];
            __syncthreads();
            if (sl < 7) {
                const float4* src = (const float4*)(W + (sl + 1) * 32 * 128);
                #pragma unroll
                for (int i = 0; i < 4; i++) pf[i] = src[t + 256 * i];
            }
            #pragma unroll 8
            for (int k = 0; k < 32; k++) {
                const int kk = sl * 32 + k;
                const ulonglong2 a = *(const ulonglong2*)(hfT + kk * 32 + r0);
                const float4 w = *(const float4*)(stage + k * 128 + c0);
                const unsigned long long wp[4] = {pack2(w.x), pack2(w.y),
                                                  pack2(w.z), pack2(w.w)};
                #pragma unroll
                for (int j = 0; j < 4; j++) { fma2(acc2[0][j], a.x, wp[j]);
                                              fma2(acc2[1][j], a.y, wp[j]); }
            }
        }
        #pragma unroll
        for (int j = 0; j < 4; j++) {
            const float bb = bv[c0 + j];
            const float2 v0 = unpack2(acc2[0][j]);
            const float2 v1 = unpack2(acc2[1][j]);
            hf2T[(c0 + j) * 32 + r0 + 0] = fmaxf(v0.x + bb, 0.0f);
            hf2T[(c0 + j) * 32 + r0 + 1] = fmaxf(v0.y + bb, 0.0f);
            hf2T[(c0 + j) * 32 + r0 + 2] = fmaxf(v1.x + bb, 0.0f);
            hf2T[(c0 + j) * 32 + r0 + 3] = fmaxf(v1.y + bb, 0.0f);
        }
        __syncthreads();

        if (stagei == 0) {
            // fold1c: fv[r][q] = hf2[r]·Wf1c[:,q] + bf1c[q]
            if (t < 96) {
                const int r = t / 3, q = t - (t / 3) * 3;
                float acc = bf1c[q];
                #pragma unroll 8
                for (int k = 0; k < 128; k++) acc += hf2T[k * 32 + r] * Wc1[k * 3 + q];
                fv[t] = acc;
            }
            __syncthreads();
            // hg: reuse hfT
            #pragma unroll
            for (int i = 0; i < 32; i++) {
                const int o = i * 256 + t;
                const int k = o >> 5, r = o & 31;
                hfT[k * 32 + r] = fmaxf(b2[k] + fv[r * 3] * wf[k]
                                        + fv[r * 3 + 1] * wf[256 + k]
                                        + fv[r * 3 + 2] * wf[512 + k], 0.0f);
            }
            __syncthreads();
        } else {
            // fold2c + output
            if (t < 96) {
                const int r = t / 3, q = t - (t / 3) * 3;
                float acc = bf2c[q];
                #pragma unroll 8
                for (int k = 0; k < 128; k++) acc += hf2T[k * 32 + r] * Wc2[k * 3 + q];
                out[(size_t)m * 96 + t] = acc * scale + cm[q];
            }
        }
    }
}

// ============================================================================
extern "C" void kernel_launch(void* const* d_in, const int* in_sizes, int n_in,
                              void* d_out, int out_size)
{
    (void)in_sizes; (void)n_in; (void)out_size;
    const float* data = (const float*)d_in[0];
    const int*   perm = (const int*)  d_in[1];
    const float* grid = (const float*)d_in[2];
    const float* We1  = (const float*)d_in[3];
    const float* be1  = (const float*)d_in[4];
    const float* We2  = (const float*)d_in[5];
    const float* be2  = (const float*)d_in[6];
    const float* Wf1a = (const float*)d_in[7];
    const float* bf1a = (const float*)d_in[8];
    const float* Wf1b = (const float*)d_in[9];
    const float* bf1b = (const float*)d_in[10];
    const float* Wf1c = (const float*)d_in[11];
    const float* bf1c = (const float*)d_in[12];
    const float* Wf2a = (const float*)d_in[13];
    const float* bf2a = (const float*)d_in[14];
    const float* Wf2b = (const float*)d_in[15];
    const float* bf2b = (const float*)d_in[16];
    const float* Wf2c = (const float*)d_in[17];
    const float* bf2c = (const float*)d_in[18];
    float* out = (float*)d_out;

    const int fps_smem  = 3 * NN * sizeof(float);      // 98304
    const int knn_smem  = 3 * NN * sizeof(float);      // 98304
    const int enc_smem  = 14528 * sizeof(float);       // 58112
    const int base_smem = 20480 * sizeof(float);       // 81920
    const int fold_smem = 19108 * sizeof(float);       // 76432
    cudaFuncSetAttribute(fps_kernel,  cudaFuncAttributeMaxDynamicSharedMemorySize, fps_smem);
    cudaFuncSetAttribute(knn_kernel,  cudaFuncAttributeMaxDynamicSharedMemorySize, knn_smem);
    cudaFuncSetAttribute(enc_kernel,  cudaFuncAttributeMaxDynamicSharedMemorySize, enc_smem);
    cudaFuncSetAttribute(base_kernel, cudaFuncAttributeMaxDynamicSharedMemorySize, base_smem);
    cudaFuncSetAttribute(fold_kernel, cudaFuncAttributeMaxDynamicSharedMemorySize, fold_smem);

    fps_kernel <<<BB, 1024, fps_smem>>>(data);
    knn_kernel <<<(BB * NC) / 8, 256, knn_smem>>>(data, perm);
    enc_kernel <<<MTOT / 2, 256, enc_smem>>>(We1, be1, We2, be2);
    base_kernel<<<dim3(MTOT / 64, 2), 256, base_smem>>>(Wf1a, bf1a, Wf2a, bf2a);
    fold_kernel<<<MTOT, 256, fold_smem>>>(grid, Wf1a, Wf1b, bf1b, Wf1c, bf1c,
                                          Wf2a, Wf2b, bf2b, Wf2c, bf2c, out);
}

// round 6
// speedup vs baseline: 1.1930x; 1.0408x over previous
#include <cuda_runtime.h>
#include <math.h>

#define BB 32
#define NN 8192
#define NC 256
#define NP 32
#define MTOT (BB * NC)          // 8192 patches

// ---------------- scratch (device globals; no allocation allowed) ----------
__device__ float    g_centers[BB * NC * 3];
__device__ float    g_local  [MTOT * NP * 3];
__device__ float    g_cmean  [MTOT * 3];
__device__ unsigned g_scale_bits;
__device__ float    g_codeT [256 * MTOT];      // code transposed [c][m]
__device__ float    g_base1 [MTOT * 256];      // [m][c]
__device__ float    g_base2 [MTOT * 256];      // [m][c]

// ---------------- packed fp32x2 helpers (sm_100+) ---------------------------
__device__ __forceinline__ unsigned long long pack2(float w) {
    unsigned long long r;
    asm("mov.b64 %0, {%1, %1};" : "=l"(r) : "f"(w));
    return r;
}
__device__ __forceinline__ void fma2(unsigned long long& acc,
                                     unsigned long long a, unsigned long long b) {
    asm("fma.rn.f32x2 %0, %1, %2, %0;" : "+l"(acc) : "l"(a), "l"(b));
}
__device__ __forceinline__ float2 unpack2(unsigned long long v) {
    float2 r;
    asm("mov.b64 {%0, %1}, %2;" : "=f"(r.x), "=f"(r.y) : "l"(v));
    return r;
}

// ============================================================================
// K1: FPS — one block per batch, points/mind in registers, atomic-free block
// argmax (per-warp shfl reduce -> 32 smem slots -> warp0 shfl reduce).
// Exact jnp.argmax tie semantics via key = (value_bits << 32) | (NN-1-idx).
// Distance arithmetic replicates the reference exactly (no FMA contraction).
// ============================================================================
__global__ __launch_bounds__(1024, 1)
void fps_kernel(const float* __restrict__ data)
{
    extern __shared__ float sm[];
    float* sx = sm;
    float* sy = sm + NN;
    float* sz = sm + 2 * NN;
    __shared__ unsigned long long skeys[32];
    __shared__ unsigned long long sres;

    const int b = blockIdx.x;
    const int t = threadIdx.x;
    const int wid = t >> 5, lane = t & 31;
    if (b == 0 && t == 0) g_scale_bits = 0u;   // reset every launch (graph replay safe)

    const float* dp = data + (size_t)b * 3 * NN;
    for (int n = t; n < NN; n += 1024) {
        sx[n] = dp[n];
        sy[n] = dp[NN + n];
        sz[n] = dp[2 * NN + n];
    }
    __syncthreads();

    float rx[8], ry[8], rz[8], md[8];
    const int base = t * 8;
    #pragma unroll
    for (int j = 0; j < 8; j++) {
        rx[j] = sx[base + j];
        ry[j] = sy[base + j];
        rz[j] = sz[base + j];
        md[j] = 3.4e38f;
    }

    float px = sx[0], py = sy[0], pz = sz[0];
    if (t == 0) {
        float* c = g_centers + (size_t)(b * NC) * 3;
        c[0] = px; c[1] = py; c[2] = pz;
    }

    for (int i = 1; i < NC; i++) {
        float bv = -1.0f; int bi = base;
        #pragma unroll
        for (int j = 0; j < 8; j++) {
            float dx = __fadd_rn(rx[j], -px);
            float dy = __fadd_rn(ry[j], -py);
            float dz = __fadd_rn(rz[j], -pz);
            float d  = __fadd_rn(__fadd_rn(__fmul_rn(dx, dx), __fmul_rn(dy, dy)),
                                 __fmul_rn(dz, dz));
            float m  = fminf(md[j], d);
            md[j] = m;
            if (m > bv) { bv = m; bi = base + j; }
        }
        unsigned long long key =
            ((unsigned long long)__float_as_uint(bv) << 32) | (unsigned)(NN - 1 - bi);
        #pragma unroll
        for (int off = 16; off; off >>= 1) {
            unsigned long long o = __shfl_down_sync(0xFFFFFFFFu, key, off);
            if (o > key) key = o;
        }
        if (lane == 0) skeys[wid] = key;
        __syncthreads();
        if (t < 32) {
            unsigned long long k2 = skeys[t];
            #pragma unroll
            for (int off = 16; off; off >>= 1) {
                unsigned long long o = __shfl_down_sync(0xFFFFFFFFu, k2, off);
                if (o > k2) k2 = o;
            }
            if (t == 0) sres = k2;
        }
        __syncthreads();
        const unsigned long long kk = sres;
        const int sel = NN - 1 - (int)(kk & 0xFFFFFFFFull);
        px = sx[sel]; py = sy[sel]; pz = sz[sel];
        if (t == 0) {
            float* c = g_centers + (size_t)(b * NC + i) * 3;
            c[0] = px; c[1] = py; c[2] = pz;
        }
    }
}

// ============================================================================
// K2: kNN set of 32 — one warp per center, 8 centers/block, points in smem.
// ============================================================================
__global__ __launch_bounds__(256, 2)
void knn_kernel(const float* __restrict__ data, const int* __restrict__ perm)
{
    extern __shared__ float sp[];                    // [3*NN]
    const int warp = threadIdx.x >> 5;
    const int lane = threadIdx.x & 31;
    const int w  = blockIdx.x * 8 + warp;
    const int b  = w >> 8;
    const int ci = w & 255;
    const int p  = perm[ci];

    const float* dp = data + (size_t)b * 3 * NN;
    for (int i = threadIdx.x; i < 3 * NN / 4; i += 256)
        ((float4*)sp)[i] = ((const float4*)dp)[i];
    __syncthreads();
    const float* sx = sp, *sy = sp + NN, *sz = sp + 2 * NN;

    const float* cc = g_centers + (size_t)(b * NC + p) * 3;
    const float cx = cc[0], cy = cc[1], cz = cc[2];
    const float cs = (cx * cx + cy * cy) + cz * cz;

    float px = sx[lane], py = sy[lane], pz = sz[lane];
    float ps  = (px * px + py * py) + pz * pz;
    float dot = (cx * px + cy * py) + cz * pz;
    float kd  = (cs + ps) - 2.0f * dot;
    int   ki  = lane;
    float cm = kd;
    #pragma unroll
    for (int off = 16; off; off >>= 1) cm = fmaxf(cm, __shfl_xor_sync(0xFFFFFFFFu, cm, off));

    for (int bse = 32; bse < NN; bse += 32) {
        const int n = bse + lane;
        px = sx[n]; py = sy[n]; pz = sz[n];
        ps  = (px * px + py * py) + pz * pz;
        dot = (cx * px + cy * py) + cz * pz;
        const float d = (cs + ps) - 2.0f * dot;

        unsigned m = __ballot_sync(0xFFFFFFFFu, d < cm);
        while (m) {
            const int src = __ffs(m) - 1; m &= m - 1;
            const float dc = __shfl_sync(0xFFFFFFFFu, d, src);
            if (dc < cm) {
                float mv = kd; int mi = ki, ml = lane;
                #pragma unroll
                for (int off = 16; off; off >>= 1) {
                    float ov = __shfl_down_sync(0xFFFFFFFFu, mv, off);
                    int   oi = __shfl_down_sync(0xFFFFFFFFu, mi, off);
                    int   ol = __shfl_down_sync(0xFFFFFFFFu, ml, off);
                    if (ov > mv || (ov == mv && oi > mi)) { mv = ov; mi = oi; ml = ol; }
                }
                ml = __shfl_sync(0xFFFFFFFFu, ml, 0);
                if (lane == ml) { kd = dc; ki = bse + src; }
                float q = kd;
                #pragma unroll
                for (int off = 16; off; off >>= 1) q = fmaxf(q, __shfl_xor_sync(0xFFFFFFFFu, q, off));
                cm = q;
            }
        }
    }

    const float nx = sx[ki], ny = sy[ki], nz = sz[ki];
    float sxx = nx, syy = ny, szz = nz;
    #pragma unroll
    for (int off = 16; off; off >>= 1) {
        sxx += __shfl_xor_sync(0xFFFFFFFFu, sxx, off);
        syy += __shfl_xor_sync(0xFFFFFFFFu, syy, off);
        szz += __shfl_xor_sync(0xFFFFFFFFu, szz, off);
    }
    const float mx = sxx * (1.0f / 32.0f);
    const float my = syy * (1.0f / 32.0f);
    const float mz = szz * (1.0f / 32.0f);
    const float lx = nx - mx, ly = ny - my, lz = nz - mz;
    const float ns = (lx * lx + ly * ly) + lz * lz;
    float wm = ns;
    #pragma unroll
    for (int off = 16; off; off >>= 1) wm = fmaxf(wm, __shfl_xor_sync(0xFFFFFFFFu, wm, off));
    if (lane == 0) atomicMax(&g_scale_bits, __float_as_uint(wm));

    float* lp = g_local + ((size_t)w * NP + lane) * 3;
    lp[0] = lx; lp[1] = ly; lp[2] = lz;
    if (lane < 3) g_cmean[(size_t)w * 3 + lane] = (lane == 0) ? mx : ((lane == 1) ? my : mz);
}

// ============================================================================
// K3a enc: 2 patches/block (64 rows). We2 staged in 16-k smem slices with
// register double-buffer (prefetch next slice during compute).
// ============================================================================
__global__ __launch_bounds__(256, 2)
void enc_kernel(const float* __restrict__ We1, const float* __restrict__ be1,
                const float* __restrict__ We2, const float* __restrict__ be2)
{
    extern __shared__ float s[];
    float* h1T   = s;            // [128][64]   8192
    float* stage = s + 8192;     // [16][256]   4096
    float* xs    = s + 12288;    // [64][3]      192
    float* codep = s + 12480;    // [8][256]    2048  -> total 14528 fl

    const int t  = threadIdx.x;
    const int m0 = blockIdx.x * 2;
    const float scale = sqrtf(__uint_as_float(g_scale_bits));

    if (t < 192) xs[t] = g_local[(size_t)blockIdx.x * 192 + t] / scale;
    __syncthreads();

    // enc1: h1T[k][r] = relu(xs[r]·We1[:,k] + be1[k])
    #pragma unroll
    for (int i = 0; i < 32; i++) {
        const int o = i * 256 + t;
        const int k = o >> 6, r = o & 63;
        float v = xs[r * 3] * We1[k] + xs[r * 3 + 1] * We1[128 + k]
                + xs[r * 3 + 2] * We1[256 + k] + be1[k];
        h1T[k * 64 + r] = fmaxf(v, 0.0f);
    }

    const int rg = t & 7, cg = t >> 3;
    const int r0 = rg * 8, c0 = cg * 8;
    unsigned long long acc2[4][8];
    #pragma unroll
    for (int i = 0; i < 4; i++)
        #pragma unroll
        for (int j = 0; j < 8; j++) acc2[i][j] = 0ull;

    float4 pf[4];
    {
        const float4* src = (const float4*)We2;
        #pragma unroll
        for (int i = 0; i < 4; i++) pf[i] = src[t + 256 * i];
    }
    for (int sl = 0; sl < 8; sl++) {
        __syncthreads();
        #pragma unroll
        for (int i = 0; i < 4; i++) ((float4*)stage)[t + 256 * i] = pf[i];
        __syncthreads();
        if (sl < 7) {
            const float4* src = (const float4*)(We2 + (sl + 1) * 16 * 256);
            #pragma unroll
            for (int i = 0; i < 4; i++) pf[i] = src[t + 256 * i];
        }
        #pragma unroll 4
        for (int k = 0; k < 16; k++) {
            const int kk = sl * 16 + k;
            const ulonglong2 a0 = *(const ulonglong2*)(h1T + kk * 64 + r0);
            const ulonglong2 a1 = *(const ulonglong2*)(h1T + kk * 64 + r0 + 4);
            const unsigned long long ap[4] = {a0.x, a0.y, a1.x, a1.y};
            const float4 w0 = *(const float4*)(stage + k * 256 + c0);
            const float4 w1 = *(const float4*)(stage + k * 256 + c0 + 4);
            const unsigned long long wp[8] = {pack2(w0.x), pack2(w0.y), pack2(w0.z), pack2(w0.w),
                                              pack2(w1.x), pack2(w1.y), pack2(w1.z), pack2(w1.w)};
            #pragma unroll
            for (int i = 0; i < 4; i++)
                #pragma unroll
                for (int j = 0; j < 8; j++) fma2(acc2[i][j], ap[i], wp[j]);
        }
    }
    #pragma unroll
    for (int j = 0; j < 8; j++) {
        const float bb = be2[c0 + j];
        float mj = 0.0f;
        #pragma unroll
        for (int i = 0; i < 4; i++) {
            const float2 v = unpack2(acc2[i][j]);
            mj = fmaxf(mj, fmaxf(fmaxf(v.x + bb, 0.0f), fmaxf(v.y + bb, 0.0f)));
        }
        codep[rg * 256 + c0 + j] = mj;
    }
    __syncthreads();
    {
        const int c = t;
        const float v0 = fmaxf(fmaxf(codep[c], codep[256 + c]),
                               fmaxf(codep[512 + c], codep[768 + c]));
        const float v1 = fmaxf(fmaxf(codep[1024 + c], codep[1280 + c]),
                               fmaxf(codep[1536 + c], codep[1792 + c]));
        *(float2*)(g_codeT + (size_t)c * MTOT + m0) = make_float2(v0, v1);
    }
}

// ============================================================================
// K3b base: base{1,2}[m][c] = code[m]·Wf{1,2}a[:256,c] + b.
// 2D grid (matrix on blockIdx.y), 16-k slices, register double-buffer.
// ============================================================================
__global__ __launch_bounds__(256, 2)
void base_kernel(const float* __restrict__ Wf1a, const float* __restrict__ bf1a,
                 const float* __restrict__ Wf2a, const float* __restrict__ bf2a)
{
    extern __shared__ float s[];
    float* ct    = s;            // [256 k][64 m]  16384
    float* stage = s + 16384;    // [16 k][256 c]   4096  -> 20480 fl

    const int t  = threadIdx.x;
    const int m0 = blockIdx.x * 64;
    const int mat = blockIdx.y;
    const float* W  = mat ? Wf2a : Wf1a;
    const float* bv = mat ? bf2a : bf1a;
    float* dst = mat ? g_base2 : g_base1;

    for (int i = t; i < 4096; i += 256) {
        const int k = i >> 4, mq = i & 15;
        *(float4*)(ct + k * 64 + mq * 4) =
            *(const float4*)(g_codeT + (size_t)k * MTOT + m0 + mq * 4);
    }

    const int rg = t & 7, cg = t >> 3;
    const int r0 = rg * 8, c0 = cg * 8;

    unsigned long long acc2[4][8];
    #pragma unroll
    for (int i = 0; i < 4; i++)
        #pragma unroll
        for (int j = 0; j < 8; j++) acc2[i][j] = 0ull;

    float4 pf[4];
    {
        const float4* src = (const float4*)W;
        #pragma unroll
        for (int i = 0; i < 4; i++) pf[i] = src[t + 256 * i];
    }
    for (int sl = 0; sl < 16; sl++) {
        __syncthreads();
        #pragma unroll
        for (int i = 0; i < 4; i++) ((float4*)stage)[t + 256 * i] = pf[i];
        __syncthreads();
        if (sl < 15) {
            const float4* src = (const float4*)(W + (sl + 1) * 16 * 256);
            #pragma unroll
            for (int i = 0; i < 4; i++) pf[i] = src[t + 256 * i];
        }
        #pragma unroll 4
        for (int k = 0; k < 16; k++) {
            const int kk = sl * 16 + k;
            const ulonglong2 a0 = *(const ulonglong2*)(ct + kk * 64 + r0);
            const ulonglong2 a1 = *(const ulonglong2*)(ct + kk * 64 + r0 + 4);
            const unsigned long long ap[4] = {a0.x, a0.y, a1.x, a1.y};
            const float4 w0 = *(const float4*)(stage + k * 256 + c0);
            const float4 w1 = *(const float4*)(stage + k * 256 + c0 + 4);
            const unsigned long long wp[8] = {pack2(w0.x), pack2(w0.y), pack2(w0.z), pack2(w0.w),
                                              pack2(w1.x), pack2(w1.y), pack2(w1.z), pack2(w1.w)};
            #pragma unroll
            for (int i = 0; i < 4; i++)
                #pragma unroll
                for (int j = 0; j < 8; j++) fma2(acc2[i][j], ap[i], wp[j]);
        }
    }
    #pragma unroll
    for (int i = 0; i < 4; i++) {
        float4 lo0, lo1, hi0, hi1;
        float* l0 = (float*)&lo0; float* l1 = (float*)&lo1;
        float* h0 = (float*)&hi0; float* h1 = (float*)&hi1;
        #pragma unroll
        for (int j = 0; j < 8; j++) {
            const float bb = bv[c0 + j];
            const float2 v = unpack2(acc2[i][j]);
            if (j < 4) { l0[j] = v.x + bb; h0[j] = v.y + bb; }
            else       { l1[j - 4] = v.x + bb; h1[j - 4] = v.y + bb; }
        }
        float* d0 = dst + (size_t)(m0 + r0 + 2 * i) * 256 + c0;
        float* d1 = dst + (size_t)(m0 + r0 + 2 * i + 1) * 256 + c0;
        *(float4*)d0 = lo0; *(float4*)(d0 + 4) = lo1;
        *(float4*)d1 = hi0; *(float4*)(d1 + 4) = hi1;
    }
}

// ============================================================================
// K3c fold: 1 patch/block, 4r x 4c tiles. OCCUPANCY 3 (was 2): 16-k weight
// slices shrink smem to 68 KB so 3 blocks/SM fit, and __launch_bounds__(256,3)
// caps regs at 85 -> 24 warps/SM = 6 eligible warps/SMSP for stall coverage.
// ============================================================================
__global__ __launch_bounds__(256, 3)
void fold_kernel(const float* __restrict__ grid_,
                 const float* __restrict__ Wf1a,
                 const float* __restrict__ Wf1b, const float* __restrict__ bf1b,
                 const float* __restrict__ Wf1c, const float* __restrict__ bf1c,
                 const float* __restrict__ Wf2a,
                 const float* __restrict__ Wf2b, const float* __restrict__ bf2b,
                 const float* __restrict__ Wf2c, const float* __restrict__ bf2c,
                 float* __restrict__ out)
{
    extern __shared__ float s[];
    float* hfT   = s;            // [256 k][32 r]  8192
    float* hf2T  = s + 8192;     // [128 k][32 r]  4096
    float* stage = s + 12288;    // [16 k][128 c]  2048
    float* b1    = s + 14336;    // [256]
    float* b2    = s + 14592;    // [256]
    float* wg    = s + 14848;    // [2][256]
    float* wf    = s + 15360;    // [3][256]
    float* Wc1   = s + 16128;    // [384]
    float* Wc2   = s + 16512;    // [384]
    float* gx    = s + 16896;    // [32]
    float* gy    = s + 16928;    // [32]
    float* fv    = s + 16960;    // [96]
    float* cm    = s + 17056;    // [4]   -> total 17060 fl = 68240 B

    const int t = threadIdx.x;
    const int m = blockIdx.x;
    const float scale = sqrtf(__uint_as_float(g_scale_bits));

    b1[t] = g_base1[(size_t)m * 256 + t];
    b2[t] = g_base2[(size_t)m * 256 + t];
    wg[t]       = Wf1a[256 * 256 + t];
    wg[256 + t] = Wf1a[257 * 256 + t];
    wf[t]       = Wf2a[256 * 256 + t];
    wf[256 + t] = Wf2a[257 * 256 + t];
    wf[512 + t] = Wf2a[258 * 256 + t];
    for (int i = t; i < 384; i += 256) { Wc1[i] = Wf1c[i]; Wc2[i] = Wf2c[i]; }
    if (t < 32) { gx[t] = grid_[2 * t]; gy[t] = grid_[2 * t + 1]; }
    if (t < 3)  cm[t] = g_cmean[(size_t)m * 3 + t];
    __syncthreads();

    // hf: [256 k][32 r]
    #pragma unroll
    for (int i = 0; i < 32; i++) {
        const int o = i * 256 + t;
        const int k = o >> 5, r = o & 31;
        hfT[k * 32 + r] = fmaxf(b1[k] + gx[r] * wg[k] + gy[r] * wg[256 + k], 0.0f);
    }

    const int rg = t & 7, cg = t >> 3;
    const int r0 = rg * 4, c0 = cg * 4;

    #pragma unroll
    for (int stagei = 0; stagei < 2; stagei++) {
        const float* W  = stagei ? Wf2b : Wf1b;
        const float* bv = stagei ? bf2b : bf1b;

        unsigned long long acc2[2][4];
        #pragma unroll
        for (int i = 0; i < 2; i++)
            #pragma unroll
            for (int j = 0; j < 4; j++) acc2[i][j] = 0ull;

        float4 pf[2];
        {
            const float4* src = (const float4*)W;
            #pragma unroll
            for (int i = 0; i < 2; i++) pf[i] = src[t + 256 * i];
        }
        for (int sl = 0; sl < 16; sl++) {
            __syncthreads();
            #pragma unroll
            for (int i = 0; i < 2; i++) ((float4*)stage)[t + 256 * i] = pf[i];
            __syncthreads();
            if (sl < 15) {
                const float4* src = (const float4*)(W + (sl + 1) * 16 * 128);
                #pragma unroll
                for (int i = 0; i < 2; i++) pf[i] = src[t + 256 * i];
            }
            #pragma unroll 8
            for (int k = 0; k < 16; k++) {
                const int kk = sl * 16 + k;
                const ulonglong2 a = *(const ulonglong2*)(hfT + kk * 32 + r0);
                const float4 w = *(const float4*)(stage + k * 128 + c0);
                const unsigned long long wp[4] = {pack2(w.x), pack2(w.y),
                                                  pack2(w.z), pack2(w.w)};
                #pragma unroll
                for (int j = 0; j < 4; j++) { fma2(acc2[0][j], a.x, wp[j]);
                                              fma2(acc2[1][j], a.y, wp[j]); }
            }
        }
        #pragma unroll
        for (int j = 0; j < 4; j++) {
            const float bb = bv[c0 + j];
            const float2 v0 = unpack2(acc2[0][j]);
            const float2 v1 = unpack2(acc2[1][j]);
            hf2T[(c0 + j) * 32 + r0 + 0] = fmaxf(v0.x + bb, 0.0f);
            hf2T[(c0 + j) * 32 + r0 + 1] = fmaxf(v0.y + bb, 0.0f);
            hf2T[(c0 + j) * 32 + r0 + 2] = fmaxf(v1.x + bb, 0.0f);
            hf2T[(c0 + j) * 32 + r0 + 3] = fmaxf(v1.y + bb, 0.0f);
        }
        __syncthreads();

        if (stagei == 0) {
            // fold1c: fv[r][q] = hf2[r]·Wf1c[:,q] + bf1c[q]
            if (t < 96) {
                const int r = t / 3, q = t - (t / 3) * 3;
                float acc = bf1c[q];
                #pragma unroll 8
                for (int k = 0; k < 128; k++) acc += hf2T[k * 32 + r] * Wc1[k * 3 + q];
                fv[t] = acc;
            }
            __syncthreads();
            // hg: reuse hfT
            #pragma unroll
            for (int i = 0; i < 32; i++) {
                const int o = i * 256 + t;
                const int k = o >> 5, r = o & 31;
                hfT[k * 32 + r] = fmaxf(b2[k] + fv[r * 3] * wf[k]
                                        + fv[r * 3 + 1] * wf[256 + k]
                                        + fv[r * 3 + 2] * wf[512 + k], 0.0f);
            }
            __syncthreads();
        } else {
            // fold2c + output
            if (t < 96) {
                const int r = t / 3, q = t - (t / 3) * 3;
                float acc = bf2c[q];
                #pragma unroll 8
                for (int k = 0; k < 128; k++) acc += hf2T[k * 32 + r] * Wc2[k * 3 + q];
                out[(size_t)m * 96 + t] = acc * scale + cm[q];
            }
        }
    }
}

// ============================================================================
extern "C" void kernel_launch(void* const* d_in, const int* in_sizes, int n_in,
                              void* d_out, int out_size)
{
    (void)in_sizes; (void)n_in; (void)out_size;
    const float* data = (const float*)d_in[0];
    const int*   perm = (const int*)  d_in[1];
    const float* grid = (const float*)d_in[2];
    const float* We1  = (const float*)d_in[3];
    const float* be1  = (const float*)d_in[4];
    const float* We2  = (const float*)d_in[5];
    const float* be2  = (const float*)d_in[6];
    const float* Wf1a = (const float*)d_in[7];
    const float* bf1a = (const float*)d_in[8];
    const float* Wf1b = (const float*)d_in[9];
    const float* bf1b = (const float*)d_in[10];
    const float* Wf1c = (const float*)d_in[11];
    const float* bf1c = (const float*)d_in[12];
    const float* Wf2a = (const float*)d_in[13];
    const float* bf2a = (const float*)d_in[14];
    const float* Wf2b = (const float*)d_in[15];
    const float* bf2b = (const float*)d_in[16];
    const float* Wf2c = (const float*)d_in[17];
    const float* bf2c = (const float*)d_in[18];
    float* out = (float*)d_out;

    const int fps_smem  = 3 * NN * sizeof(float);      // 98304
    const int knn_smem  = 3 * NN * sizeof(float);      // 98304
    const int enc_smem  = 14528 * sizeof(float);       // 58112
    const int base_smem = 20480 * sizeof(float);       // 81920
    const int fold_smem = 17060 * sizeof(float);       // 68240
    cudaFuncSetAttribute(fps_kernel,  cudaFuncAttributeMaxDynamicSharedMemorySize, fps_smem);
    cudaFuncSetAttribute(knn_kernel,  cudaFuncAttributeMaxDynamicSharedMemorySize, knn_smem);
    cudaFuncSetAttribute(enc_kernel,  cudaFuncAttributeMaxDynamicSharedMemorySize, enc_smem);
    cudaFuncSetAttribute(base_kernel, cudaFuncAttributeMaxDynamicSharedMemorySize, base_smem);
    cudaFuncSetAttribute(fold_kernel, cudaFuncAttributeMaxDynamicSharedMemorySize, fold_smem);

    fps_kernel <<<BB, 1024, fps_smem>>>(data);
    knn_kernel <<<(BB * NC) / 8, 256, knn_smem>>>(data, perm);
    enc_kernel <<<MTOT / 2, 256, enc_smem>>>(We1, be1, We2, be2);
    base_kernel<<<dim3(MTOT / 64, 2), 256, base_smem>>>(Wf1a, bf1a, Wf2a, bf2a);
    fold_kernel<<<MTOT, 256, fold_smem>>>(grid, Wf1a, Wf1b, bf1b, Wf1c, bf1c,
                                          Wf2a, Wf2b, bf2b, Wf2c, bf2c, out);
}

// round 7
// speedup vs baseline: 1.5175x; 1.2721x over previous
#include <cuda_runtime.h>
#include <math.h>

#define BB 32
#define NN 8192
#define NC 256
#define NP 32
#define MTOT (BB * NC)          // 8192 patches

// ---------------- scratch (device globals; no allocation allowed) ----------
__device__ float    g_centers[BB * NC * 3];
__device__ float    g_local  [MTOT * NP * 3];
__device__ float    g_cmean  [MTOT * 3];
__device__ unsigned g_scale_bits;
__device__ float    g_codeT [256 * MTOT];      // code transposed [c][m]
__device__ float    g_base1 [MTOT * 256];      // [m][c]
__device__ float    g_base2 [MTOT * 256];      // [m][c]

// ---------------- packed fp32x2 helpers (sm_100+) ---------------------------
__device__ __forceinline__ unsigned long long pack2(float w) {
    unsigned long long r;
    asm("mov.b64 %0, {%1, %1};" : "=l"(r) : "f"(w));
    return r;
}
__device__ __forceinline__ void fma2(unsigned long long& acc,
                                     unsigned long long a, unsigned long long b) {
    asm("fma.rn.f32x2 %0, %1, %2, %0;" : "+l"(acc) : "l"(a), "l"(b));
}
__device__ __forceinline__ float2 unpack2(unsigned long long v) {
    float2 r;
    asm("mov.b64 {%0, %1}, %2;" : "=f"(r.x), "=f"(r.y) : "l"(v));
    return r;
}

// ---------------- tf32 mma helpers ------------------------------------------
__device__ __forceinline__ float to_tf32(float x) {
    unsigned u;
    asm("cvt.rna.tf32.f32 %0, %1;" : "=r"(u) : "f"(x));
    return __uint_as_float(u);
}
__device__ __forceinline__ void mma_tf32(float* d, const unsigned* a, const unsigned* b) {
    asm volatile(
        "mma.sync.aligned.m16n8k8.row.col.f32.tf32.tf32.f32 "
        "{%0,%1,%2,%3}, {%4,%5,%6,%7}, {%8,%9}, {%0,%1,%2,%3};"
        : "+f"(d[0]), "+f"(d[1]), "+f"(d[2]), "+f"(d[3])
        : "r"(a[0]), "r"(a[1]), "r"(a[2]), "r"(a[3]), "r"(b[0]), "r"(b[1]));
}

// ============================================================================
// K1: FPS — one block per batch, points/mind in registers, atomic-free block
// argmax. Exact jnp.argmax tie semantics via key = (value<<32)|(NN-1-idx).
// Distance arithmetic replicates the reference exactly (no FMA contraction).
// ============================================================================
__global__ __launch_bounds__(1024, 1)
void fps_kernel(const float* __restrict__ data)
{
    extern __shared__ float sm[];
    float* sx = sm;
    float* sy = sm + NN;
    float* sz = sm + 2 * NN;
    __shared__ unsigned long long skeys[32];
    __shared__ unsigned long long sres;

    const int b = blockIdx.x;
    const int t = threadIdx.x;
    const int wid = t >> 5, lane = t & 31;
    if (b == 0 && t == 0) g_scale_bits = 0u;   // reset every launch (graph replay safe)

    const float* dp = data + (size_t)b * 3 * NN;
    for (int n = t; n < NN; n += 1024) {
        sx[n] = dp[n];
        sy[n] = dp[NN + n];
        sz[n] = dp[2 * NN + n];
    }
    __syncthreads();

    float rx[8], ry[8], rz[8], md[8];
    const int base = t * 8;
    #pragma unroll
    for (int j = 0; j < 8; j++) {
        rx[j] = sx[base + j];
        ry[j] = sy[base + j];
        rz[j] = sz[base + j];
        md[j] = 3.4e38f;
    }

    float px = sx[0], py = sy[0], pz = sz[0];
    if (t == 0) {
        float* c = g_centers + (size_t)(b * NC) * 3;
        c[0] = px; c[1] = py; c[2] = pz;
    }

    for (int i = 1; i < NC; i++) {
        float bv = -1.0f; int bi = base;
        #pragma unroll
        for (int j = 0; j < 8; j++) {
            float dx = __fadd_rn(rx[j], -px);
            float dy = __fadd_rn(ry[j], -py);
            float dz = __fadd_rn(rz[j], -pz);
            float d  = __fadd_rn(__fadd_rn(__fmul_rn(dx, dx), __fmul_rn(dy, dy)),
                                 __fmul_rn(dz, dz));
            float m  = fminf(md[j], d);
            md[j] = m;
            if (m > bv) { bv = m; bi = base + j; }
        }
        unsigned long long key =
            ((unsigned long long)__float_as_uint(bv) << 32) | (unsigned)(NN - 1 - bi);
        #pragma unroll
        for (int off = 16; off; off >>= 1) {
            unsigned long long o = __shfl_down_sync(0xFFFFFFFFu, key, off);
            if (o > key) key = o;
        }
        if (lane == 0) skeys[wid] = key;
        __syncthreads();
        if (t < 32) {
            unsigned long long k2 = skeys[t];
            #pragma unroll
            for (int off = 16; off; off >>= 1) {
                unsigned long long o = __shfl_down_sync(0xFFFFFFFFu, k2, off);
                if (o > k2) k2 = o;
            }
            if (t == 0) sres = k2;
        }
        __syncthreads();
        const unsigned long long kk = sres;
        const int sel = NN - 1 - (int)(kk & 0xFFFFFFFFull);
        px = sx[sel]; py = sy[sel]; pz = sz[sel];
        if (t == 0) {
            float* c = g_centers + (size_t)(b * NC + i) * 3;
            c[0] = px; c[1] = py; c[2] = pz;
        }
    }
}

// ============================================================================
// K2: kNN set of 32 — one warp per center, 8 centers/block, points in smem.
// ============================================================================
__global__ __launch_bounds__(256, 2)
void knn_kernel(const float* __restrict__ data, const int* __restrict__ perm)
{
    extern __shared__ float sp[];                    // [3*NN]
    const int warp = threadIdx.x >> 5;
    const int lane = threadIdx.x & 31;
    const int w  = blockIdx.x * 8 + warp;
    const int b  = w >> 8;
    const int ci = w & 255;
    const int p  = perm[ci];

    const float* dp = data + (size_t)b * 3 * NN;
    for (int i = threadIdx.x; i < 3 * NN / 4; i += 256)
        ((float4*)sp)[i] = ((const float4*)dp)[i];
    __syncthreads();
    const float* sx = sp, *sy = sp + NN, *sz = sp + 2 * NN;

    const float* cc = g_centers + (size_t)(b * NC + p) * 3;
    const float cx = cc[0], cy = cc[1], cz = cc[2];
    const float cs = (cx * cx + cy * cy) + cz * cz;

    float px = sx[lane], py = sy[lane], pz = sz[lane];
    float ps  = (px * px + py * py) + pz * pz;
    float dot = (cx * px + cy * py) + cz * pz;
    float kd  = (cs + ps) - 2.0f * dot;
    int   ki  = lane;
    float cm = kd;
    #pragma unroll
    for (int off = 16; off; off >>= 1) cm = fmaxf(cm, __shfl_xor_sync(0xFFFFFFFFu, cm, off));

    for (int bse = 32; bse < NN; bse += 32) {
        const int n = bse + lane;
        px = sx[n]; py = sy[n]; pz = sz[n];
        ps  = (px * px + py * py) + pz * pz;
        dot = (cx * px + cy * py) + cz * pz;
        const float d = (cs + ps) - 2.0f * dot;

        unsigned m = __ballot_sync(0xFFFFFFFFu, d < cm);
        while (m) {
            const int src = __ffs(m) - 1; m &= m - 1;
            const float dc = __shfl_sync(0xFFFFFFFFu, d, src);
            if (dc < cm) {
                float mv = kd; int mi = ki, ml = lane;
                #pragma unroll
                for (int off = 16; off; off >>= 1) {
                    float ov = __shfl_down_sync(0xFFFFFFFFu, mv, off);
                    int   oi = __shfl_down_sync(0xFFFFFFFFu, mi, off);
                    int   ol = __shfl_down_sync(0xFFFFFFFFu, ml, off);
                    if (ov > mv || (ov == mv && oi > mi)) { mv = ov; mi = oi; ml = ol; }
                }
                ml = __shfl_sync(0xFFFFFFFFu, ml, 0);
                if (lane == ml) { kd = dc; ki = bse + src; }
                float q = kd;
                #pragma unroll
                for (int off = 16; off; off >>= 1) q = fmaxf(q, __shfl_xor_sync(0xFFFFFFFFu, q, off));
                cm = q;
            }
        }
    }

    const float nx = sx[ki], ny = sy[ki], nz = sz[ki];
    float sxx = nx, syy = ny, szz = nz;
    #pragma unroll
    for (int off = 16; off; off >>= 1) {
        sxx += __shfl_xor_sync(0xFFFFFFFFu, sxx, off);
        syy += __shfl_xor_sync(0xFFFFFFFFu, syy, off);
        szz += __shfl_xor_sync(0xFFFFFFFFu, szz, off);
    }
    const float mx = sxx * (1.0f / 32.0f);
    const float my = syy * (1.0f / 32.0f);
    const float mz = szz * (1.0f / 32.0f);
    const float lx = nx - mx, ly = ny - my, lz = nz - mz;
    const float ns = (lx * lx + ly * ly) + lz * lz;
    float wm = ns;
    #pragma unroll
    for (int off = 16; off; off >>= 1) wm = fmaxf(wm, __shfl_xor_sync(0xFFFFFFFFu, wm, off));
    if (lane == 0) atomicMax(&g_scale_bits, __float_as_uint(wm));

    float* lp = g_local + ((size_t)w * NP + lane) * 3;
    lp[0] = lx; lp[1] = ly; lp[2] = lz;
    if (lane < 3) g_cmean[(size_t)w * 3 + lane] = (lane == 0) ? mx : ((lane == 1) ? my : mz);
}

// ============================================================================
// K3a enc: 2 patches/block (64 rows). We2 staged in 16-k smem slices with
// register double-buffer (prefetch next slice during compute).
// ============================================================================
__global__ __launch_bounds__(256, 2)
void enc_kernel(const float* __restrict__ We1, const float* __restrict__ be1,
                const float* __restrict__ We2, const float* __restrict__ be2)
{
    extern __shared__ float s[];
    float* h1T   = s;            // [128][64]   8192
    float* stage = s + 8192;     // [16][256]   4096
    float* xs    = s + 12288;    // [64][3]      192
    float* codep = s + 12480;    // [8][256]    2048  -> total 14528 fl

    const int t  = threadIdx.x;
    const int m0 = blockIdx.x * 2;
    const float scale = sqrtf(__uint_as_float(g_scale_bits));

    if (t < 192) xs[t] = g_local[(size_t)blockIdx.x * 192 + t] / scale;
    __syncthreads();

    // enc1: h1T[k][r] = relu(xs[r]·We1[:,k] + be1[k])
    #pragma unroll
    for (int i = 0; i < 32; i++) {
        const int o = i * 256 + t;
        const int k = o >> 6, r = o & 63;
        float v = xs[r * 3] * We1[k] + xs[r * 3 + 1] * We1[128 + k]
                + xs[r * 3 + 2] * We1[256 + k] + be1[k];
        h1T[k * 64 + r] = fmaxf(v, 0.0f);
    }

    const int rg = t & 7, cg = t >> 3;
    const int r0 = rg * 8, c0 = cg * 8;
    unsigned long long acc2[4][8];
    #pragma unroll
    for (int i = 0; i < 4; i++)
        #pragma unroll
        for (int j = 0; j < 8; j++) acc2[i][j] = 0ull;

    float4 pf[4];
    {
        const float4* src = (const float4*)We2;
        #pragma unroll
        for (int i = 0; i < 4; i++) pf[i] = src[t + 256 * i];
    }
    for (int sl = 0; sl < 8; sl++) {
        __syncthreads();
        #pragma unroll
        for (int i = 0; i < 4; i++) ((float4*)stage)[t + 256 * i] = pf[i];
        __syncthreads();
        if (sl < 7) {
            const float4* src = (const float4*)(We2 + (sl + 1) * 16 * 256);
            #pragma unroll
            for (int i = 0; i < 4; i++) pf[i] = src[t + 256 * i];
        }
        #pragma unroll 4
        for (int k = 0; k < 16; k++) {
            const int kk = sl * 16 + k;
            const ulonglong2 a0 = *(const ulonglong2*)(h1T + kk * 64 + r0);
            const ulonglong2 a1 = *(const ulonglong2*)(h1T + kk * 64 + r0 + 4);
            const unsigned long long ap[4] = {a0.x, a0.y, a1.x, a1.y};
            const float4 w0 = *(const float4*)(stage + k * 256 + c0);
            const float4 w1 = *(const float4*)(stage + k * 256 + c0 + 4);
            const unsigned long long wp[8] = {pack2(w0.x), pack2(w0.y), pack2(w0.z), pack2(w0.w),
                                              pack2(w1.x), pack2(w1.y), pack2(w1.z), pack2(w1.w)};
            #pragma unroll
            for (int i = 0; i < 4; i++)
                #pragma unroll
                for (int j = 0; j < 8; j++) fma2(acc2[i][j], ap[i], wp[j]);
        }
    }
    #pragma unroll
    for (int j = 0; j < 8; j++) {
        const float bb = be2[c0 + j];
        float mj = 0.0f;
        #pragma unroll
        for (int i = 0; i < 4; i++) {
            const float2 v = unpack2(acc2[i][j]);
            mj = fmaxf(mj, fmaxf(fmaxf(v.x + bb, 0.0f), fmaxf(v.y + bb, 0.0f)));
        }
        codep[rg * 256 + c0 + j] = mj;
    }
    __syncthreads();
    {
        const int c = t;
        const float v0 = fmaxf(fmaxf(codep[c], codep[256 + c]),
                               fmaxf(codep[512 + c], codep[768 + c]));
        const float v1 = fmaxf(fmaxf(codep[1024 + c], codep[1280 + c]),
                               fmaxf(codep[1536 + c], codep[1792 + c]));
        *(float2*)(g_codeT + (size_t)c * MTOT + m0) = make_float2(v0, v1);
    }
}

// ============================================================================
// K3b base: base{1,2}[m][c] = code[m]·Wf{1,2}a[:256,c] + b.
// 2D grid (matrix on blockIdx.y), 16-k slices, register double-buffer.
// ============================================================================
__global__ __launch_bounds__(256, 2)
void base_kernel(const float* __restrict__ Wf1a, const float* __restrict__ bf1a,
                 const float* __restrict__ Wf2a, const float* __restrict__ bf2a)
{
    extern __shared__ float s[];
    float* ct    = s;            // [256 k][64 m]  16384
    float* stage = s + 16384;    // [16 k][256 c]   4096  -> 20480 fl

    const int t  = threadIdx.x;
    const int m0 = blockIdx.x * 64;
    const int mat = blockIdx.y;
    const float* W  = mat ? Wf2a : Wf1a;
    const float* bv = mat ? bf2a : bf1a;
    float* dst = mat ? g_base2 : g_base1;

    for (int i = t; i < 4096; i += 256) {
        const int k = i >> 4, mq = i & 15;
        *(float4*)(ct + k * 64 + mq * 4) =
            *(const float4*)(g_codeT + (size_t)k * MTOT + m0 + mq * 4);
    }

    const int rg = t & 7, cg = t >> 3;
    const int r0 = rg * 8, c0 = cg * 8;

    unsigned long long acc2[4][8];
    #pragma unroll
    for (int i = 0; i < 4; i++)
        #pragma unroll
        for (int j = 0; j < 8; j++) acc2[i][j] = 0ull;

    float4 pf[4];
    {
        const float4* src = (const float4*)W;
        #pragma unroll
        for (int i = 0; i < 4; i++) pf[i] = src[t + 256 * i];
    }
    for (int sl = 0; sl < 16; sl++) {
        __syncthreads();
        #pragma unroll
        for (int i = 0; i < 4; i++) ((float4*)stage)[t + 256 * i] = pf[i];
        __syncthreads();
        if (sl < 15) {
            const float4* src = (const float4*)(W + (sl + 1) * 16 * 256);
            #pragma unroll
            for (int i = 0; i < 4; i++) pf[i] = src[t + 256 * i];
        }
        #pragma unroll 4
        for (int k = 0; k < 16; k++) {
            const int kk = sl * 16 + k;
            const ulonglong2 a0 = *(const ulonglong2*)(ct + kk * 64 + r0);
            const ulonglong2 a1 = *(const ulonglong2*)(ct + kk * 64 + r0 + 4);
            const unsigned long long ap[4] = {a0.x, a0.y, a1.x, a1.y};
            const float4 w0 = *(const float4*)(stage + k * 256 + c0);
            const float4 w1 = *(const float4*)(stage + k * 256 + c0 + 4);
            const unsigned long long wp[8] = {pack2(w0.x), pack2(w0.y), pack2(w0.z), pack2(w0.w),
                                              pack2(w1.x), pack2(w1.y), pack2(w1.z), pack2(w1.w)};
            #pragma unroll
            for (int i = 0; i < 4; i++)
                #pragma unroll
                for (int j = 0; j < 8; j++) fma2(acc2[i][j], ap[i], wp[j]);
        }
    }
    #pragma unroll
    for (int i = 0; i < 4; i++) {
        float4 lo0, lo1, hi0, hi1;
        float* l0 = (float*)&lo0; float* l1 = (float*)&lo1;
        float* h0 = (float*)&hi0; float* h1 = (float*)&hi1;
        #pragma unroll
        for (int j = 0; j < 8; j++) {
            const float bb = bv[c0 + j];
            const float2 v = unpack2(acc2[i][j]);
            if (j < 4) { l0[j] = v.x + bb; h0[j] = v.y + bb; }
            else       { l1[j - 4] = v.x + bb; h1[j - 4] = v.y + bb; }
        }
        float* d0 = dst + (size_t)(m0 + r0 + 2 * i) * 256 + c0;
        float* d1 = dst + (size_t)(m0 + r0 + 2 * i + 1) * 256 + c0;
        *(float4*)d0 = lo0; *(float4*)(d0 + 4) = lo1;
        *(float4*)d1 = hi0; *(float4*)(d1 + 4) = hi1;
    }
}

// ============================================================================
// K3c fold: 1 patch/block, TENSOR-CORE GEMMs (mma.sync.m16n8k8.tf32).
// A = hf[32 r][260] (tf32, conflict-free frag loads), B = weight slice
// [32 k][132] (tf32, float4-staged, register-prefetched). 8 warps x 16 cols,
// 2x2 m16n8 tiles, fp32 accum. fold1c/2c remain exact fp32. Occupancy 3.
// ============================================================================
__global__ __launch_bounds__(256, 3)
void fold_kernel(const float* __restrict__ grid_,
                 const float* __restrict__ Wf1a,
                 const float* __restrict__ Wf1b, const float* __restrict__ bf1b,
                 const float* __restrict__ Wf1c, const float* __restrict__ bf1c,
                 const float* __restrict__ Wf2a,
                 const float* __restrict__ Wf2b, const float* __restrict__ bf2b,
                 const float* __restrict__ Wf2c, const float* __restrict__ bf2c,
                 float* __restrict__ out)
{
    extern __shared__ float s[];
    float* hfA   = s;              // [32 r][260] tf32  8320
    float* hf2   = s + 8320;       // [32 r][132] f32   4224
    float* stage = s + 12544;      // [32 k][132] tf32  4224
    float* Wc1   = s + 16768;      // [384]
    float* Wc2   = s + 17152;      // [384]
    float* gx    = s + 17536;      // [32]
    float* gy    = s + 17568;      // [32]
    float* fv    = s + 17600;      // [96]
    float* cm    = s + 17696;      // [4]  -> total 17700 fl = 70800 B

    const int t = threadIdx.x;
    const int m = blockIdx.x;
    const float scale = sqrtf(__uint_as_float(g_scale_bits));

    // per-thread (k = t) constants for the A-build loops — no smem needed
    const float b1t = g_base1[(size_t)m * 256 + t];
    const float b2t = g_base2[(size_t)m * 256 + t];
    const float wg0 = Wf1a[256 * 256 + t], wg1 = Wf1a[257 * 256 + t];
    const float wf0 = Wf2a[256 * 256 + t], wf1 = Wf2a[257 * 256 + t],
                wf2 = Wf2a[258 * 256 + t];
    for (int i = t; i < 384; i += 256) { Wc1[i] = Wf1c[i]; Wc2[i] = Wf2c[i]; }
    if (t < 32) { gx[t] = grid_[2 * t]; gy[t] = grid_[2 * t + 1]; }
    if (t < 3)  cm[t] = g_cmean[(size_t)m * 3 + t];
    __syncthreads();

    // A build, stage 1: hfA[r][k=t] = tf32(relu(b1 + gx*wgA0 + gy*wgA1))
    #pragma unroll 8
    for (int r = 0; r < 32; r++)
        hfA[r * 260 + t] = to_tf32(fmaxf(b1t + gx[r] * wg0 + gy[r] * wg1, 0.0f));

    const int lane = t & 31, g = lane >> 2, tig = lane & 3;
    const int wb = (t >> 5) * 16;              // warp's 16-column strip
    int skj[4], scj[4];                        // staging assignment
    #pragma unroll
    for (int i = 0; i < 4; i++) { int f = t + 256 * i; skj[i] = f >> 5; scj[i] = (f & 31) * 4; }

    #pragma unroll
    for (int stagei = 0; stagei < 2; stagei++) {
        const float* W  = stagei ? Wf2b : Wf1b;
        const float* bv = stagei ? bf2b : bf1b;

        float d[2][2][4];
        #pragma unroll
        for (int mt = 0; mt < 2; mt++)
            #pragma unroll
            for (int nt = 0; nt < 2; nt++)
                #pragma unroll
                for (int j = 0; j < 4; j++) d[mt][nt][j] = 0.0f;

        float4 pf[4];
        #pragma unroll
        for (int i = 0; i < 4; i++)
            pf[i] = *(const float4*)(W + skj[i] * 128 + scj[i]);

        for (int sl = 0; sl < 8; sl++) {             // 8 slices of 32 k
            __syncthreads();                          // prev slice consumed / hfA ready
            #pragma unroll
            for (int i = 0; i < 4; i++) {
                float4 o = make_float4(to_tf32(pf[i].x), to_tf32(pf[i].y),
                                       to_tf32(pf[i].z), to_tf32(pf[i].w));
                *(float4*)(stage + skj[i] * 132 + scj[i]) = o;
            }
            __syncthreads();
            if (sl < 7) {
                #pragma unroll
                for (int i = 0; i < 4; i++)
                    pf[i] = *(const float4*)(W + ((sl + 1) * 32 + skj[i]) * 128 + scj[i]);
            }
            const int kg0 = sl * 32;
            #pragma unroll
            for (int ks = 0; ks < 4; ks++) {         // 4 k-steps of 8
                const int kl = ks * 8;
                unsigned a[2][4];
                #pragma unroll
                for (int mt = 0; mt < 2; mt++) {
                    const float* ap = hfA + (mt * 16 + g) * 260 + kg0 + kl + tig;
                    a[mt][0] = __float_as_uint(ap[0]);
                    a[mt][1] = __float_as_uint(ap[8 * 260]);
                    a[mt][2] = __float_as_uint(ap[4]);
                    a[mt][3] = __float_as_uint(ap[8 * 260 + 4]);
                }
                #pragma unroll
                for (int nt = 0; nt < 2; nt++) {
                    const float* bp = stage + (kl + tig) * 132 + wb + nt * 8 + g;
                    unsigned b[2];
                    b[0] = __float_as_uint(bp[0]);
                    b[1] = __float_as_uint(bp[4 * 132]);
                    mma_tf32(d[0][nt], a[0], b);
                    mma_tf32(d[1][nt], a[1], b);
                }
            }
        }

        // epilogue: bias + relu -> hf2[r][c]
        #pragma unroll
        for (int nt = 0; nt < 2; nt++) {
            const int col = wb + nt * 8 + 2 * tig;
            const float bb0 = bv[col], bb1 = bv[col + 1];
            #pragma unroll
            for (int mt = 0; mt < 2; mt++) {
                const int r = mt * 16 + g;
                *(float2*)(hf2 + r * 132 + col) =
                    make_float2(fmaxf(d[mt][nt][0] + bb0, 0.0f),
                                fmaxf(d[mt][nt][1] + bb1, 0.0f));
                *(float2*)(hf2 + (r + 8) * 132 + col) =
                    make_float2(fmaxf(d[mt][nt][2] + bb0, 0.0f),
                                fmaxf(d[mt][nt][3] + bb1, 0.0f));
            }
        }
        __syncthreads();

        if (stagei == 0) {
            // fold1c: fv[r][q] = hf2[r]·Wf1c[:,q] + bf1c[q]  (exact fp32)
            if (t < 96) {
                const int r = t / 3, q = t - (t / 3) * 3;
                float acc = bf1c[q];
                #pragma unroll 8
                for (int k = 0; k < 128; k++) acc += hf2[r * 132 + k] * Wc1[k * 3 + q];
                fv[t] = acc;
            }
            __syncthreads();
            // A build, stage 2
            #pragma unroll 8
            for (int r = 0; r < 32; r++)
                hfA[r * 260 + t] = to_tf32(fmaxf(b2t + fv[3 * r] * wf0
                                                 + fv[3 * r + 1] * wf1
                                                 + fv[3 * r + 2] * wf2, 0.0f));
            // visibility ensured by first slice __syncthreads of stage 2
        } else {
            // fold2c + output (exact fp32)
            if (t < 96) {
                const int r = t / 3, q = t - (t / 3) * 3;
                float acc = bf2c[q];
                #pragma unroll 8
                for (int k = 0; k < 128; k++) acc += hf2[r * 132 + k] * Wc2[k * 3 + q];
                out[(size_t)m * 96 + t] = acc * scale + cm[q];
            }
        }
    }
}

// ============================================================================
extern "C" void kernel_launch(void* const* d_in, const int* in_sizes, int n_in,
                              void* d_out, int out_size)
{
    (void)in_sizes; (void)n_in; (void)out_size;
    const float* data = (const float*)d_in[0];
    const int*   perm = (const int*)  d_in[1];
    const float* grid = (const float*)d_in[2];
    const float* We1  = (const float*)d_in[3];
    const float* be1  = (const float*)d_in[4];
    const float* We2  = (const float*)d_in[5];
    const float* be2  = (const float*)d_in[6];
    const float* Wf1a = (const float*)d_in[7];
    const float* bf1a = (const float*)d_in[8];
    const float* Wf1b = (const float*)d_in[9];
    const float* bf1b = (const float*)d_in[10];
    const float* Wf1c = (const float*)d_in[11];
    const float* bf1c = (const float*)d_in[12];
    const float* Wf2a = (const float*)d_in[13];
    const float* bf2a = (const float*)d_in[14];
    const float* Wf2b = (const float*)d_in[15];
    const float* bf2b = (const float*)d_in[16];
    const float* Wf2c = (const float*)d_in[17];
    const float* bf2c = (const float*)d_in[18];
    float* out = (float*)d_out;

    const int fps_smem  = 3 * NN * sizeof(float);      // 98304
    const int knn_smem  = 3 * NN * sizeof(float);      // 98304
    const int enc_smem  = 14528 * sizeof(float);       // 58112
    const int base_smem = 20480 * sizeof(float);       // 81920
    const int fold_smem = 17700 * sizeof(float);       // 70800
    cudaFuncSetAttribute(fps_kernel,  cudaFuncAttributeMaxDynamicSharedMemorySize, fps_smem);
    cudaFuncSetAttribute(knn_kernel,  cudaFuncAttributeMaxDynamicSharedMemorySize, knn_smem);
    cudaFuncSetAttribute(enc_kernel,  cudaFuncAttributeMaxDynamicSharedMemorySize, enc_smem);
    cudaFuncSetAttribute(base_kernel, cudaFuncAttributeMaxDynamicSharedMemorySize, base_smem);
    cudaFuncSetAttribute(fold_kernel, cudaFuncAttributeMaxDynamicSharedMemorySize, fold_smem);

    fps_kernel <<<BB, 1024, fps_smem>>>(data);
    knn_kernel <<<(BB * NC) / 8, 256, knn_smem>>>(data, perm);
    enc_kernel <<<MTOT / 2, 256, enc_smem>>>(We1, be1, We2, be2);
    base_kernel<<<dim3(MTOT / 64, 2), 256, base_smem>>>(Wf1a, bf1a, Wf2a, bf2a);
    fold_kernel<<<MTOT, 256, fold_smem>>>(grid, Wf1a, Wf1b, bf1b, Wf1c, bf1c,
                                          Wf2a, Wf2b, bf2b, Wf2c, bf2c, out);
}

// round 8
// speedup vs baseline: 1.7501x; 1.1533x over previous
#include <cuda_runtime.h>
#include <math.h>

#define BB 32
#define NN 8192
#define NC 256
#define NP 32
#define MTOT (BB * NC)          // 8192 patches

// ---------------- scratch (device globals; no allocation allowed) ----------
__device__ float    g_centers[BB * NC * 3];
__device__ float    g_local  [MTOT * NP * 3];
__device__ float    g_cmean  [MTOT * 3];
__device__ unsigned g_scale_bits;
__device__ float    g_codeT [256 * MTOT];      // code transposed [c][m]
__device__ float    g_base1 [MTOT * 256];      // [m][c]
__device__ float    g_base2 [MTOT * 256];      // [m][c]

// ---------------- packed fp32x2 helpers (sm_100+) ---------------------------
__device__ __forceinline__ unsigned long long pack2(float w) {
    unsigned long long r;
    asm("mov.b64 %0, {%1, %1};" : "=l"(r) : "f"(w));
    return r;
}
__device__ __forceinline__ void fma2(unsigned long long& acc,
                                     unsigned long long a, unsigned long long b) {
    asm("fma.rn.f32x2 %0, %1, %2, %0;" : "+l"(acc) : "l"(a), "l"(b));
}
__device__ __forceinline__ float2 unpack2(unsigned long long v) {
    float2 r;
    asm("mov.b64 {%0, %1}, %2;" : "=f"(r.x), "=f"(r.y) : "l"(v));
    return r;
}

// ---------------- tf32 mma helpers ------------------------------------------
__device__ __forceinline__ float to_tf32(float x) {
    unsigned u;
    asm("cvt.rna.tf32.f32 %0, %1;" : "=r"(u) : "f"(x));
    return __uint_as_float(u);
}
__device__ __forceinline__ void mma_tf32(float* d, const unsigned* a, const unsigned* b) {
    asm volatile(
        "mma.sync.aligned.m16n8k8.row.col.f32.tf32.tf32.f32 "
        "{%0,%1,%2,%3}, {%4,%5,%6,%7}, {%8,%9}, {%0,%1,%2,%3};"
        : "+f"(d[0]), "+f"(d[1]), "+f"(d[2]), "+f"(d[3])
        : "r"(a[0]), "r"(a[1]), "r"(a[2]), "r"(a[3]), "r"(b[0]), "r"(b[1]));
}

// ============================================================================
// K1: FPS — one block per batch, points/mind in registers, atomic-free block
// argmax. Exact jnp.argmax tie semantics via key = (value<<32)|(NN-1-idx).
// Distance arithmetic replicates the reference exactly (no FMA contraction).
// ============================================================================
__global__ __launch_bounds__(1024, 1)
void fps_kernel(const float* __restrict__ data)
{
    extern __shared__ float sm[];
    float* sx = sm;
    float* sy = sm + NN;
    float* sz = sm + 2 * NN;
    __shared__ unsigned long long skeys[32];
    __shared__ unsigned long long sres;

    const int b = blockIdx.x;
    const int t = threadIdx.x;
    const int wid = t >> 5, lane = t & 31;
    if (b == 0 && t == 0) g_scale_bits = 0u;   // reset every launch (graph replay safe)

    const float* dp = data + (size_t)b * 3 * NN;
    for (int n = t; n < NN; n += 1024) {
        sx[n] = dp[n];
        sy[n] = dp[NN + n];
        sz[n] = dp[2 * NN + n];
    }
    __syncthreads();

    float rx[8], ry[8], rz[8], md[8];
    const int base = t * 8;
    #pragma unroll
    for (int j = 0; j < 8; j++) {
        rx[j] = sx[base + j];
        ry[j] = sy[base + j];
        rz[j] = sz[base + j];
        md[j] = 3.4e38f;
    }

    float px = sx[0], py = sy[0], pz = sz[0];
    if (t == 0) {
        float* c = g_centers + (size_t)(b * NC) * 3;
        c[0] = px; c[1] = py; c[2] = pz;
    }

    for (int i = 1; i < NC; i++) {
        float bv = -1.0f; int bi = base;
        #pragma unroll
        for (int j = 0; j < 8; j++) {
            float dx = __fadd_rn(rx[j], -px);
            float dy = __fadd_rn(ry[j], -py);
            float dz = __fadd_rn(rz[j], -pz);
            float d  = __fadd_rn(__fadd_rn(__fmul_rn(dx, dx), __fmul_rn(dy, dy)),
                                 __fmul_rn(dz, dz));
            float m  = fminf(md[j], d);
            md[j] = m;
            if (m > bv) { bv = m; bi = base + j; }
        }
        unsigned long long key =
            ((unsigned long long)__float_as_uint(bv) << 32) | (unsigned)(NN - 1 - bi);
        #pragma unroll
        for (int off = 16; off; off >>= 1) {
            unsigned long long o = __shfl_down_sync(0xFFFFFFFFu, key, off);
            if (o > key) key = o;
        }
        if (lane == 0) skeys[wid] = key;
        __syncthreads();
        if (t < 32) {
            unsigned long long k2 = skeys[t];
            #pragma unroll
            for (int off = 16; off; off >>= 1) {
                unsigned long long o = __shfl_down_sync(0xFFFFFFFFu, k2, off);
                if (o > k2) k2 = o;
            }
            if (t == 0) sres = k2;
        }
        __syncthreads();
        const unsigned long long kk = sres;
        const int sel = NN - 1 - (int)(kk & 0xFFFFFFFFull);
        px = sx[sel]; py = sy[sel]; pz = sz[sel];
        if (t == 0) {
            float* c = g_centers + (size_t)(b * NC + i) * 3;
            c[0] = px; c[1] = py; c[2] = pz;
        }
    }
}

// ============================================================================
// K2: kNN set of 32 — one warp per center, 8 centers/block, points in smem.
// ============================================================================
__global__ __launch_bounds__(256, 2)
void knn_kernel(const float* __restrict__ data, const int* __restrict__ perm)
{
    extern __shared__ float sp[];                    // [3*NN]
    const int warp = threadIdx.x >> 5;
    const int lane = threadIdx.x & 31;
    const int w  = blockIdx.x * 8 + warp;
    const int b  = w >> 8;
    const int ci = w & 255;
    const int p  = perm[ci];

    const float* dp = data + (size_t)b * 3 * NN;
    for (int i = threadIdx.x; i < 3 * NN / 4; i += 256)
        ((float4*)sp)[i] = ((const float4*)dp)[i];
    __syncthreads();
    const float* sx = sp, *sy = sp + NN, *sz = sp + 2 * NN;

    const float* cc = g_centers + (size_t)(b * NC + p) * 3;
    const float cx = cc[0], cy = cc[1], cz = cc[2];
    const float cs = (cx * cx + cy * cy) + cz * cz;

    float px = sx[lane], py = sy[lane], pz = sz[lane];
    float ps  = (px * px + py * py) + pz * pz;
    float dot = (cx * px + cy * py) + cz * pz;
    float kd  = (cs + ps) - 2.0f * dot;
    int   ki  = lane;
    float cm = kd;
    #pragma unroll
    for (int off = 16; off; off >>= 1) cm = fmaxf(cm, __shfl_xor_sync(0xFFFFFFFFu, cm, off));

    for (int bse = 32; bse < NN; bse += 32) {
        const int n = bse + lane;
        px = sx[n]; py = sy[n]; pz = sz[n];
        ps  = (px * px + py * py) + pz * pz;
        dot = (cx * px + cy * py) + cz * pz;
        const float d = (cs + ps) - 2.0f * dot;

        unsigned m = __ballot_sync(0xFFFFFFFFu, d < cm);
        while (m) {
            const int src = __ffs(m) - 1; m &= m - 1;
            const float dc = __shfl_sync(0xFFFFFFFFu, d, src);
            if (dc < cm) {
                float mv = kd; int mi = ki, ml = lane;
                #pragma unroll
                for (int off = 16; off; off >>= 1) {
                    float ov = __shfl_down_sync(0xFFFFFFFFu, mv, off);
                    int   oi = __shfl_down_sync(0xFFFFFFFFu, mi, off);
                    int   ol = __shfl_down_sync(0xFFFFFFFFu, ml, off);
                    if (ov > mv || (ov == mv && oi > mi)) { mv = ov; mi = oi; ml = ol; }
                }
                ml = __shfl_sync(0xFFFFFFFFu, ml, 0);
                if (lane == ml) { kd = dc; ki = bse + src; }
                float q = kd;
                #pragma unroll
                for (int off = 16; off; off >>= 1) q = fmaxf(q, __shfl_xor_sync(0xFFFFFFFFu, q, off));
                cm = q;
            }
        }
    }

    const float nx = sx[ki], ny = sy[ki], nz = sz[ki];
    float sxx = nx, syy = ny, szz = nz;
    #pragma unroll
    for (int off = 16; off; off >>= 1) {
        sxx += __shfl_xor_sync(0xFFFFFFFFu, sxx, off);
        syy += __shfl_xor_sync(0xFFFFFFFFu, syy, off);
        szz += __shfl_xor_sync(0xFFFFFFFFu, szz, off);
    }
    const float mx = sxx * (1.0f / 32.0f);
    const float my = syy * (1.0f / 32.0f);
    const float mz = szz * (1.0f / 32.0f);
    const float lx = nx - mx, ly = ny - my, lz = nz - mz;
    const float ns = (lx * lx + ly * ly) + lz * lz;
    float wm = ns;
    #pragma unroll
    for (int off = 16; off; off >>= 1) wm = fmaxf(wm, __shfl_xor_sync(0xFFFFFFFFu, wm, off));
    if (lane == 0) atomicMax(&g_scale_bits, __float_as_uint(wm));

    float* lp = g_local + ((size_t)w * NP + lane) * 3;
    lp[0] = lx; lp[1] = ly; lp[2] = lz;
    if (lane < 3) g_cmean[(size_t)w * 3 + lane] = (lane == 0) ? mx : ((lane == 1) ? my : mz);
}

// ============================================================================
// K3a enc: 2 patches/block (64 rows), TENSOR-CORE enc2 (m16n8k8.tf32).
// A = h1[64 r][132 k] tf32 (stride-132 -> conflict-free A frags), B = We2
// slice [16 k][260 c] tf32 (float4-staged, register-prefetched). 8 warps x
// 32 cols, 4x4 m16n8 tiles, fp32 accum. Maxpool fused in epilogue: bias+relu
// on accumulators, per-thread row max, shfl_xor over g -> g_codeT direct.
// ============================================================================
__global__ __launch_bounds__(256, 2)
void enc_kernel(const float* __restrict__ We1, const float* __restrict__ be1,
                const float* __restrict__ We2, const float* __restrict__ be2)
{
    extern __shared__ float s[];
    float* h1A   = s;            // [64 r][132 k] tf32   8448
    float* stage = s + 8448;     // [16 k][260 c] tf32   4160
    float* xs    = s + 12608;    // [64][3]               192  -> 12800 fl

    const int t  = threadIdx.x;
    const int m0 = blockIdx.x * 2;
    const float scale = sqrtf(__uint_as_float(g_scale_bits));

    if (t < 192) xs[t] = g_local[(size_t)blockIdx.x * 192 + t] / scale;
    __syncthreads();

    // enc1: h1A[r][k] = tf32(relu(xs[r]·We1[:,k] + be1[k]))  (exact fp32 math)
    #pragma unroll
    for (int i = 0; i < 32; i++) {
        const int o = i * 256 + t;
        const int r = o >> 7, k = o & 127;
        float v = xs[r * 3] * We1[k] + xs[r * 3 + 1] * We1[128 + k]
                + xs[r * 3 + 2] * We1[256 + k] + be1[k];
        h1A[r * 132 + k] = to_tf32(fmaxf(v, 0.0f));
    }

    const int lane = t & 31, g = lane >> 2, tig = lane & 3;
    const int wb = (t >> 5) * 32;              // warp's 32-column strip

    // staging assignment: 16k x 256c = 1024 float4, 4 per thread
    int skj[4], scj[4];
    #pragma unroll
    for (int i = 0; i < 4; i++) { int f = t + 256 * i; skj[i] = f >> 6; scj[i] = (f & 63) * 4; }

    float d[4][4][4];                          // [m-tile][n-tile][frag]
    #pragma unroll
    for (int mt = 0; mt < 4; mt++)
        #pragma unroll
        for (int nt = 0; nt < 4; nt++)
            #pragma unroll
            for (int j = 0; j < 4; j++) d[mt][nt][j] = 0.0f;

    float4 pf[4];
    #pragma unroll
    for (int i = 0; i < 4; i++)
        pf[i] = *(const float4*)(We2 + skj[i] * 256 + scj[i]);

    for (int sl = 0; sl < 8; sl++) {           // 8 slices of 16 k
        __syncthreads();                       // prev slice consumed / h1A ready
        #pragma unroll
        for (int i = 0; i < 4; i++) {
            float4 o = make_float4(to_tf32(pf[i].x), to_tf32(pf[i].y),
                                   to_tf32(pf[i].z), to_tf32(pf[i].w));
            *(float4*)(stage + skj[i] * 260 + scj[i]) = o;
        }
        __syncthreads();
        if (sl < 7) {
            #pragma unroll
            for (int i = 0; i < 4; i++)
                pf[i] = *(const float4*)(We2 + ((sl + 1) * 16 + skj[i]) * 256 + scj[i]);
        }
        const int kg0 = sl * 16;
        #pragma unroll
        for (int ks = 0; ks < 2; ks++) {       // 2 k-steps of 8
            const int kl = ks * 8;
            unsigned a[4][4];
            #pragma unroll
            for (int mt = 0; mt < 4; mt++) {
                const float* ap = h1A + (mt * 16 + g) * 132 + kg0 + kl + tig;
                a[mt][0] = __float_as_uint(ap[0]);
                a[mt][1] = __float_as_uint(ap[8 * 132]);
                a[mt][2] = __float_as_uint(ap[4]);
                a[mt][3] = __float_as_uint(ap[8 * 132 + 4]);
            }
            #pragma unroll
            for (int nt = 0; nt < 4; nt++) {
                const float* bp = stage + (kl + tig) * 260 + wb + nt * 8 + g;
                unsigned b[2];
                b[0] = __float_as_uint(bp[0]);
                b[1] = __float_as_uint(bp[4 * 260]);
                #pragma unroll
                for (int mt = 0; mt < 4; mt++) mma_tf32(d[mt][nt], a[mt], b);
            }
        }
    }

    // epilogue: bias + relu (exact fp32 on accumulators), maxpool per patch,
    // shfl_xor over g (lane bits 2..4), write transposed code.
    #pragma unroll
    for (int nt = 0; nt < 4; nt++) {
        const int c0 = wb + nt * 8 + 2 * tig;
        const float bb0 = be2[c0], bb1 = be2[c0 + 1];
        // patch 0 = m-tiles 0,1 ; patch 1 = m-tiles 2,3 ; frag j: {0,2}=col c0, {1,3}=col c0+1
        float p00 = fmaxf(fmaxf(fmaxf(d[0][nt][0], d[0][nt][2]),
                                fmaxf(d[1][nt][0], d[1][nt][2])) + bb0, 0.0f);
        float p01 = fmaxf(fmaxf(fmaxf(d[0][nt][1], d[0][nt][3]),
                                fmaxf(d[1][nt][1], d[1][nt][3])) + bb1, 0.0f);
        float p10 = fmaxf(fmaxf(fmaxf(d[2][nt][0], d[2][nt][2]),
                                fmaxf(d[3][nt][0], d[3][nt][2])) + bb0, 0.0f);
        float p11 = fmaxf(fmaxf(fmaxf(d[2][nt][1], d[2][nt][3]),
                                fmaxf(d[3][nt][1], d[3][nt][3])) + bb1, 0.0f);
        #pragma unroll
        for (int off = 4; off <= 16; off <<= 1) {
            p00 = fmaxf(p00, __shfl_xor_sync(0xFFFFFFFFu, p00, off));
            p01 = fmaxf(p01, __shfl_xor_sync(0xFFFFFFFFu, p01, off));
            p10 = fmaxf(p10, __shfl_xor_sync(0xFFFFFFFFu, p10, off));
            p11 = fmaxf(p11, __shfl_xor_sync(0xFFFFFFFFu, p11, off));
        }
        if (g == 0) {
            *(float2*)(g_codeT + (size_t)c0 * MTOT + m0)       = make_float2(p00, p10);
            *(float2*)(g_codeT + (size_t)(c0 + 1) * MTOT + m0) = make_float2(p01, p11);
        }
    }
}

// ============================================================================
// K3b base: base{1,2}[m][c] = code[m]·Wf{1,2}a[:256,c] + b.
// 2D grid (matrix on blockIdx.y), 16-k slices, register double-buffer.
// ============================================================================
__global__ __launch_bounds__(256, 2)
void base_kernel(const float* __restrict__ Wf1a, const float* __restrict__ bf1a,
                 const float* __restrict__ Wf2a, const float* __restrict__ bf2a)
{
    extern __shared__ float s[];
    float* ct    = s;            // [256 k][64 m]  16384
    float* stage = s + 16384;    // [16 k][256 c]   4096  -> 20480 fl

    const int t  = threadIdx.x;
    const int m0 = blockIdx.x * 64;
    const int mat = blockIdx.y;
    const float* W  = mat ? Wf2a : Wf1a;
    const float* bv = mat ? bf2a : bf1a;
    float* dst = mat ? g_base2 : g_base1;

    for (int i = t; i < 4096; i += 256) {
        const int k = i >> 4, mq = i & 15;
        *(float4*)(ct + k * 64 + mq * 4) =
            *(const float4*)(g_codeT + (size_t)k * MTOT + m0 + mq * 4);
    }

    const int rg = t & 7, cg = t >> 3;
    const int r0 = rg * 8, c0 = cg * 8;

    unsigned long long acc2[4][8];
    #pragma unroll
    for (int i = 0; i < 4; i++)
        #pragma unroll
        for (int j = 0; j < 8; j++) acc2[i][j] = 0ull;

    float4 pf[4];
    {
        const float4* src = (const float4*)W;
        #pragma unroll
        for (int i = 0; i < 4; i++) pf[i] = src[t + 256 * i];
    }
    for (int sl = 0; sl < 16; sl++) {
        __syncthreads();
        #pragma unroll
        for (int i = 0; i < 4; i++) ((float4*)stage)[t + 256 * i] = pf[i];
        __syncthreads();
        if (sl < 15) {
            const float4* src = (const float4*)(W + (sl + 1) * 16 * 256);
            #pragma unroll
            for (int i = 0; i < 4; i++) pf[i] = src[t + 256 * i];
        }
        #pragma unroll 4
        for (int k = 0; k < 16; k++) {
            const int kk = sl * 16 + k;
            const ulonglong2 a0 = *(const ulonglong2*)(ct + kk * 64 + r0);
            const ulonglong2 a1 = *(const ulonglong2*)(ct + kk * 64 + r0 + 4);
            const unsigned long long ap[4] = {a0.x, a0.y, a1.x, a1.y};
            const float4 w0 = *(const float4*)(stage + k * 256 + c0);
            const float4 w1 = *(const float4*)(stage + k * 256 + c0 + 4);
            const unsigned long long wp[8] = {pack2(w0.x), pack2(w0.y), pack2(w0.z), pack2(w0.w),
                                              pack2(w1.x), pack2(w1.y), pack2(w1.z), pack2(w1.w)};
            #pragma unroll
            for (int i = 0; i < 4; i++)
                #pragma unroll
                for (int j = 0; j < 8; j++) fma2(acc2[i][j], ap[i], wp[j]);
        }
    }
    #pragma unroll
    for (int i = 0; i < 4; i++) {
        float4 lo0, lo1, hi0, hi1;
        float* l0 = (float*)&lo0; float* l1 = (float*)&lo1;
        float* h0 = (float*)&hi0; float* h1 = (float*)&hi1;
        #pragma unroll
        for (int j = 0; j < 8; j++) {
            const float bb = bv[c0 + j];
            const float2 v = unpack2(acc2[i][j]);
            if (j < 4) { l0[j] = v.x + bb; h0[j] = v.y + bb; }
            else       { l1[j - 4] = v.x + bb; h1[j - 4] = v.y + bb; }
        }
        float* d0 = dst + (size_t)(m0 + r0 + 2 * i) * 256 + c0;
        float* d1 = dst + (size_t)(m0 + r0 + 2 * i + 1) * 256 + c0;
        *(float4*)d0 = lo0; *(float4*)(d0 + 4) = lo1;
        *(float4*)d1 = hi0; *(float4*)(d1 + 4) = hi1;
    }
}

// ============================================================================
// K3c fold: 1 patch/block, TENSOR-CORE GEMMs (mma.sync.m16n8k8.tf32).
// A = hf[32 r][260] (tf32, conflict-free frag loads), B = weight slice
// [32 k][132] (tf32, float4-staged, register-prefetched). 8 warps x 16 cols,
// 2x2 m16n8 tiles, fp32 accum. fold1c/2c remain exact fp32. Occupancy 3.
// ============================================================================
__global__ __launch_bounds__(256, 3)
void fold_kernel(const float* __restrict__ grid_,
                 const float* __restrict__ Wf1a,
                 const float* __restrict__ Wf1b, const float* __restrict__ bf1b,
                 const float* __restrict__ Wf1c, const float* __restrict__ bf1c,
                 const float* __restrict__ Wf2a,
                 const float* __restrict__ Wf2b, const float* __restrict__ bf2b,
                 const float* __restrict__ Wf2c, const float* __restrict__ bf2c,
                 float* __restrict__ out)
{
    extern __shared__ float s[];
    float* hfA   = s;              // [32 r][260] tf32  8320
    float* hf2   = s + 8320;       // [32 r][132] f32   4224
    float* stage = s + 12544;      // [32 k][132] tf32  4224
    float* Wc1   = s + 16768;      // [384]
    float* Wc2   = s + 17152;      // [384]
    float* gx    = s + 17536;      // [32]
    float* gy    = s + 17568;      // [32]
    float* fv    = s + 17600;      // [96]
    float* cm    = s + 17696;      // [4]  -> total 17700 fl = 70800 B

    const int t = threadIdx.x;
    const int m = blockIdx.x;
    const float scale = sqrtf(__uint_as_float(g_scale_bits));

    // per-thread (k = t) constants for the A-build loops — no smem needed
    const float b1t = g_base1[(size_t)m * 256 + t];
    const float b2t = g_base2[(size_t)m * 256 + t];
    const float wg0 = Wf1a[256 * 256 + t], wg1 = Wf1a[257 * 256 + t];
    const float wf0 = Wf2a[256 * 256 + t], wf1 = Wf2a[257 * 256 + t],
                wf2 = Wf2a[258 * 256 + t];
    for (int i = t; i < 384; i += 256) { Wc1[i] = Wf1c[i]; Wc2[i] = Wf2c[i]; }
    if (t < 32) { gx[t] = grid_[2 * t]; gy[t] = grid_[2 * t + 1]; }
    if (t < 3)  cm[t] = g_cmean[(size_t)m * 3 + t];
    __syncthreads();

    // A build, stage 1: hfA[r][k=t] = tf32(relu(b1 + gx*wgA0 + gy*wgA1))
    #pragma unroll 8
    for (int r = 0; r < 32; r++)
        hfA[r * 260 + t] = to_tf32(fmaxf(b1t + gx[r] * wg0 + gy[r] * wg1, 0.0f));

    const int lane = t & 31, g = lane >> 2, tig = lane & 3;
    const int wb = (t >> 5) * 16;              // warp's 16-column strip
    int skj[4], scj[4];                        // staging assignment
    #pragma unroll
    for (int i = 0; i < 4; i++) { int f = t + 256 * i; skj[i] = f >> 5; scj[i] = (f & 31) * 4; }

    #pragma unroll
    for (int stagei = 0; stagei < 2; stagei++) {
        const float* W  = stagei ? Wf2b : Wf1b;
        const float* bv = stagei ? bf2b : bf1b;

        float d[2][2][4];
        #pragma unroll
        for (int mt = 0; mt < 2; mt++)
            #pragma unroll
            for (int nt = 0; nt < 2; nt++)
                #pragma unroll
                for (int j = 0; j < 4; j++) d[mt][nt][j] = 0.0f;

        float4 pf[4];
        #pragma unroll
        for (int i = 0; i < 4; i++)
            pf[i] = *(const float4*)(W + skj[i] * 128 + scj[i]);

        for (int sl = 0; sl < 8; sl++) {             // 8 slices of 32 k
            __syncthreads();                          // prev slice consumed / hfA ready
            #pragma unroll
            for (int i = 0; i < 4; i++) {
                float4 o = make_float4(to_tf32(pf[i].x), to_tf32(pf[i].y),
                                       to_tf32(pf[i].z), to_tf32(pf[i].w));
                *(float4*)(stage + skj[i] * 132 + scj[i]) = o;
            }
            __syncthreads();
            if (sl < 7) {
                #pragma unroll
                for (int i = 0; i < 4; i++)
                    pf[i] = *(const float4*)(W + ((sl + 1) * 32 + skj[i]) * 128 + scj[i]);
            }
            const int kg0 = sl * 32;
            #pragma unroll
            for (int ks = 0; ks < 4; ks++) {         // 4 k-steps of 8
                const int kl = ks * 8;
                unsigned a[2][4];
                #pragma unroll
                for (int mt = 0; mt < 2; mt++) {
                    const float* ap = hfA + (mt * 16 + g) * 260 + kg0 + kl + tig;
                    a[mt][0] = __float_as_uint(ap[0]);
                    a[mt][1] = __float_as_uint(ap[8 * 260]);
                    a[mt][2] = __float_as_uint(ap[4]);
                    a[mt][3] = __float_as_uint(ap[8 * 260 + 4]);
                }
                #pragma unroll
                for (int nt = 0; nt < 2; nt++) {
                    const float* bp = stage + (kl + tig) * 132 + wb + nt * 8 + g;
                    unsigned b[2];
                    b[0] = __float_as_uint(bp[0]);
                    b[1] = __float_as_uint(bp[4 * 132]);
                    mma_tf32(d[0][nt], a[0], b);
                    mma_tf32(d[1][nt], a[1], b);
                }
            }
        }

        // epilogue: bias + relu -> hf2[r][c]
        #pragma unroll
        for (int nt = 0; nt < 2; nt++) {
            const int col = wb + nt * 8 + 2 * tig;
            const float bb0 = bv[col], bb1 = bv[col + 1];
            #pragma unroll
            for (int mt = 0; mt < 2; mt++) {
                const int r = mt * 16 + g;
                *(float2*)(hf2 + r * 132 + col) =
                    make_float2(fmaxf(d[mt][nt][0] + bb0, 0.0f),
                                fmaxf(d[mt][nt][1] + bb1, 0.0f));
                *(float2*)(hf2 + (r + 8) * 132 + col) =
                    make_float2(fmaxf(d[mt][nt][2] + bb0, 0.0f),
                                fmaxf(d[mt][nt][3] + bb1, 0.0f));
            }
        }
        __syncthreads();

        if (stagei == 0) {
            // fold1c: fv[r][q] = hf2[r]·Wf1c[:,q] + bf1c[q]  (exact fp32)
            if (t < 96) {
                const int r = t / 3, q = t - (t / 3) * 3;
                float acc = bf1c[q];
                #pragma unroll 8
                for (int k = 0; k < 128; k++) acc += hf2[r * 132 + k] * Wc1[k * 3 + q];
                fv[t] = acc;
            }
            __syncthreads();
            // A build, stage 2
            #pragma unroll 8
            for (int r = 0; r < 32; r++)
                hfA[r * 260 + t] = to_tf32(fmaxf(b2t + fv[3 * r] * wf0
                                                 + fv[3 * r + 1] * wf1
                                                 + fv[3 * r + 2] * wf2, 0.0f));
            // visibility ensured by first slice __syncthreads of stage 2
        } else {
            // fold2c + output (exact fp32)
            if (t < 96) {
                const int r = t / 3, q = t - (t / 3) * 3;
                float acc = bf2c[q];
                #pragma unroll 8
                for (int k = 0; k < 128; k++) acc += hf2[r * 132 + k] * Wc2[k * 3 + q];
                out[(size_t)m * 96 + t] = acc * scale + cm[q];
            }
        }
    }
}

// ============================================================================
extern "C" void kernel_launch(void* const* d_in, const int* in_sizes, int n_in,
                              void* d_out, int out_size)
{
    (void)in_sizes; (void)n_in; (void)out_size;
    const float* data = (const float*)d_in[0];
    const int*   perm = (const int*)  d_in[1];
    const float* grid = (const float*)d_in[2];
    const float* We1  = (const float*)d_in[3];
    const float* be1  = (const float*)d_in[4];
    const float* We2  = (const float*)d_in[5];
    const float* be2  = (const float*)d_in[6];
    const float* Wf1a = (const float*)d_in[7];
    const float* bf1a = (const float*)d_in[8];
    const float* Wf1b = (const float*)d_in[9];
    const float* bf1b = (const float*)d_in[10];
    const float* Wf1c = (const float*)d_in[11];
    const float* bf1c = (const float*)d_in[12];
    const float* Wf2a = (const float*)d_in[13];
    const float* bf2a = (const float*)d_in[14];
    const float* Wf2b = (const float*)d_in[15];
    const float* bf2b = (const float*)d_in[16];
    const float* Wf2c = (const float*)d_in[17];
    const float* bf2c = (const float*)d_in[18];
    float* out = (float*)d_out;

    const int fps_smem  = 3 * NN * sizeof(float);      // 98304
    const int knn_smem  = 3 * NN * sizeof(float);      // 98304
    const int enc_smem  = 12800 * sizeof(float);       // 51200
    const int base_smem = 20480 * sizeof(float);       // 81920
    const int fold_smem = 17700 * sizeof(float);       // 70800
    cudaFuncSetAttribute(fps_kernel,  cudaFuncAttributeMaxDynamicSharedMemorySize, fps_smem);
    cudaFuncSetAttribute(knn_kernel,  cudaFuncAttributeMaxDynamicSharedMemorySize, knn_smem);
    cudaFuncSetAttribute(enc_kernel,  cudaFuncAttributeMaxDynamicSharedMemorySize, enc_smem);
    cudaFuncSetAttribute(base_kernel, cudaFuncAttributeMaxDynamicSharedMemorySize, base_smem);
    cudaFuncSetAttribute(fold_kernel, cudaFuncAttributeMaxDynamicSharedMemorySize, fold_smem);

    fps_kernel <<<BB, 1024, fps_smem>>>(data);
    knn_kernel <<<(BB * NC) / 8, 256, knn_smem>>>(data, perm);
    enc_kernel <<<MTOT / 2, 256, enc_smem>>>(We1, be1, We2, be2);
    base_kernel<<<dim3(MTOT / 64, 2), 256, base_smem>>>(Wf1a, bf1a, Wf2a, bf2a);
    fold_kernel<<<MTOT, 256, fold_smem>>>(grid, Wf1a, Wf1b, bf1b, Wf1c, bf1c,
                                          Wf2a, Wf2b, bf2b, Wf2c, bf2c, out);
}

// round 10
// speedup vs baseline: 1.8133x; 1.0361x over previous
#include <cuda_runtime.h>
#include <math.h>

#define BB 32
#define NN 8192
#define NC 256
#define NP 32
#define MTOT (BB * NC)          // 8192 patches

// ---------------- scratch (device globals; no allocation allowed) ----------
__device__ float    g_centers[BB * NC * 3];
__device__ float    g_local  [MTOT * NP * 3];
__device__ float    g_cmean  [MTOT * 3];
__device__ unsigned g_scale_bits;
__device__ float    g_codeT [256 * MTOT];      // code transposed [c][m]
__device__ float    g_base1 [MTOT * 256];      // [m][c]
__device__ float    g_base2 [MTOT * 256];      // [m][c]

// ---------------- packed fp32x2 helpers (sm_100+) ---------------------------
__device__ __forceinline__ unsigned long long pack2(float w) {
    unsigned long long r;
    asm("mov.b64 %0, {%1, %1};" : "=l"(r) : "f"(w));
    return r;
}
__device__ __forceinline__ void fma2(unsigned long long& acc,
                                     unsigned long long a, unsigned long long b) {
    asm("fma.rn.f32x2 %0, %1, %2, %0;" : "+l"(acc) : "l"(a), "l"(b));
}
__device__ __forceinline__ float2 unpack2(unsigned long long v) {
    float2 r;
    asm("mov.b64 {%0, %1}, %2;" : "=f"(r.x), "=f"(r.y) : "l"(v));
    return r;
}

// ---------------- tf32 mma helpers ------------------------------------------
__device__ __forceinline__ float to_tf32(float x) {
    unsigned u;
    asm("cvt.rna.tf32.f32 %0, %1;" : "=r"(u) : "f"(x));
    return __uint_as_float(u);
}
__device__ __forceinline__ void mma_tf32(float* d, const unsigned* a, const unsigned* b) {
    asm volatile(
        "mma.sync.aligned.m16n8k8.row.col.f32.tf32.tf32.f32 "
        "{%0,%1,%2,%3}, {%4,%5,%6,%7}, {%8,%9}, {%0,%1,%2,%3};"
        : "+f"(d[0]), "+f"(d[1]), "+f"(d[2]), "+f"(d[3])
        : "r"(a[0]), "r"(a[1]), "r"(a[2]), "r"(a[3]), "r"(b[0]), "r"(b[1]));
}

// ============================================================================
// K1: FPS — one block per batch, points/mind in registers, atomic-free block
// argmax. Exact jnp.argmax tie semantics via key = (value<<32)|(NN-1-idx).
// Distance arithmetic replicates the reference exactly (no FMA contraction).
// ============================================================================
__global__ __launch_bounds__(1024, 1)
void fps_kernel(const float* __restrict__ data)
{
    extern __shared__ float sm[];
    float* sx = sm;
    float* sy = sm + NN;
    float* sz = sm + 2 * NN;
    __shared__ unsigned long long skeys[32];
    __shared__ unsigned long long sres;

    const int b = blockIdx.x;
    const int t = threadIdx.x;
    const int wid = t >> 5, lane = t & 31;
    if (b == 0 && t == 0) g_scale_bits = 0u;   // reset every launch (graph replay safe)

    const float* dp = data + (size_t)b * 3 * NN;
    for (int n = t; n < NN; n += 1024) {
        sx[n] = dp[n];
        sy[n] = dp[NN + n];
        sz[n] = dp[2 * NN + n];
    }
    __syncthreads();

    float rx[8], ry[8], rz[8], md[8];
    const int base = t * 8;
    #pragma unroll
    for (int j = 0; j < 8; j++) {
        rx[j] = sx[base + j];
        ry[j] = sy[base + j];
        rz[j] = sz[base + j];
        md[j] = 3.4e38f;
    }

    float px = sx[0], py = sy[0], pz = sz[0];
    if (t == 0) {
        float* c = g_centers + (size_t)(b * NC) * 3;
        c[0] = px; c[1] = py; c[2] = pz;
    }

    for (int i = 1; i < NC; i++) {
        float bv = -1.0f; int bi = base;
        #pragma unroll
        for (int j = 0; j < 8; j++) {
            float dx = __fadd_rn(rx[j], -px);
            float dy = __fadd_rn(ry[j], -py);
            float dz = __fadd_rn(rz[j], -pz);
            float d  = __fadd_rn(__fadd_rn(__fmul_rn(dx, dx), __fmul_rn(dy, dy)),
                                 __fmul_rn(dz, dz));
            float m  = fminf(md[j], d);
            md[j] = m;
            if (m > bv) { bv = m; bi = base + j; }
        }
        unsigned long long key =
            ((unsigned long long)__float_as_uint(bv) << 32) | (unsigned)(NN - 1 - bi);
        #pragma unroll
        for (int off = 16; off; off >>= 1) {
            unsigned long long o = __shfl_down_sync(0xFFFFFFFFu, key, off);
            if (o > key) key = o;
        }
        if (lane == 0) skeys[wid] = key;
        __syncthreads();
        if (t < 32) {
            unsigned long long k2 = skeys[t];
            #pragma unroll
            for (int off = 16; off; off >>= 1) {
                unsigned long long o = __shfl_down_sync(0xFFFFFFFFu, k2, off);
                if (o > k2) k2 = o;
            }
            if (t == 0) sres = k2;
        }
        __syncthreads();
        const unsigned long long kk = sres;
        const int sel = NN - 1 - (int)(kk & 0xFFFFFFFFull);
        px = sx[sel]; py = sy[sel]; pz = sz[sel];
        if (t == 0) {
            float* c = g_centers + (size_t)(b * NC + i) * 3;
            c[0] = px; c[1] = py; c[2] = pz;
        }
    }
}

// ============================================================================
// K2: kNN set of 32 — one warp per center, 8 centers/block, points in smem.
// ============================================================================
__global__ __launch_bounds__(256, 2)
void knn_kernel(const float* __restrict__ data, const int* __restrict__ perm)
{
    extern __shared__ float sp[];                    // [3*NN]
    const int warp = threadIdx.x >> 5;
    const int lane = threadIdx.x & 31;
    const int w  = blockIdx.x * 8 + warp;
    const int b  = w >> 8;
    const int ci = w & 255;
    const int p  = perm[ci];

    const float* dp = data + (size_t)b * 3 * NN;
    for (int i = threadIdx.x; i < 3 * NN / 4; i += 256)
        ((float4*)sp)[i] = ((const float4*)dp)[i];
    __syncthreads();
    const float* sx = sp, *sy = sp + NN, *sz = sp + 2 * NN;

    const float* cc = g_centers + (size_t)(b * NC + p) * 3;
    const float cx = cc[0], cy = cc[1], cz = cc[2];
    const float cs = (cx * cx + cy * cy) + cz * cz;

    float px = sx[lane], py = sy[lane], pz = sz[lane];
    float ps  = (px * px + py * py) + pz * pz;
    float dot = (cx * px + cy * py) + cz * pz;
    float kd  = (cs + ps) - 2.0f * dot;
    int   ki  = lane;
    float cm = kd;
    #pragma unroll
    for (int off = 16; off; off >>= 1) cm = fmaxf(cm, __shfl_xor_sync(0xFFFFFFFFu, cm, off));

    for (int bse = 32; bse < NN; bse += 32) {
        const int n = bse + lane;
        px = sx[n]; py = sy[n]; pz = sz[n];
        ps  = (px * px + py * py) + pz * pz;
        dot = (cx * px + cy * py) + cz * pz;
        const float d = (cs + ps) - 2.0f * dot;

        unsigned m = __ballot_sync(0xFFFFFFFFu, d < cm);
        while (m) {
            const int src = __ffs(m) - 1; m &= m - 1;
            const float dc = __shfl_sync(0xFFFFFFFFu, d, src);
            if (dc < cm) {
                float mv = kd; int mi = ki, ml = lane;
                #pragma unroll
                for (int off = 16; off; off >>= 1) {
                    float ov = __shfl_down_sync(0xFFFFFFFFu, mv, off);
                    int   oi = __shfl_down_sync(0xFFFFFFFFu, mi, off);
                    int   ol = __shfl_down_sync(0xFFFFFFFFu, ml, off);
                    if (ov > mv || (ov == mv && oi > mi)) { mv = ov; mi = oi; ml = ol; }
                }
                ml = __shfl_sync(0xFFFFFFFFu, ml, 0);
                if (lane == ml) { kd = dc; ki = bse + src; }
                float q = kd;
                #pragma unroll
                for (int off = 16; off; off >>= 1) q = fmaxf(q, __shfl_xor_sync(0xFFFFFFFFu, q, off));
                cm = q;
            }
        }
    }

    const float nx = sx[ki], ny = sy[ki], nz = sz[ki];
    float sxx = nx, syy = ny, szz = nz;
    #pragma unroll
    for (int off = 16; off; off >>= 1) {
        sxx += __shfl_xor_sync(0xFFFFFFFFu, sxx, off);
        syy += __shfl_xor_sync(0xFFFFFFFFu, syy, off);
        szz += __shfl_xor_sync(0xFFFFFFFFu, szz, off);
    }
    const float mx = sxx * (1.0f / 32.0f);
    const float my = syy * (1.0f / 32.0f);
    const float mz = szz * (1.0f / 32.0f);
    const float lx = nx - mx, ly = ny - my, lz = nz - mz;
    const float ns = (lx * lx + ly * ly) + lz * lz;
    float wm = ns;
    #pragma unroll
    for (int off = 16; off; off >>= 1) wm = fmaxf(wm, __shfl_xor_sync(0xFFFFFFFFu, wm, off));
    if (lane == 0) atomicMax(&g_scale_bits, __float_as_uint(wm));

    float* lp = g_local + ((size_t)w * NP + lane) * 3;
    lp[0] = lx; lp[1] = ly; lp[2] = lz;
    if (lane < 3) g_cmean[(size_t)w * 3 + lane] = (lane == 0) ? mx : ((lane == 1) ? my : mz);
}

// ============================================================================
// K3a enc: 2 patches/block (64 rows), TENSOR-CORE enc2 (m16n8k8.tf32).
// Maxpool fused in epilogue -> g_codeT direct.
// ============================================================================
__global__ __launch_bounds__(256, 2)
void enc_kernel(const float* __restrict__ We1, const float* __restrict__ be1,
                const float* __restrict__ We2, const float* __restrict__ be2)
{
    extern __shared__ float s[];
    float* h1A   = s;            // [64 r][132 k] tf32   8448
    float* stage = s + 8448;     // [16 k][260 c] tf32   4160
    float* xs    = s + 12608;    // [64][3]               192  -> 12800 fl

    const int t  = threadIdx.x;
    const int m0 = blockIdx.x * 2;
    const float scale = sqrtf(__uint_as_float(g_scale_bits));

    if (t < 192) xs[t] = g_local[(size_t)blockIdx.x * 192 + t] / scale;
    __syncthreads();

    // enc1: h1A[r][k] = tf32(relu(xs[r]·We1[:,k] + be1[k]))  (exact fp32 math)
    #pragma unroll
    for (int i = 0; i < 32; i++) {
        const int o = i * 256 + t;
        const int r = o >> 7, k = o & 127;
        float v = xs[r * 3] * We1[k] + xs[r * 3 + 1] * We1[128 + k]
                + xs[r * 3 + 2] * We1[256 + k] + be1[k];
        h1A[r * 132 + k] = to_tf32(fmaxf(v, 0.0f));
    }

    const int lane = t & 31, g = lane >> 2, tig = lane & 3;
    const int wb = (t >> 5) * 32;              // warp's 32-column strip

    int skj[4], scj[4];
    #pragma unroll
    for (int i = 0; i < 4; i++) { int f = t + 256 * i; skj[i] = f >> 6; scj[i] = (f & 63) * 4; }

    float d[4][4][4];                          // [m-tile][n-tile][frag]
    #pragma unroll
    for (int mt = 0; mt < 4; mt++)
        #pragma unroll
        for (int nt = 0; nt < 4; nt++)
            #pragma unroll
            for (int j = 0; j < 4; j++) d[mt][nt][j] = 0.0f;

    float4 pf[4];
    #pragma unroll
    for (int i = 0; i < 4; i++)
        pf[i] = *(const float4*)(We2 + skj[i] * 256 + scj[i]);

    for (int sl = 0; sl < 8; sl++) {           // 8 slices of 16 k
        __syncthreads();
        #pragma unroll
        for (int i = 0; i < 4; i++) {
            float4 o = make_float4(to_tf32(pf[i].x), to_tf32(pf[i].y),
                                   to_tf32(pf[i].z), to_tf32(pf[i].w));
            *(float4*)(stage + skj[i] * 260 + scj[i]) = o;
        }
        __syncthreads();
        if (sl < 7) {
            #pragma unroll
            for (int i = 0; i < 4; i++)
                pf[i] = *(const float4*)(We2 + ((sl + 1) * 16 + skj[i]) * 256 + scj[i]);
        }
        const int kg0 = sl * 16;
        #pragma unroll
        for (int ks = 0; ks < 2; ks++) {       // 2 k-steps of 8
            const int kl = ks * 8;
            unsigned a[4][4];
            #pragma unroll
            for (int mt = 0; mt < 4; mt++) {
                const float* ap = h1A + (mt * 16 + g) * 132 + kg0 + kl + tig;
                a[mt][0] = __float_as_uint(ap[0]);
                a[mt][1] = __float_as_uint(ap[8 * 132]);
                a[mt][2] = __float_as_uint(ap[4]);
                a[mt][3] = __float_as_uint(ap[8 * 132 + 4]);
            }
            #pragma unroll
            for (int nt = 0; nt < 4; nt++) {
                const float* bp = stage + (kl + tig) * 260 + wb + nt * 8 + g;
                unsigned b[2];
                b[0] = __float_as_uint(bp[0]);
                b[1] = __float_as_uint(bp[4 * 260]);
                #pragma unroll
                for (int mt = 0; mt < 4; mt++) mma_tf32(d[mt][nt], a[mt], b);
            }
        }
    }

    // epilogue: bias + relu, maxpool per patch, shfl over g, transposed write
    #pragma unroll
    for (int nt = 0; nt < 4; nt++) {
        const int c0 = wb + nt * 8 + 2 * tig;
        const float bb0 = be2[c0], bb1 = be2[c0 + 1];
        float p00 = fmaxf(fmaxf(fmaxf(d[0][nt][0], d[0][nt][2]),
                                fmaxf(d[1][nt][0], d[1][nt][2])) + bb0, 0.0f);
        float p01 = fmaxf(fmaxf(fmaxf(d[0][nt][1], d[0][nt][3]),
                                fmaxf(d[1][nt][1], d[1][nt][3])) + bb1, 0.0f);
        float p10 = fmaxf(fmaxf(fmaxf(d[2][nt][0], d[2][nt][2]),
                                fmaxf(d[3][nt][0], d[3][nt][2])) + bb0, 0.0f);
        float p11 = fmaxf(fmaxf(fmaxf(d[2][nt][1], d[2][nt][3]),
                                fmaxf(d[3][nt][1], d[3][nt][3])) + bb1, 0.0f);
        #pragma unroll
        for (int off = 4; off <= 16; off <<= 1) {
            p00 = fmaxf(p00, __shfl_xor_sync(0xFFFFFFFFu, p00, off));
            p01 = fmaxf(p01, __shfl_xor_sync(0xFFFFFFFFu, p01, off));
            p10 = fmaxf(p10, __shfl_xor_sync(0xFFFFFFFFu, p10, off));
            p11 = fmaxf(p11, __shfl_xor_sync(0xFFFFFFFFu, p11, off));
        }
        if (g == 0) {
            *(float2*)(g_codeT + (size_t)c0 * MTOT + m0)       = make_float2(p00, p10);
            *(float2*)(g_codeT + (size_t)(c0 + 1) * MTOT + m0) = make_float2(p01, p11);
        }
    }
}

// ============================================================================
// K3b base: base{1,2}[m][c] = code[m]·Wf{1,2}a[:256,c] + b.
// 2D grid (matrix on blockIdx.y), 16-k slices, register double-buffer.
// ============================================================================
__global__ __launch_bounds__(256, 2)
void base_kernel(const float* __restrict__ Wf1a, const float* __restrict__ bf1a,
                 const float* __restrict__ Wf2a, const float* __restrict__ bf2a)
{
    extern __shared__ float s[];
    float* ct    = s;            // [256 k][64 m]  16384
    float* stage = s + 16384;    // [16 k][256 c]   4096  -> 20480 fl

    const int t  = threadIdx.x;
    const int m0 = blockIdx.x * 64;
    const int mat = blockIdx.y;
    const float* W  = mat ? Wf2a : Wf1a;
    const float* bv = mat ? bf2a : bf1a;
    float* dst = mat ? g_base2 : g_base1;

    for (int i = t; i < 4096; i += 256) {
        const int k = i >> 4, mq = i & 15;
        *(float4*)(ct + k * 64 + mq * 4) =
            *(const float4*)(g_codeT + (size_t)k * MTOT + m0 + mq * 4);
    }

    const int rg = t & 7, cg = t >> 3;
    const int r0 = rg * 8, c0 = cg * 8;

    unsigned long long acc2[4][8];
    #pragma unroll
    for (int i = 0; i < 4; i++)
        #pragma unroll
        for (int j = 0; j < 8; j++) acc2[i][j] = 0ull;

    float4 pf[4];
    {
        const float4* src = (const float4*)W;
        #pragma unroll
        for (int i = 0; i < 4; i++) pf[i] = src[t + 256 * i];
    }
    for (int sl = 0; sl < 16; sl++) {
        __syncthreads();
        #pragma unroll
        for (int i = 0; i < 4; i++) ((float4*)stage)[t + 256 * i] = pf[i];
        __syncthreads();
        if (sl < 15) {
            const float4* src = (const float4*)(W + (sl + 1) * 16 * 256);
            #pragma unroll
            for (int i = 0; i < 4; i++) pf[i] = src[t + 256 * i];
        }
        #pragma unroll 4
        for (int k = 0; k < 16; k++) {
            const int kk = sl * 16 + k;
            const ulonglong2 a0 = *(const ulonglong2*)(ct + kk * 64 + r0);
            const ulonglong2 a1 = *(const ulonglong2*)(ct + kk * 64 + r0 + 4);
            const unsigned long long ap[4] = {a0.x, a0.y, a1.x, a1.y};
            const float4 w0 = *(const float4*)(stage + k * 256 + c0);
            const float4 w1 = *(const float4*)(stage + k * 256 + c0 + 4);
            const unsigned long long wp[8] = {pack2(w0.x), pack2(w0.y), pack2(w0.z), pack2(w0.w),
                                              pack2(w1.x), pack2(w1.y), pack2(w1.z), pack2(w1.w)};
            #pragma unroll
            for (int i = 0; i < 4; i++)
                #pragma unroll
                for (int j = 0; j < 8; j++) fma2(acc2[i][j], ap[i], wp[j]);
        }
    }
    #pragma unroll
    for (int i = 0; i < 4; i++) {
        float4 lo0, lo1, hi0, hi1;
        float* l0 = (float*)&lo0; float* l1 = (float*)&lo1;
        float* h0 = (float*)&hi0; float* h1 = (float*)&hi1;
        #pragma unroll
        for (int j = 0; j < 8; j++) {
            const float bb = bv[c0 + j];
            const float2 v = unpack2(acc2[i][j]);
            if (j < 4) { l0[j] = v.x + bb; h0[j] = v.y + bb; }
            else       { l1[j - 4] = v.x + bb; h1[j - 4] = v.y + bb; }
        }
        float* d0 = dst + (size_t)(m0 + r0 + 2 * i) * 256 + c0;
        float* d1 = dst + (size_t)(m0 + r0 + 2 * i + 1) * 256 + c0;
        *(float4*)d0 = lo0; *(float4*)(d0 + 4) = lo1;
        *(float4*)d1 = hi0; *(float4*)(d1 + 4) = hi1;
    }
}

// ============================================================================
// K3c fold: 2 patches/block, 512 threads, occupancy 2 (32 warps/SM).
// TENSOR-CORE GEMMs (m16n8k8.tf32). A = hf[64 r][132] covering one 128-k half
// at a time (rebuilt per half). FIX vs round 9: MMA A-fragment loads now add
// the within-half slice offset kh = (gs&3)*32 (round 9 always read slice 0 ->
// rel_err 2e-2). B = weight slice [32 k][132] tf32, float4-staged, register-
// prefetched. 16 warps x 8 cols, 4 m-tiles each. fold1c/2c exact fp32.
// ============================================================================
__global__ __launch_bounds__(512, 2)
void fold_kernel(const float* __restrict__ grid_,
                 const float* __restrict__ Wf1a,
                 const float* __restrict__ Wf1b, const float* __restrict__ bf1b,
                 const float* __restrict__ Wf1c, const float* __restrict__ bf1c,
                 const float* __restrict__ Wf2a,
                 const float* __restrict__ Wf2b, const float* __restrict__ bf2b,
                 const float* __restrict__ Wf2c, const float* __restrict__ bf2c,
                 float* __restrict__ out)
{
    extern __shared__ float s[];
    float* hfA   = s;              // [64 r][132] tf32 (one 128-k half)  8448
    float* hf2   = s + 8448;       // [64 r][132] f32                    8448
    float* stage = s + 16896;      // [32 k][132] tf32                   4224
    float* Wc1   = s + 21120;      // [384]
    float* Wc2   = s + 21504;      // [384]
    float* gx    = s + 21888;      // [32]
    float* gy    = s + 21920;      // [32]
    float* fv    = s + 21952;      // [64][3] = 192
    float* cm    = s + 22144;      // [8]   -> total 22152 fl = 88608 B

    const int t = threadIdx.x;
    const int m0 = blockIdx.x * 2;
    const float scale = sqrtf(__uint_as_float(g_scale_bits));

    const int kk   = t & 127;      // k within half (A-build)
    const int rgrp = t >> 7;       // 0..3 -> rows [rgrp*16, +16)
    const int pA   = rgrp >> 1;    // patch of those rows

    if (t < 384) { Wc1[t] = Wf1c[t]; Wc2[t] = Wf2c[t]; }
    if (t < 32) { gx[t] = grid_[2 * t]; gy[t] = grid_[2 * t + 1]; }
    if (t < 6)  cm[t] = g_cmean[(size_t)m0 * 3 + t];
    __syncthreads();

    const int lane = t & 31, g = lane >> 2, tig = lane & 3;
    const int wb = (t >> 5) * 8;               // warp's 8-column strip
    int skj[2], scj[2];                        // staging: 1024 float4 / 512 thr
    #pragma unroll
    for (int i = 0; i < 2; i++) { int f = t + 512 * i; skj[i] = f >> 5; scj[i] = (f & 31) * 4; }

    #pragma unroll
    for (int stagei = 0; stagei < 2; stagei++) {
        const float* W  = stagei ? Wf2b : Wf1b;
        const float* bv = stagei ? bf2b : bf1b;

        float d[4][4];
        #pragma unroll
        for (int mt = 0; mt < 4; mt++)
            #pragma unroll
            for (int j = 0; j < 4; j++) d[mt][j] = 0.0f;

        float4 pf[2];
        #pragma unroll
        for (int i = 0; i < 2; i++)
            pf[i] = *(const float4*)(W + skj[i] * 128 + scj[i]);

        for (int gs = 0; gs < 8; gs++) {       // 8 slices of 32 k (2 halves x 4)
            if ((gs & 3) == 0) {
                // rebuild A for half h = gs>>2
                const int h = gs >> 2;
                if (gs) __syncthreads();       // prior half's MMA reads done
                const int kg = h * 128 + kk;
                if (stagei == 0) {
                    const float b  = g_base1[(size_t)(m0 + pA) * 256 + kg];
                    const float w0 = Wf1a[256 * 256 + kg];
                    const float w1 = Wf1a[257 * 256 + kg];
                    #pragma unroll
                    for (int i = 0; i < 16; i++) {
                        const int r  = rgrp * 16 + i;
                        const int rr = r & 31;
                        hfA[r * 132 + kk] =
                            to_tf32(fmaxf(b + gx[rr] * w0 + gy[rr] * w1, 0.0f));
                    }
                } else {
                    const float b  = g_base2[(size_t)(m0 + pA) * 256 + kg];
                    const float w0 = Wf2a[256 * 256 + kg];
                    const float w1 = Wf2a[257 * 256 + kg];
                    const float w2 = Wf2a[258 * 256 + kg];
                    #pragma unroll
                    for (int i = 0; i < 16; i++) {
                        const int r = rgrp * 16 + i;
                        hfA[r * 132 + kk] =
                            to_tf32(fmaxf(b + fv[r * 3] * w0 + fv[r * 3 + 1] * w1
                                          + fv[r * 3 + 2] * w2, 0.0f));
                    }
                }
            }
            __syncthreads();                   // A ready / prev stage consumed
            #pragma unroll
            for (int i = 0; i < 2; i++) {
                float4 o = make_float4(to_tf32(pf[i].x), to_tf32(pf[i].y),
                                       to_tf32(pf[i].z), to_tf32(pf[i].w));
                *(float4*)(stage + skj[i] * 132 + scj[i]) = o;
            }
            __syncthreads();
            if (gs < 7) {
                #pragma unroll
                for (int i = 0; i < 2; i++)
                    pf[i] = *(const float4*)(W + ((gs + 1) * 32 + skj[i]) * 128 + scj[i]);
            }
            const int kh = (gs & 3) * 32;      // within-half k offset (THE FIX)
            #pragma unroll
            for (int ks = 0; ks < 4; ks++) {   // 4 k-steps of 8 within slice
                const int kl = ks * 8;
                const float* bp = stage + (kl + tig) * 132 + wb + g;
                unsigned b2r[2];
                b2r[0] = __float_as_uint(bp[0]);
                b2r[1] = __float_as_uint(bp[4 * 132]);
                #pragma unroll
                for (int mg = 0; mg < 2; mg++) {
                    unsigned a[2][4];
                    #pragma unroll
                    for (int q2 = 0; q2 < 2; q2++) {
                        const int mt = mg * 2 + q2;
                        const float* ap = hfA + (mt * 16 + g) * 132 + kh + kl + tig;
                        a[q2][0] = __float_as_uint(ap[0]);
                        a[q2][1] = __float_as_uint(ap[8 * 132]);
                        a[q2][2] = __float_as_uint(ap[4]);
                        a[q2][3] = __float_as_uint(ap[8 * 132 + 4]);
                    }
                    mma_tf32(d[mg * 2],     a[0], b2r);
                    mma_tf32(d[mg * 2 + 1], a[1], b2r);
                }
            }
        }

        // epilogue: bias + relu -> hf2[64 r][132]
        {
            const int col = wb + 2 * tig;
            const float bb0 = bv[col], bb1 = bv[col + 1];
            #pragma unroll
            for (int mt = 0; mt < 4; mt++) {
                const int r = mt * 16 + g;
                *(float2*)(hf2 + r * 132 + col) =
                    make_float2(fmaxf(d[mt][0] + bb0, 0.0f),
                                fmaxf(d[mt][1] + bb1, 0.0f));
                *(float2*)(hf2 + (r + 8) * 132 + col) =
                    make_float2(fmaxf(d[mt][2] + bb0, 0.0f),
                                fmaxf(d[mt][3] + bb1, 0.0f));
            }
        }
        __syncthreads();

        if (stagei == 0) {
            // fold1c: fv[r][q] = hf2[r]·Wf1c[:,q] + bf1c[q]  (exact fp32)
            if (t < 192) {
                const int r = t / 3, q = t - (t / 3) * 3;
                float acc = bf1c[q];
                #pragma unroll 8
                for (int k = 0; k < 128; k++) acc += hf2[r * 132 + k] * Wc1[k * 3 + q];
                fv[t] = acc;
            }
            __syncthreads();
        } else {
            // fold2c + output (exact fp32)
            if (t < 192) {
                const int r = t / 3, q = t - (t / 3) * 3;
                const int p = r >> 5, rr = r & 31;
                float acc = bf2c[q];
                #pragma unroll 8
                for (int k = 0; k < 128; k++) acc += hf2[r * 132 + k] * Wc2[k * 3 + q];
                out[(size_t)(m0 + p) * 96 + rr * 3 + q] = acc * scale + cm[p * 3 + q];
            }
        }
    }
}

// ============================================================================
extern "C" void kernel_launch(void* const* d_in, const int* in_sizes, int n_in,
                              void* d_out, int out_size)
{
    (void)in_sizes; (void)n_in; (void)out_size;
    const float* data = (const float*)d_in[0];
    const int*   perm = (const int*)  d_in[1];
    const float* grid = (const float*)d_in[2];
    const float* We1  = (const float*)d_in[3];
    const float* be1  = (const float*)d_in[4];
    const float* We2  = (const float*)d_in[5];
    const float* be2  = (const float*)d_in[6];
    const float* Wf1a = (const float*)d_in[7];
    const float* bf1a = (const float*)d_in[8];
    const float* Wf1b = (const float*)d_in[9];
    const float* bf1b = (const float*)d_in[10];
    const float* Wf1c = (const float*)d_in[11];
    const float* bf1c = (const float*)d_in[12];
    const float* Wf2a = (const float*)d_in[13];
    const float* bf2a = (const float*)d_in[14];
    const float* Wf2b = (const float*)d_in[15];
    const float* bf2b = (const float*)d_in[16];
    const float* Wf2c = (const float*)d_in[17];
    const float* bf2c = (const float*)d_in[18];
    float* out = (float*)d_out;

    const int fps_smem  = 3 * NN * sizeof(float);      // 98304
    const int knn_smem  = 3 * NN * sizeof(float);      // 98304
    const int enc_smem  = 12800 * sizeof(float);       // 51200
    const int base_smem = 20480 * sizeof(float);       // 81920
    const int fold_smem = 22152 * sizeof(float);       // 88608
    cudaFuncSetAttribute(fps_kernel,  cudaFuncAttributeMaxDynamicSharedMemorySize, fps_smem);
    cudaFuncSetAttribute(knn_kernel,  cudaFuncAttributeMaxDynamicSharedMemorySize, knn_smem);
    cudaFuncSetAttribute(enc_kernel,  cudaFuncAttributeMaxDynamicSharedMemorySize, enc_smem);
    cudaFuncSetAttribute(base_kernel, cudaFuncAttributeMaxDynamicSharedMemorySize, base_smem);
    cudaFuncSetAttribute(fold_kernel, cudaFuncAttributeMaxDynamicSharedMemorySize, fold_smem);

    fps_kernel <<<BB, 1024, fps_smem>>>(data);
    knn_kernel <<<(BB * NC) / 8, 256, knn_smem>>>(data, perm);
    enc_kernel <<<MTOT / 2, 256, enc_smem>>>(We1, be1, We2, be2);
    base_kernel<<<dim3(MTOT / 64, 2), 256, base_smem>>>(Wf1a, bf1a, Wf2a, bf2a);
    fold_kernel<<<MTOT / 2, 512, fold_smem>>>(grid, Wf1a, Wf1b, bf1b, Wf1c, bf1c,
                                              Wf2a, Wf2b, bf2b, Wf2c, bf2c, out);
}

// round 12
// speedup vs baseline: 2.6907x; 1.4839x over previous
#include <cuda_runtime.h>
#include <cuda_bf16.h>
#include <math.h>

#define BB 32
#define NN 8192
#define NC 256
#define NP 32
#define MTOT (BB * NC)          // 8192 patches

// ---------------- scratch (device globals; no allocation allowed) ----------
__device__ float    g_centers[BB * NC * 3];
__device__ float    g_local  [MTOT * NP * 3];
__device__ float    g_cmean  [MTOT * 3];
__device__ unsigned g_scale_bits;
__device__ float    g_codeT [256 * MTOT];      // code transposed [c][m]
__device__ float    g_base1 [MTOT * 256];      // [m][c]
__device__ float    g_base2 [MTOT * 256];      // [m][c]

// ---------------- packed fp32x2 helpers (sm_100+) ---------------------------
__device__ __forceinline__ unsigned long long pack2(float w) {
    unsigned long long r;
    asm("mov.b64 %0, {%1, %1};" : "=l"(r) : "f"(w));
    return r;
}
__device__ __forceinline__ void fma2(unsigned long long& acc,
                                     unsigned long long a, unsigned long long b) {
    asm("fma.rn.f32x2 %0, %1, %2, %0;" : "+l"(acc) : "l"(a), "l"(b));
}
__device__ __forceinline__ float2 unpack2(unsigned long long v) {
    float2 r;
    asm("mov.b64 {%0, %1}, %2;" : "=f"(r.x), "=f"(r.y) : "l"(v));
    return r;
}

// ---------------- bf16 mma helpers ------------------------------------------
// pack_bf16x2(lo, hi): lower 16 bits = bf16(lo) (smaller k), upper = bf16(hi)
__device__ __forceinline__ unsigned pack_bf16x2(float lo, float hi) {
    unsigned r;
    asm("cvt.rn.bf16x2.f32 %0, %1, %2;" : "=r"(r) : "f"(hi), "f"(lo));
    return r;
}
// mma.m16n8k16 bf16: A row-major 16x16 (4 .b32 of bf16x2), B col-major 16x8
// (2 .b32), D/C fp32 (4 regs).
__device__ __forceinline__ void mma_bf16(float* d, const unsigned* a,
                                         unsigned b0, unsigned b1) {
    asm volatile(
        "mma.sync.aligned.m16n8k16.row.col.f32.bf16.bf16.f32 "
        "{%0,%1,%2,%3}, {%4,%5,%6,%7}, {%8,%9}, {%0,%1,%2,%3};"
        : "+f"(d[0]), "+f"(d[1]), "+f"(d[2]), "+f"(d[3])
        : "r"(a[0]), "r"(a[1]), "r"(a[2]), "r"(a[3]), "r"(b0), "r"(b1));
}

// ============================================================================
// K1: FPS — one block per batch, points/mind in registers, atomic-free block
// argmax. Exact jnp.argmax tie semantics via key = (value<<32)|(NN-1-idx).
// Distance arithmetic replicates the reference exactly (no FMA contraction).
// ============================================================================
__global__ __launch_bounds__(1024, 1)
void fps_kernel(const float* __restrict__ data)
{
    extern __shared__ float sm[];
    float* sx = sm;
    float* sy = sm + NN;
    float* sz = sm + 2 * NN;
    __shared__ unsigned long long skeys[32];
    __shared__ unsigned long long sres;

    const int b = blockIdx.x;
    const int t = threadIdx.x;
    const int wid = t >> 5, lane = t & 31;
    if (b == 0 && t == 0) g_scale_bits = 0u;   // reset every launch (graph replay safe)

    const float* dp = data + (size_t)b * 3 * NN;
    for (int n = t; n < NN; n += 1024) {
        sx[n] = dp[n];
        sy[n] = dp[NN + n];
        sz[n] = dp[2 * NN + n];
    }
    __syncthreads();

    float rx[8], ry[8], rz[8], md[8];
    const int base = t * 8;
    #pragma unroll
    for (int j = 0; j < 8; j++) {
        rx[j] = sx[base + j];
        ry[j] = sy[base + j];
        rz[j] = sz[base + j];
        md[j] = 3.4e38f;
    }

    float px = sx[0], py = sy[0], pz = sz[0];
    if (t == 0) {
        float* c = g_centers + (size_t)(b * NC) * 3;
        c[0] = px; c[1] = py; c[2] = pz;
    }

    for (int i = 1; i < NC; i++) {
        float bv = -1.0f; int bi = base;
        #pragma unroll
        for (int j = 0; j < 8; j++) {
            float dx = __fadd_rn(rx[j], -px);
            float dy = __fadd_rn(ry[j], -py);
            float dz = __fadd_rn(rz[j], -pz);
            float d  = __fadd_rn(__fadd_rn(__fmul_rn(dx, dx), __fmul_rn(dy, dy)),
                                 __fmul_rn(dz, dz));
            float m  = fminf(md[j], d);
            md[j] = m;
            if (m > bv) { bv = m; bi = base + j; }
        }
        unsigned long long key =
            ((unsigned long long)__float_as_uint(bv) << 32) | (unsigned)(NN - 1 - bi);
        #pragma unroll
        for (int off = 16; off; off >>= 1) {
            unsigned long long o = __shfl_down_sync(0xFFFFFFFFu, key, off);
            if (o > key) key = o;
        }
        if (lane == 0) skeys[wid] = key;
        __syncthreads();
        if (t < 32) {
            unsigned long long k2 = skeys[t];
            #pragma unroll
            for (int off = 16; off; off >>= 1) {
                unsigned long long o = __shfl_down_sync(0xFFFFFFFFu, k2, off);
                if (o > k2) k2 = o;
            }
            if (t == 0) sres = k2;
        }
        __syncthreads();
        const unsigned long long kk = sres;
        const int sel = NN - 1 - (int)(kk & 0xFFFFFFFFull);
        px = sx[sel]; py = sy[sel]; pz = sz[sel];
        if (t == 0) {
            float* c = g_centers + (size_t)(b * NC + i) * 3;
            c[0] = px; c[1] = py; c[2] = pz;
        }
    }
}

// ============================================================================
// K2: kNN set of 32 — one warp per center, 8 centers/block, points in smem.
// Sorted-insertion top-32 (lane 31 = current max); tie semantics match
// lax.top_k exactly (ascending-index candidates, stable insert after equals).
// ============================================================================
__global__ __launch_bounds__(256, 2)
void knn_kernel(const float* __restrict__ data, const int* __restrict__ perm)
{
    extern __shared__ float sp[];                    // [3*NN]
    const int warp = threadIdx.x >> 5;
    const int lane = threadIdx.x & 31;
    const int w  = blockIdx.x * 8 + warp;
    const int b  = w >> 8;
    const int ci = w & 255;
    const int p  = perm[ci];

    const float* dp = data + (size_t)b * 3 * NN;
    for (int i = threadIdx.x; i < 3 * NN / 4; i += 256)
        ((float4*)sp)[i] = ((const float4*)dp)[i];
    __syncthreads();
    const float* sx = sp, *sy = sp + NN, *sz = sp + 2 * NN;

    const float* cc = g_centers + (size_t)(b * NC + p) * 3;
    const float cx = cc[0], cy = cc[1], cz = cc[2];
    const float cs = (cx * cx + cy * cy) + cz * cz;

    float kd = 3.4e38f;          // sorted ascending across lanes
    int   ki = -1;
    float cm = 3.4e38f;          // = kd at lane 31

    for (int bse = 0; bse < NN; bse += 32) {
        const int n = bse + lane;
        const float px = sx[n], py = sy[n], pz = sz[n];
        const float ps  = (px * px + py * py) + pz * pz;
        const float dot = (cx * px + cy * py) + cz * pz;
        const float d = (cs + ps) - 2.0f * dot;

        unsigned m = __ballot_sync(0xFFFFFFFFu, d < cm);
        while (m) {
            const int src = __ffs(m) - 1; m &= m - 1;
            const float dc = __shfl_sync(0xFFFFFFFFu, d, src);
            if (dc < cm) {                       // strict: equal-to-max never enters
                const int pos = __popc(__ballot_sync(0xFFFFFFFFu, kd <= dc));
                const float skd = __shfl_up_sync(0xFFFFFFFFu, kd, 1);
                const int   ski = __shfl_up_sync(0xFFFFFFFFu, ki, 1);
                if (lane > pos)       { kd = skd; ki = ski; }
                else if (lane == pos) { kd = dc;  ki = bse + src; }
                cm = __shfl_sync(0xFFFFFFFFu, kd, 31);
            }
        }
    }

    const float nx = sx[ki], ny = sy[ki], nz = sz[ki];
    float sxx = nx, syy = ny, szz = nz;
    #pragma unroll
    for (int off = 16; off; off >>= 1) {
        sxx += __shfl_xor_sync(0xFFFFFFFFu, sxx, off);
        syy += __shfl_xor_sync(0xFFFFFFFFu, syy, off);
        szz += __shfl_xor_sync(0xFFFFFFFFu, szz, off);
    }
    const float mx = sxx * (1.0f / 32.0f);
    const float my = syy * (1.0f / 32.0f);
    const float mz = szz * (1.0f / 32.0f);
    const float lx = nx - mx, ly = ny - my, lz = nz - mz;
    const float ns = (lx * lx + ly * ly) + lz * lz;
    float wm = ns;
    #pragma unroll
    for (int off = 16; off; off >>= 1) wm = fmaxf(wm, __shfl_xor_sync(0xFFFFFFFFu, wm, off));
    if (lane == 0) atomicMax(&g_scale_bits, __float_as_uint(wm));

    float* lp = g_local + ((size_t)w * NP + lane) * 3;
    lp[0] = lx; lp[1] = ly; lp[2] = lz;
    if (lane < 3) g_cmean[(size_t)w * 3 + lane] = (lane == 0) ? mx : ((lane == 1) ? my : mz);
}

// ============================================================================
// K3a enc: 2 patches/block (64 rows), BF16 TENSOR-CORE enc2 (m16n8k16.bf16).
// SMEM FIX vs round 11: h1A is [64][136] bf16 = 4352 FLOATS (not 2176) — the
// round-11 layout overlapped stageu with h1A's upper half.
// ============================================================================
__global__ __launch_bounds__(256, 2)
void enc_kernel(const float* __restrict__ We1, const float* __restrict__ be1,
                const float* __restrict__ We2, const float* __restrict__ be2)
{
    extern __shared__ float s[];
    __nv_bfloat16* h1A = (__nv_bfloat16*)s;        // [64][136] bf16 = 4352 fl
    unsigned* stageu   = (unsigned*)(s + 4352);    // [8 k2][264]    = 2112 fl
    float* xs          = s + 4352 + 2112;          // [64][3]        =  192 fl
                                                   // total 6656 fl = 26624 B
    const int t  = threadIdx.x;
    const int m0 = blockIdx.x * 2;
    const float scale = sqrtf(__uint_as_float(g_scale_bits));

    if (t < 192) xs[t] = g_local[(size_t)blockIdx.x * 192 + t] / scale;
    __syncthreads();

    // enc1 (exact fp32): thread handles k-pair (2kp, 2kp+1), rows rh,rh+4,...
    {
        const int kp = t & 63;          // k-pair index, k = 2kp, 2kp+1
        const int rh = t >> 6;          // 0..3
        const float2 w0 = *(const float2*)(We1 + 0 * 128 + 2 * kp);
        const float2 w1 = *(const float2*)(We1 + 1 * 128 + 2 * kp);
        const float2 w2 = *(const float2*)(We1 + 2 * 128 + 2 * kp);
        const float2 bb = *(const float2*)(be1 + 2 * kp);
        unsigned* h1w = (unsigned*)h1A;
        #pragma unroll
        for (int i = 0; i < 16; i++) {
            const int r = i * 4 + rh;
            const float x0 = xs[r * 3], x1 = xs[r * 3 + 1], x2 = xs[r * 3 + 2];
            const float v0 = fmaxf(x0 * w0.x + x1 * w1.x + x2 * w2.x + bb.x, 0.0f);
            const float v1 = fmaxf(x0 * w0.y + x1 * w1.y + x2 * w2.y + bb.y, 0.0f);
            h1w[r * 68 + kp] = pack_bf16x2(v0, v1);
        }
    }

    const int lane = t & 31, g = lane >> 2, tig = lane & 3;
    const int wb = (t >> 5) * 32;              // warp's 32-column strip

    // staging assignment: thread -> k2 = t>>5 (row pair), cols (t&31)*4 in
    // both c-halves {0,128}. 8 words per thread.
    const int sk2 = t >> 5;
    const int sc0 = (t & 31) * 4;

    float d[4][4][4];                          // [m-tile][n-tile][frag]
    #pragma unroll
    for (int mt = 0; mt < 4; mt++)
        #pragma unroll
        for (int nt = 0; nt < 4; nt++)
            #pragma unroll
            for (int j = 0; j < 4; j++) d[mt][nt][j] = 0.0f;

    // register prefetch (rows 2k2, 2k2+1; both c-halves)
    float4 pf[4];
    pf[0] = *(const float4*)(We2 + (2 * sk2) * 256 + sc0);
    pf[1] = *(const float4*)(We2 + (2 * sk2 + 1) * 256 + sc0);
    pf[2] = *(const float4*)(We2 + (2 * sk2) * 256 + 128 + sc0);
    pf[3] = *(const float4*)(We2 + (2 * sk2 + 1) * 256 + 128 + sc0);

    for (int sl = 0; sl < 8; sl++) {           // 8 slices of 16 k (1 kstep each)
        __syncthreads();
        {
            const float* p0 = (const float*)&pf[0];
            const float* p1 = (const float*)&pf[1];
            const float* p2 = (const float*)&pf[2];
            const float* p3 = (const float*)&pf[3];
            #pragma unroll
            for (int i = 0; i < 4; i++) {
                stageu[sk2 * 264 + sc0 + i]       = pack_bf16x2(p0[i], p1[i]);
                stageu[sk2 * 264 + 128 + sc0 + i] = pack_bf16x2(p2[i], p3[i]);
            }
        }
        __syncthreads();
        if (sl < 7) {
            const int kg = (sl + 1) * 16 + 2 * sk2;
            pf[0] = *(const float4*)(We2 + kg * 256 + sc0);
            pf[1] = *(const float4*)(We2 + (kg + 1) * 256 + sc0);
            pf[2] = *(const float4*)(We2 + kg * 256 + 128 + sc0);
            pf[3] = *(const float4*)(We2 + (kg + 1) * 256 + 128 + sc0);
        }
        // one k16 step covering the whole slice
        unsigned a[4][4];
        #pragma unroll
        for (int mt = 0; mt < 4; mt++) {
            const unsigned* ap = (const unsigned*)h1A + (mt * 16 + g) * 68 + sl * 8 + tig;
            a[mt][0] = ap[0];
            a[mt][1] = ap[8 * 68];
            a[mt][2] = ap[4];
            a[mt][3] = ap[8 * 68 + 4];
        }
        #pragma unroll
        for (int nt = 0; nt < 4; nt++) {
            const unsigned b0 = stageu[tig * 264 + wb + nt * 8 + g];
            const unsigned b1 = stageu[(tig + 4) * 264 + wb + nt * 8 + g];
            #pragma unroll
            for (int mt = 0; mt < 4; mt++) mma_bf16(d[mt][nt], a[mt], b0, b1);
        }
    }

    // epilogue: bias + relu (exact fp32), maxpool per patch, shfl over g,
    // transposed write to g_codeT.
    #pragma unroll
    for (int nt = 0; nt < 4; nt++) {
        const int c0 = wb + nt * 8 + 2 * tig;
        const float bb0 = be2[c0], bb1 = be2[c0 + 1];
        float p00 = fmaxf(fmaxf(fmaxf(d[0][nt][0], d[0][nt][2]),
                                fmaxf(d[1][nt][0], d[1][nt][2])) + bb0, 0.0f);
        float p01 = fmaxf(fmaxf(fmaxf(d[0][nt][1], d[0][nt][3]),
                                fmaxf(d[1][nt][1], d[1][nt][3])) + bb1, 0.0f);
        float p10 = fmaxf(fmaxf(fmaxf(d[2][nt][0], d[2][nt][2]),
                                fmaxf(d[3][nt][0], d[3][nt][2])) + bb0, 0.0f);
        float p11 = fmaxf(fmaxf(fmaxf(d[2][nt][1], d[2][nt][3]),
                                fmaxf(d[3][nt][1], d[3][nt][3])) + bb1, 0.0f);
        #pragma unroll
        for (int off = 4; off <= 16; off <<= 1) {
            p00 = fmaxf(p00, __shfl_xor_sync(0xFFFFFFFFu, p00, off));
            p01 = fmaxf(p01, __shfl_xor_sync(0xFFFFFFFFu, p01, off));
            p10 = fmaxf(p10, __shfl_xor_sync(0xFFFFFFFFu, p10, off));
            p11 = fmaxf(p11, __shfl_xor_sync(0xFFFFFFFFu, p11, off));
        }
        if (g == 0) {
            *(float2*)(g_codeT + (size_t)c0 * MTOT + m0)       = make_float2(p00, p10);
            *(float2*)(g_codeT + (size_t)(c0 + 1) * MTOT + m0) = make_float2(p01, p11);
        }
    }
}

// ============================================================================
// K3b base: base{1,2}[m][c] = code[m]·Wf{1,2}a[:256,c] + b.  (exact fp32 fma2)
// 2D grid (matrix on blockIdx.y), 16-k slices, register double-buffer.
// ============================================================================
__global__ __launch_bounds__(256, 2)
void base_kernel(const float* __restrict__ Wf1a, const float* __restrict__ bf1a,
                 const float* __restrict__ Wf2a, const float* __restrict__ bf2a)
{
    extern __shared__ float s[];
    float* ct    = s;            // [256 k][64 m]  16384
    float* stage = s + 16384;    // [16 k][256 c]   4096  -> 20480 fl

    const int t  = threadIdx.x;
    const int m0 = blockIdx.x * 64;
    const int mat = blockIdx.y;
    const float* W  = mat ? Wf2a : Wf1a;
    const float* bv = mat ? bf2a : bf1a;
    float* dst = mat ? g_base2 : g_base1;

    for (int i = t; i < 4096; i += 256) {
        const int k = i >> 4, mq = i & 15;
        *(float4*)(ct + k * 64 + mq * 4) =
            *(const float4*)(g_codeT + (size_t)k * MTOT + m0 + mq * 4);
    }

    const int rg = t & 7, cg = t >> 3;
    const int r0 = rg * 8, c0 = cg * 8;

    unsigned long long acc2[4][8];
    #pragma unroll
    for (int i = 0; i < 4; i++)
        #pragma unroll
        for (int j = 0; j < 8; j++) acc2[i][j] = 0ull;

    float4 pf[4];
    {
        const float4* src = (const float4*)W;
        #pragma unroll
        for (int i = 0; i < 4; i++) pf[i] = src[t + 256 * i];
    }
    for (int sl = 0; sl < 16; sl++) {
        __syncthreads();
        #pragma unroll
        for (int i = 0; i < 4; i++) ((float4*)stage)[t + 256 * i] = pf[i];
        __syncthreads();
        if (sl < 15) {
            const float4* src = (const float4*)(W + (sl + 1) * 16 * 256);
            #pragma unroll
            for (int i = 0; i < 4; i++) pf[i] = src[t + 256 * i];
        }
        #pragma unroll 4
        for (int k = 0; k < 16; k++) {
            const int kk = sl * 16 + k;
            const ulonglong2 a0 = *(const ulonglong2*)(ct + kk * 64 + r0);
            const ulonglong2 a1 = *(const ulonglong2*)(ct + kk * 64 + r0 + 4);
            const unsigned long long ap[4] = {a0.x, a0.y, a1.x, a1.y};
            const float4 w0 = *(const float4*)(stage + k * 256 + c0);
            const float4 w1 = *(const float4*)(stage + k * 256 + c0 + 4);
            const unsigned long long wp[8] = {pack2(w0.x), pack2(w0.y), pack2(w0.z), pack2(w0.w),
                                              pack2(w1.x), pack2(w1.y), pack2(w1.z), pack2(w1.w)};
            #pragma unroll
            for (int i = 0; i < 4; i++)
                #pragma unroll
                for (int j = 0; j < 8; j++) fma2(acc2[i][j], ap[i], wp[j]);
        }
    }
    #pragma unroll
    for (int i = 0; i < 4; i++) {
        float4 lo0, lo1, hi0, hi1;
        float* l0 = (float*)&lo0; float* l1 = (float*)&lo1;
        float* h0 = (float*)&hi0; float* h1 = (float*)&hi1;
        #pragma unroll
        for (int j = 0; j < 8; j++) {
            const float bb = bv[c0 + j];
            const float2 v = unpack2(acc2[i][j]);
            if (j < 4) { l0[j] = v.x + bb; h0[j] = v.y + bb; }
            else       { l1[j - 4] = v.x + bb; h1[j - 4] = v.y + bb; }
        }
        float* d0 = dst + (size_t)(m0 + r0 + 2 * i) * 256 + c0;
        float* d1 = dst + (size_t)(m0 + r0 + 2 * i + 1) * 256 + c0;
        *(float4*)d0 = lo0; *(float4*)(d0 + 4) = lo1;
        *(float4*)d1 = hi0; *(float4*)(d1 + 4) = hi1;
    }
}

// ============================================================================
// K3c fold: 2 patches/block, 512 threads, occupancy 2, BF16 TENSOR-CORE GEMMs
// (m16n8k16.bf16). SMEM FIX vs round 11: hfA = [64][136] bf16 = 4352 FLOATS;
// hf2 moved to s+4352, stageu to s+12800 (round 11 overlapped hf2 with hfA).
// A covers one 128-k half at a time (rebuilt per half, packed bf16x2 stores);
// within-half k offset kh kept. fold1c/2c and epilogue exact fp32.
// ============================================================================
__global__ __launch_bounds__(512, 2)
void fold_kernel(const float* __restrict__ grid_,
                 const float* __restrict__ Wf1a,
                 const float* __restrict__ Wf1b, const float* __restrict__ bf1b,
                 const float* __restrict__ Wf1c, const float* __restrict__ bf1c,
                 const float* __restrict__ Wf2a,
                 const float* __restrict__ Wf2b, const float* __restrict__ bf2b,
                 const float* __restrict__ Wf2c, const float* __restrict__ bf2c,
                 float* __restrict__ out)
{
    extern __shared__ float s[];
    __nv_bfloat16* hfA = (__nv_bfloat16*)s;        // [64][136] bf16 = 4352 fl
    float* hf2         = s + 4352;                 // [64 r][132] f32 = 8448 fl
    unsigned* stageu   = (unsigned*)(s + 12800);   // [16 k2][136]   = 2176 fl
    float* Wc1         = s + 14976;                // [384]
    float* Wc2         = s + 15360;                // [384]
    float* gx          = s + 15744;                // [32]
    float* gy          = s + 15776;                // [32]
    float* fv          = s + 15808;                // [192]
    float* cm          = s + 16000;                // [8]  -> 16008 fl = 64032 B

    const int t = threadIdx.x;
    const int m0 = blockIdx.x * 2;
    const float scale = sqrtf(__uint_as_float(g_scale_bits));

    // A-build thread mapping: k-pair kp = t&63 (k = 2kp, 2kp+1 within half),
    // row group rgrp = t>>6 (rows rgrp*8 .. +7, all within one patch)
    const int kp   = t & 63;
    const int rgrp = t >> 6;
    const int pA   = rgrp >> 2;

    if (t < 384) { Wc1[t] = Wf1c[t]; Wc2[t] = Wf2c[t]; }
    if (t < 32) { gx[t] = grid_[2 * t]; gy[t] = grid_[2 * t + 1]; }
    if (t < 6)  cm[t] = g_cmean[(size_t)m0 * 3 + t];
    __syncthreads();

    const int lane = t & 31, g = lane >> 2, tig = lane & 3;
    const int wb = (t >> 5) * 8;               // warp's 8-column strip

    // staging: 16 k2-rows x 128 c = 2048 words / 512 thr = 4 per thread
    const int sk2 = t >> 5;                    // 0..15
    const int sc0 = (t & 31) * 4;

    unsigned* h1w = (unsigned*)hfA;            // word view, stride 68

    #pragma unroll
    for (int stagei = 0; stagei < 2; stagei++) {
        const float* W  = stagei ? Wf2b : Wf1b;
        const float* bv = stagei ? bf2b : bf1b;

        float d[4][4];
        #pragma unroll
        for (int mt = 0; mt < 4; mt++)
            #pragma unroll
            for (int j = 0; j < 4; j++) d[mt][j] = 0.0f;

        float4 pf0 = *(const float4*)(W + (2 * sk2) * 128 + sc0);
        float4 pf1 = *(const float4*)(W + (2 * sk2 + 1) * 128 + sc0);

        for (int gs = 0; gs < 8; gs++) {       // 8 slices of 32 k (2 halves x 4)
            if ((gs & 3) == 0) {
                // rebuild A for half h = gs>>2 (packed bf16x2 stores)
                const int h = gs >> 2;
                if (gs) __syncthreads();       // prior half's MMA reads done
                const int kg = h * 128 + 2 * kp;
                if (stagei == 0) {
                    const float2 bb = *(const float2*)(g_base1 + (size_t)(m0 + pA) * 256 + kg);
                    const float2 w0 = *(const float2*)(Wf1a + 256 * 256 + kg);
                    const float2 w1 = *(const float2*)(Wf1a + 257 * 256 + kg);
                    #pragma unroll
                    for (int i = 0; i < 8; i++) {
                        const int r  = rgrp * 8 + i;
                        const int rr = r & 31;
                        const float v0 = fmaxf(bb.x + gx[rr] * w0.x + gy[rr] * w1.x, 0.0f);
                        const float v1 = fmaxf(bb.y + gx[rr] * w0.y + gy[rr] * w1.y, 0.0f);
                        h1w[r * 68 + kp] = pack_bf16x2(v0, v1);
                    }
                } else {
                    const float2 bb = *(const float2*)(g_base2 + (size_t)(m0 + pA) * 256 + kg);
                    const float2 w0 = *(const float2*)(Wf2a + 256 * 256 + kg);
                    const float2 w1 = *(const float2*)(Wf2a + 257 * 256 + kg);
                    const float2 w2 = *(const float2*)(Wf2a + 258 * 256 + kg);
                    #pragma unroll
                    for (int i = 0; i < 8; i++) {
                        const int r = rgrp * 8 + i;
                        const float f0 = fv[r * 3], f1 = fv[r * 3 + 1], f2 = fv[r * 3 + 2];
                        const float v0 = fmaxf(bb.x + f0 * w0.x + f1 * w1.x + f2 * w2.x, 0.0f);
                        const float v1 = fmaxf(bb.y + f0 * w0.y + f1 * w1.y + f2 * w2.y, 0.0f);
                        h1w[r * 68 + kp] = pack_bf16x2(v0, v1);
                    }
                }
            }
            __syncthreads();                   // A ready / prev stage consumed
            {
                const float* p0 = (const float*)&pf0;
                const float* p1 = (const float*)&pf1;
                #pragma unroll
                for (int i = 0; i < 4; i++)
                    stageu[sk2 * 136 + sc0 + i] = pack_bf16x2(p0[i], p1[i]);
            }
            __syncthreads();
            if (gs < 7) {
                const int kgn = (gs + 1) * 32 + 2 * sk2;
                pf0 = *(const float4*)(W + kgn * 128 + sc0);
                pf1 = *(const float4*)(W + (kgn + 1) * 128 + sc0);
            }
            const int khw = (gs & 3) * 16;     // within-half k offset (words)
            #pragma unroll
            for (int ks2 = 0; ks2 < 2; ks2++) {   // 2 k16-steps per slice
                const unsigned b0 = stageu[(ks2 * 8 + tig) * 136 + wb + g];
                const unsigned b1 = stageu[(ks2 * 8 + tig + 4) * 136 + wb + g];
                #pragma unroll
                for (int mt = 0; mt < 4; mt++) {
                    const unsigned* ap = h1w + (mt * 16 + g) * 68 + khw + ks2 * 8 + tig;
                    unsigned a[4];
                    a[0] = ap[0];
                    a[1] = ap[8 * 68];
                    a[2] = ap[4];
                    a[3] = ap[8 * 68 + 4];
                    mma_bf16(d[mt], a, b0, b1);
                }
            }
        }

        // epilogue: bias + relu -> hf2[64 r][132]  (exact fp32)
        {
            const int col = wb + 2 * tig;
            const float bb0 = bv[col], bb1 = bv[col + 1];
            #pragma unroll
            for (int mt = 0; mt < 4; mt++) {
                const int r = mt * 16 + g;
                *(float2*)(hf2 + r * 132 + col) =
                    make_float2(fmaxf(d[mt][0] + bb0, 0.0f),
                                fmaxf(d[mt][1] + bb1, 0.0f));
                *(float2*)(hf2 + (r + 8) * 132 + col) =
                    make_float2(fmaxf(d[mt][2] + bb0, 0.0f),
                                fmaxf(d[mt][3] + bb1, 0.0f));
            }
        }
        __syncthreads();

        if (stagei == 0) {
            // fold1c: fv[r][q] = hf2[r]·Wf1c[:,q] + bf1c[q]  (exact fp32)
            if (t < 192) {
                const int r = t / 3, q = t - (t / 3) * 3;
                float acc = bf1c[q];
                #pragma unroll 8
                for (int k = 0; k < 128; k++) acc += hf2[r * 132 + k] * Wc1[k * 3 + q];
                fv[t] = acc;
            }
            __syncthreads();
        } else {
            // fold2c + output (exact fp32)
            if (t < 192) {
                const int r = t / 3, q = t - (t / 3) * 3;
                const int p = r >> 5, rr = r & 31;
                float acc = bf2c[q];
                #pragma unroll 8
                for (int k = 0; k < 128; k++) acc += hf2[r * 132 + k] * Wc2[k * 3 + q];
                out[(size_t)(m0 + p) * 96 + rr * 3 + q] = acc * scale + cm[p * 3 + q];
            }
        }
    }
}

// ============================================================================
extern "C" void kernel_launch(void* const* d_in, const int* in_sizes, int n_in,
                              void* d_out, int out_size)
{
    (void)in_sizes; (void)n_in; (void)out_size;
    const float* data = (const float*)d_in[0];
    const int*   perm = (const int*)  d_in[1];
    const float* grid = (const float*)d_in[2];
    const float* We1  = (const float*)d_in[3];
    const float* be1  = (const float*)d_in[4];
    const float* We2  = (const float*)d_in[5];
    const float* be2  = (const float*)d_in[6];
    const float* Wf1a = (const float*)d_in[7];
    const float* bf1a = (const float*)d_in[8];
    const float* Wf1b = (const float*)d_in[9];
    const float* bf1b = (const float*)d_in[10];
    const float* Wf1c = (const float*)d_in[11];
    const float* bf1c = (const float*)d_in[12];
    const float* Wf2a = (const float*)d_in[13];
    const float* bf2a = (const float*)d_in[14];
    const float* Wf2b = (const float*)d_in[15];
    const float* bf2b = (const float*)d_in[16];
    const float* Wf2c = (const float*)d_in[17];
    const float* bf2c = (const float*)d_in[18];
    float* out = (float*)d_out;

    const int fps_smem  = 3 * NN * sizeof(float);      // 98304
    const int knn_smem  = 3 * NN * sizeof(float);      // 98304
    const int enc_smem  = 6656  * sizeof(float);       // 26624
    const int base_smem = 20480 * sizeof(float);       // 81920
    const int fold_smem = 16008 * sizeof(float);       // 64032
    cudaFuncSetAttribute(fps_kernel,  cudaFuncAttributeMaxDynamicSharedMemorySize, fps_smem);
    cudaFuncSetAttribute(knn_kernel,  cudaFuncAttributeMaxDynamicSharedMemorySize, knn_smem);
    cudaFuncSetAttribute(enc_kernel,  cudaFuncAttributeMaxDynamicSharedMemorySize, enc_smem);
    cudaFuncSetAttribute(base_kernel, cudaFuncAttributeMaxDynamicSharedMemorySize, base_smem);
    cudaFuncSetAttribute(fold_kernel, cudaFuncAttributeMaxDynamicSharedMemorySize, fold_smem);

    fps_kernel <<<BB, 1024, fps_smem>>>(data);
    knn_kernel <<<(BB * NC) / 8, 256, knn_smem>>>(data, perm);
    enc_kernel <<<MTOT / 2, 256, enc_smem>>>(We1, be1, We2, be2);
    base_kernel<<<dim3(MTOT / 64, 2), 256, base_smem>>>(Wf1a, bf1a, Wf2a, bf2a);
    fold_kernel<<<MTOT / 2, 512, fold_smem>>>(grid, Wf1a, Wf1b, bf1b, Wf1c, bf1c,
                                              Wf2a, Wf2b, bf2b, Wf2c, bf2c, out);
}

// round 13
// speedup vs baseline: 2.6957x; 1.0019x over previous
#include <cuda_runtime.h>
#include <cuda_bf16.h>
#include <math.h>

#define BB 32
#define NN 8192
#define NC 256
#define NP 32
#define MTOT (BB * NC)          // 8192 patches

// ---------------- scratch (device globals; no allocation allowed) ----------
__device__ float    g_centers[BB * NC * 3];
__device__ float    g_local  [MTOT * NP * 3];
__device__ float    g_cmean  [MTOT * 3];
__device__ unsigned g_scale_bits;
__device__ float    g_codeT [256 * MTOT];      // code transposed [c][m]
__device__ float    g_base1 [MTOT * 256];      // [m][c]
__device__ float    g_base2 [MTOT * 256];      // [m][c]

// ---------------- bf16 mma helpers ------------------------------------------
// pack_bf16x2(lo, hi): lower 16 bits = bf16(lo) (smaller k), upper = bf16(hi)
__device__ __forceinline__ unsigned pack_bf16x2(float lo, float hi) {
    unsigned r;
    asm("cvt.rn.bf16x2.f32 %0, %1, %2;" : "=r"(r) : "f"(hi), "f"(lo));
    return r;
}
// mma.m16n8k16 bf16: A row-major 16x16 (4 .b32 of bf16x2), B col-major 16x8
// (2 .b32), D/C fp32 (4 regs).
__device__ __forceinline__ void mma_bf16(float* d, const unsigned* a,
                                         unsigned b0, unsigned b1) {
    asm volatile(
        "mma.sync.aligned.m16n8k16.row.col.f32.bf16.bf16.f32 "
        "{%0,%1,%2,%3}, {%4,%5,%6,%7}, {%8,%9}, {%0,%1,%2,%3};"
        : "+f"(d[0]), "+f"(d[1]), "+f"(d[2]), "+f"(d[3])
        : "r"(a[0]), "r"(a[1]), "r"(a[2]), "r"(a[3]), "r"(b0), "r"(b1));
}

// ============================================================================
// K1: FPS — one block per batch, points/mind in registers. ONE barrier per
// iteration: ping-pong skeys[2][32] + every warp redundantly reduces all 32
// keys (deterministic). Exact jnp.argmax tie semantics via key packing.
// Distance arithmetic replicates the reference exactly (no FMA contraction).
// ============================================================================
__global__ __launch_bounds__(1024, 1)
void fps_kernel(const float* __restrict__ data)
{
    extern __shared__ float sm[];
    float* sx = sm;
    float* sy = sm + NN;
    float* sz = sm + 2 * NN;
    __shared__ unsigned long long skeys[2][32];

    const int b = blockIdx.x;
    const int t = threadIdx.x;
    const int wid = t >> 5, lane = t & 31;
    if (b == 0 && t == 0) g_scale_bits = 0u;   // reset every launch (graph replay safe)

    const float* dp = data + (size_t)b * 3 * NN;
    for (int n = t; n < NN; n += 1024) {
        sx[n] = dp[n];
        sy[n] = dp[NN + n];
        sz[n] = dp[2 * NN + n];
    }
    __syncthreads();

    float rx[8], ry[8], rz[8], md[8];
    const int base = t * 8;
    #pragma unroll
    for (int j = 0; j < 8; j++) {
        rx[j] = sx[base + j];
        ry[j] = sy[base + j];
        rz[j] = sz[base + j];
        md[j] = 3.4e38f;
    }

    float px = sx[0], py = sy[0], pz = sz[0];
    if (t == 0) {
        float* c = g_centers + (size_t)(b * NC) * 3;
        c[0] = px; c[1] = py; c[2] = pz;
    }

    for (int i = 1; i < NC; i++) {
        float bv = -1.0f; int bi = base;
        #pragma unroll
        for (int j = 0; j < 8; j++) {
            float dx = __fadd_rn(rx[j], -px);
            float dy = __fadd_rn(ry[j], -py);
            float dz = __fadd_rn(rz[j], -pz);
            float d  = __fadd_rn(__fadd_rn(__fmul_rn(dx, dx), __fmul_rn(dy, dy)),
                                 __fmul_rn(dz, dz));
            float m  = fminf(md[j], d);
            md[j] = m;
            if (m > bv) { bv = m; bi = base + j; }
        }
        unsigned long long key =
            ((unsigned long long)__float_as_uint(bv) << 32) | (unsigned)(NN - 1 - bi);
        #pragma unroll
        for (int off = 16; off; off >>= 1) {
            unsigned long long o = __shfl_down_sync(0xFFFFFFFFu, key, off);
            if (o > key) key = o;
        }
        if (lane == 0) skeys[i & 1][wid] = key;
        __syncthreads();
        // every warp reduces all 32 keys redundantly — no second barrier
        unsigned long long k2 = skeys[i & 1][lane];
        #pragma unroll
        for (int off = 16; off; off >>= 1) {
            unsigned long long o = __shfl_down_sync(0xFFFFFFFFu, k2, off);
            if (o > k2) k2 = o;
        }
        k2 = __shfl_sync(0xFFFFFFFFu, k2, 0);
        const int sel = NN - 1 - (int)(k2 & 0xFFFFFFFFull);
        px = sx[sel]; py = sy[sel]; pz = sz[sel];
        if (t == 0) {
            float* c = g_centers + (size_t)(b * NC + i) * 3;
            c[0] = px; c[1] = py; c[2] = pz;
        }
    }
}

// ============================================================================
// K2: kNN set of 32 — one warp per center, 8 centers/block, points in smem.
// Sorted-insertion top-32 (lane 31 = current max); tie semantics match
// lax.top_k exactly (ascending-index candidates, stable insert after equals).
// ============================================================================
__global__ __launch_bounds__(256, 2)
void knn_kernel(const float* __restrict__ data, const int* __restrict__ perm)
{
    extern __shared__ float sp[];                    // [3*NN]
    const int warp = threadIdx.x >> 5;
    const int lane = threadIdx.x & 31;
    const int w  = blockIdx.x * 8 + warp;
    const int b  = w >> 8;
    const int ci = w & 255;
    const int p  = perm[ci];

    const float* dp = data + (size_t)b * 3 * NN;
    for (int i = threadIdx.x; i < 3 * NN / 4; i += 256)
        ((float4*)sp)[i] = ((const float4*)dp)[i];
    __syncthreads();
    const float* sx = sp, *sy = sp + NN, *sz = sp + 2 * NN;

    const float* cc = g_centers + (size_t)(b * NC + p) * 3;
    const float cx = cc[0], cy = cc[1], cz = cc[2];
    const float cs = (cx * cx + cy * cy) + cz * cz;

    float kd = 3.4e38f;          // sorted ascending across lanes
    int   ki = -1;
    float cm = 3.4e38f;          // = kd at lane 31

    for (int bse = 0; bse < NN; bse += 32) {
        const int n = bse + lane;
        const float px = sx[n], py = sy[n], pz = sz[n];
        const float ps  = (px * px + py * py) + pz * pz;
        const float dot = (cx * px + cy * py) + cz * pz;
        const float d = (cs + ps) - 2.0f * dot;

        unsigned m = __ballot_sync(0xFFFFFFFFu, d < cm);
        while (m) {
            const int src = __ffs(m) - 1; m &= m - 1;
            const float dc = __shfl_sync(0xFFFFFFFFu, d, src);
            if (dc < cm) {                       // strict: equal-to-max never enters
                const int pos = __popc(__ballot_sync(0xFFFFFFFFu, kd <= dc));
                const float skd = __shfl_up_sync(0xFFFFFFFFu, kd, 1);
                const int   ski = __shfl_up_sync(0xFFFFFFFFu, ki, 1);
                if (lane > pos)       { kd = skd; ki = ski; }
                else if (lane == pos) { kd = dc;  ki = bse + src; }
                cm = __shfl_sync(0xFFFFFFFFu, kd, 31);
            }
        }
    }

    const float nx = sx[ki], ny = sy[ki], nz = sz[ki];
    float sxx = nx, syy = ny, szz = nz;
    #pragma unroll
    for (int off = 16; off; off >>= 1) {
        sxx += __shfl_xor_sync(0xFFFFFFFFu, sxx, off);
        syy += __shfl_xor_sync(0xFFFFFFFFu, syy, off);
        szz += __shfl_xor_sync(0xFFFFFFFFu, szz, off);
    }
    const float mx = sxx * (1.0f / 32.0f);
    const float my = syy * (1.0f / 32.0f);
    const float mz = szz * (1.0f / 32.0f);
    const float lx = nx - mx, ly = ny - my, lz = nz - mz;
    const float ns = (lx * lx + ly * ly) + lz * lz;
    float wm = ns;
    #pragma unroll
    for (int off = 16; off; off >>= 1) wm = fmaxf(wm, __shfl_xor_sync(0xFFFFFFFFu, wm, off));
    if (lane == 0) atomicMax(&g_scale_bits, __float_as_uint(wm));

    float* lp = g_local + ((size_t)w * NP + lane) * 3;
    lp[0] = lx; lp[1] = ly; lp[2] = lz;
    if (lane < 3) g_cmean[(size_t)w * 3 + lane] = (lane == 0) ? mx : ((lane == 1) ? my : mz);
}

// ============================================================================
// K3a enc: 2 patches/block (64 rows), BF16 TENSOR-CORE enc2 (m16n8k16.bf16).
// (unchanged from round 12 — passing)
// ============================================================================
__global__ __launch_bounds__(256, 2)
void enc_kernel(const float* __restrict__ We1, const float* __restrict__ be1,
                const float* __restrict__ We2, const float* __restrict__ be2)
{
    extern __shared__ float s[];
    __nv_bfloat16* h1A = (__nv_bfloat16*)s;        // [64][136] bf16 = 4352 fl
    unsigned* stageu   = (unsigned*)(s + 4352);    // [8 k2][264]    = 2112 fl
    float* xs          = s + 4352 + 2112;          // [64][3]        =  192 fl
                                                   // total 6656 fl = 26624 B
    const int t  = threadIdx.x;
    const int m0 = blockIdx.x * 2;
    const float scale = sqrtf(__uint_as_float(g_scale_bits));

    if (t < 192) xs[t] = g_local[(size_t)blockIdx.x * 192 + t] / scale;
    __syncthreads();

    // enc1 (exact fp32): thread handles k-pair (2kp, 2kp+1), rows rh,rh+4,...
    {
        const int kp = t & 63;          // k-pair index, k = 2kp, 2kp+1
        const int rh = t >> 6;          // 0..3
        const float2 w0 = *(const float2*)(We1 + 0 * 128 + 2 * kp);
        const float2 w1 = *(const float2*)(We1 + 1 * 128 + 2 * kp);
        const float2 w2 = *(const float2*)(We1 + 2 * 128 + 2 * kp);
        const float2 bb = *(const float2*)(be1 + 2 * kp);
        unsigned* h1w = (unsigned*)h1A;
        #pragma unroll
        for (int i = 0; i < 16; i++) {
            const int r = i * 4 + rh;
            const float x0 = xs[r * 3], x1 = xs[r * 3 + 1], x2 = xs[r * 3 + 2];
            const float v0 = fmaxf(x0 * w0.x + x1 * w1.x + x2 * w2.x + bb.x, 0.0f);
            const float v1 = fmaxf(x0 * w0.y + x1 * w1.y + x2 * w2.y + bb.y, 0.0f);
            h1w[r * 68 + kp] = pack_bf16x2(v0, v1);
        }
    }

    const int lane = t & 31, g = lane >> 2, tig = lane & 3;
    const int wb = (t >> 5) * 32;              // warp's 32-column strip

    const int sk2 = t >> 5;
    const int sc0 = (t & 31) * 4;

    float d[4][4][4];                          // [m-tile][n-tile][frag]
    #pragma unroll
    for (int mt = 0; mt < 4; mt++)
        #pragma unroll
        for (int nt = 0; nt < 4; nt++)
            #pragma unroll
            for (int j = 0; j < 4; j++) d[mt][nt][j] = 0.0f;

    float4 pf[4];
    pf[0] = *(const float4*)(We2 + (2 * sk2) * 256 + sc0);
    pf[1] = *(const float4*)(We2 + (2 * sk2 + 1) * 256 + sc0);
    pf[2] = *(const float4*)(We2 + (2 * sk2) * 256 + 128 + sc0);
    pf[3] = *(const float4*)(We2 + (2 * sk2 + 1) * 256 + 128 + sc0);

    for (int sl = 0; sl < 8; sl++) {           // 8 slices of 16 k (1 kstep each)
        __syncthreads();
        {
            const float* p0 = (const float*)&pf[0];
            const float* p1 = (const float*)&pf[1];
            const float* p2 = (const float*)&pf[2];
            const float* p3 = (const float*)&pf[3];
            #pragma unroll
            for (int i = 0; i < 4; i++) {
                stageu[sk2 * 264 + sc0 + i]       = pack_bf16x2(p0[i], p1[i]);
                stageu[sk2 * 264 + 128 + sc0 + i] = pack_bf16x2(p2[i], p3[i]);
            }
        }
        __syncthreads();
        if (sl < 7) {
            const int kg = (sl + 1) * 16 + 2 * sk2;
            pf[0] = *(const float4*)(We2 + kg * 256 + sc0);
            pf[1] = *(const float4*)(We2 + (kg + 1) * 256 + sc0);
            pf[2] = *(const float4*)(We2 + kg * 256 + 128 + sc0);
            pf[3] = *(const float4*)(We2 + (kg + 1) * 256 + 128 + sc0);
        }
        unsigned a[4][4];
        #pragma unroll
        for (int mt = 0; mt < 4; mt++) {
            const unsigned* ap = (const unsigned*)h1A + (mt * 16 + g) * 68 + sl * 8 + tig;
            a[mt][0] = ap[0];
            a[mt][1] = ap[8 * 68];
            a[mt][2] = ap[4];
            a[mt][3] = ap[8 * 68 + 4];
        }
        #pragma unroll
        for (int nt = 0; nt < 4; nt++) {
            const unsigned b0 = stageu[tig * 264 + wb + nt * 8 + g];
            const unsigned b1 = stageu[(tig + 4) * 264 + wb + nt * 8 + g];
            #pragma unroll
            for (int mt = 0; mt < 4; mt++) mma_bf16(d[mt][nt], a[mt], b0, b1);
        }
    }

    #pragma unroll
    for (int nt = 0; nt < 4; nt++) {
        const int c0 = wb + nt * 8 + 2 * tig;
        const float bb0 = be2[c0], bb1 = be2[c0 + 1];
        float p00 = fmaxf(fmaxf(fmaxf(d[0][nt][0], d[0][nt][2]),
                                fmaxf(d[1][nt][0], d[1][nt][2])) + bb0, 0.0f);
        float p01 = fmaxf(fmaxf(fmaxf(d[0][nt][1], d[0][nt][3]),
                                fmaxf(d[1][nt][1], d[1][nt][3])) + bb1, 0.0f);
        float p10 = fmaxf(fmaxf(fmaxf(d[2][nt][0], d[2][nt][2]),
                                fmaxf(d[3][nt][0], d[3][nt][2])) + bb0, 0.0f);
        float p11 = fmaxf(fmaxf(fmaxf(d[2][nt][1], d[2][nt][3]),
                                fmaxf(d[3][nt][1], d[3][nt][3])) + bb1, 0.0f);
        #pragma unroll
        for (int off = 4; off <= 16; off <<= 1) {
            p00 = fmaxf(p00, __shfl_xor_sync(0xFFFFFFFFu, p00, off));
            p01 = fmaxf(p01, __shfl_xor_sync(0xFFFFFFFFu, p01, off));
            p10 = fmaxf(p10, __shfl_xor_sync(0xFFFFFFFFu, p10, off));
            p11 = fmaxf(p11, __shfl_xor_sync(0xFFFFFFFFu, p11, off));
        }
        if (g == 0) {
            *(float2*)(g_codeT + (size_t)c0 * MTOT + m0)       = make_float2(p00, p10);
            *(float2*)(g_codeT + (size_t)(c0 + 1) * MTOT + m0) = make_float2(p01, p11);
        }
    }
}

// ============================================================================
// K3b base: NOW BF16 TENSOR-CORE (m16n8k16). base{1,2}[m][c] = code[m]·W + b.
// M=64, N=256, K=256; same fragment/staging recipe as enc. A built from
// g_codeT[k][m] into bf16 words [64 m][132 k-words] (stride 132 == 4 mod 32
// -> conflict-free A-frags). Bias added in fp32 epilogue.
// ============================================================================
__global__ __launch_bounds__(256, 2)
void base_kernel(const float* __restrict__ Wf1a, const float* __restrict__ bf1a,
                 const float* __restrict__ Wf2a, const float* __restrict__ bf2a)
{
    extern __shared__ float s[];
    unsigned* cAw    = (unsigned*)s;            // [64 m][132 w] = 8448 fl
    unsigned* stageu = (unsigned*)(s + 8448);   // [8 k2][264]   = 2112 fl
                                                // total 10560 fl = 42240 B
    const int t  = threadIdx.x;
    const int m0 = blockIdx.x * 64;
    const int mat = blockIdx.y;
    const float* W  = mat ? Wf2a : Wf1a;
    const float* bv = mat ? bf2a : bf1a;
    float* dst = mat ? g_base2 : g_base1;

    // A build: thread -> mq = t&15 (4 m's), k2 = (t>>4) + 16*i
    {
        const int mq  = t & 15;
        const int k2g = t >> 4;
        #pragma unroll
        for (int i = 0; i < 8; i++) {
            const int k2 = k2g + 16 * i;
            const float4 a = *(const float4*)(g_codeT + (size_t)(2 * k2) * MTOT + m0 + 4 * mq);
            const float4 b = *(const float4*)(g_codeT + (size_t)(2 * k2 + 1) * MTOT + m0 + 4 * mq);
            cAw[(4 * mq + 0) * 132 + k2] = pack_bf16x2(a.x, b.x);
            cAw[(4 * mq + 1) * 132 + k2] = pack_bf16x2(a.y, b.y);
            cAw[(4 * mq + 2) * 132 + k2] = pack_bf16x2(a.z, b.z);
            cAw[(4 * mq + 3) * 132 + k2] = pack_bf16x2(a.w, b.w);
        }
    }

    const int lane = t & 31, g = lane >> 2, tig = lane & 3;
    const int wb = (t >> 5) * 32;              // warp's 32-column strip
    const int sk2 = t >> 5;
    const int sc0 = (t & 31) * 4;

    float d[4][4][4];
    #pragma unroll
    for (int mt = 0; mt < 4; mt++)
        #pragma unroll
        for (int nt = 0; nt < 4; nt++)
            #pragma unroll
            for (int j = 0; j < 4; j++) d[mt][nt][j] = 0.0f;

    float4 pf[4];
    pf[0] = *(const float4*)(W + (2 * sk2) * 256 + sc0);
    pf[1] = *(const float4*)(W + (2 * sk2 + 1) * 256 + sc0);
    pf[2] = *(const float4*)(W + (2 * sk2) * 256 + 128 + sc0);
    pf[3] = *(const float4*)(W + (2 * sk2 + 1) * 256 + 128 + sc0);

    for (int sl = 0; sl < 16; sl++) {          // 16 slices of 16 k
        __syncthreads();
        {
            const float* p0 = (const float*)&pf[0];
            const float* p1 = (const float*)&pf[1];
            const float* p2 = (const float*)&pf[2];
            const float* p3 = (const float*)&pf[3];
            #pragma unroll
            for (int i = 0; i < 4; i++) {
                stageu[sk2 * 264 + sc0 + i]       = pack_bf16x2(p0[i], p1[i]);
                stageu[sk2 * 264 + 128 + sc0 + i] = pack_bf16x2(p2[i], p3[i]);
            }
        }
        __syncthreads();
        if (sl < 15) {
            const int kg = (sl + 1) * 16 + 2 * sk2;
            pf[0] = *(const float4*)(W + kg * 256 + sc0);
            pf[1] = *(const float4*)(W + (kg + 1) * 256 + sc0);
            pf[2] = *(const float4*)(W + kg * 256 + 128 + sc0);
            pf[3] = *(const float4*)(W + (kg + 1) * 256 + 128 + sc0);
        }
        unsigned a[4][4];
        #pragma unroll
        for (int mt = 0; mt < 4; mt++) {
            const unsigned* ap = cAw + (mt * 16 + g) * 132 + sl * 8 + tig;
            a[mt][0] = ap[0];
            a[mt][1] = ap[8 * 132];
            a[mt][2] = ap[4];
            a[mt][3] = ap[8 * 132 + 4];
        }
        #pragma unroll
        for (int nt = 0; nt < 4; nt++) {
            const unsigned b0 = stageu[tig * 264 + wb + nt * 8 + g];
            const unsigned b1 = stageu[(tig + 4) * 264 + wb + nt * 8 + g];
            #pragma unroll
            for (int mt = 0; mt < 4; mt++) mma_bf16(d[mt][nt], a[mt], b0, b1);
        }
    }

    // epilogue: + bias (fp32), float2 stores
    #pragma unroll
    for (int nt = 0; nt < 4; nt++) {
        const int c0 = wb + nt * 8 + 2 * tig;
        const float bb0 = bv[c0], bb1 = bv[c0 + 1];
        #pragma unroll
        for (int mt = 0; mt < 4; mt++) {
            const int r = mt * 16 + g;
            *(float2*)(dst + (size_t)(m0 + r) * 256 + c0) =
                make_float2(d[mt][nt][0] + bb0, d[mt][nt][1] + bb1);
            *(float2*)(dst + (size_t)(m0 + r + 8) * 256 + c0) =
                make_float2(d[mt][nt][2] + bb0, d[mt][nt][3] + bb1);
        }
    }
}

// ============================================================================
// K3c fold: 2 patches/block, 512 threads, occupancy 2, BF16 TENSOR-CORE GEMMs.
// NEW vs round 12: FULL 256-k A in smem (no per-half rebuild) + 64-k weight
// slices -> barriers per block ~20 (was ~38). fold1c/2c + epilogue exact fp32.
// ============================================================================
__global__ __launch_bounds__(512, 2)
void fold_kernel(const float* __restrict__ grid_,
                 const float* __restrict__ Wf1a,
                 const float* __restrict__ Wf1b, const float* __restrict__ bf1b,
                 const float* __restrict__ Wf1c, const float* __restrict__ bf1c,
                 const float* __restrict__ Wf2a,
                 const float* __restrict__ Wf2b, const float* __restrict__ bf2b,
                 const float* __restrict__ Wf2c, const float* __restrict__ bf2c,
                 float* __restrict__ out)
{
    extern __shared__ float s[];
    unsigned* h1w    = (unsigned*)s;               // A: [64 r][132 w] = 8448 fl
    float* hf2       = s + 8448;                   // [64 r][132] f32 = 8448 fl
    unsigned* stageu = (unsigned*)(s + 16896);     // [32 k2][136]    = 4352 fl
    float* Wc1       = s + 21248;                  // [384]
    float* Wc2       = s + 21632;                  // [384]
    float* gx        = s + 22016;                  // [32]
    float* gy        = s + 22048;                  // [32]
    float* fv        = s + 22080;                  // [192]
    float* cm        = s + 22272;                  // [8] -> 22280 fl = 89120 B

    const int t = threadIdx.x;
    const int m0 = blockIdx.x * 2;
    const float scale = sqrtf(__uint_as_float(g_scale_bits));

    // A-build: k-pair kp = t&127 (covers all 256 k), rgrp = t>>7 (rows 16)
    const int kp   = t & 127;
    const int rgrp = t >> 7;
    const int pA   = rgrp >> 1;

    if (t < 384) { Wc1[t] = Wf1c[t]; Wc2[t] = Wf2c[t]; }
    if (t < 32) { gx[t] = grid_[2 * t]; gy[t] = grid_[2 * t + 1]; }
    if (t < 6)  cm[t] = g_cmean[(size_t)m0 * 3 + t];
    __syncthreads();

    const int lane = t & 31, g = lane >> 2, tig = lane & 3;
    const int wb = (t >> 5) * 8;               // warp's 8-column strip

    // staging: [32 k2][136]; thread -> sk2 = t>>4 (0..31), 8 cols
    const int sk2 = t >> 4;
    const int sc0 = (t & 15) * 8;

    #pragma unroll
    for (int stagei = 0; stagei < 2; stagei++) {
        const float* W  = stagei ? Wf2b : Wf1b;
        const float* bv = stagei ? bf2b : bf1b;

        float d[4][4];
        #pragma unroll
        for (int mt = 0; mt < 4; mt++)
            #pragma unroll
            for (int j = 0; j < 4; j++) d[mt][j] = 0.0f;

        // A build: all 256 k at once (packed bf16x2)
        {
            const int kg = 2 * kp;
            if (stagei == 0) {
                const float2 bb = *(const float2*)(g_base1 + (size_t)(m0 + pA) * 256 + kg);
                const float2 w0 = *(const float2*)(Wf1a + 256 * 256 + kg);
                const float2 w1 = *(const float2*)(Wf1a + 257 * 256 + kg);
                #pragma unroll
                for (int i = 0; i < 16; i++) {
                    const int r  = rgrp * 16 + i;
                    const int rr = r & 31;
                    const float v0 = fmaxf(bb.x + gx[rr] * w0.x + gy[rr] * w1.x, 0.0f);
                    const float v1 = fmaxf(bb.y + gx[rr] * w0.y + gy[rr] * w1.y, 0.0f);
                    h1w[r * 132 + kp] = pack_bf16x2(v0, v1);
                }
            } else {
                const float2 bb = *(const float2*)(g_base2 + (size_t)(m0 + pA) * 256 + kg);
                const float2 w0 = *(const float2*)(Wf2a + 256 * 256 + kg);
                const float2 w1 = *(const float2*)(Wf2a + 257 * 256 + kg);
                const float2 w2 = *(const float2*)(Wf2a + 258 * 256 + kg);
                #pragma unroll
                for (int i = 0; i < 16; i++) {
                    const int r = rgrp * 16 + i;
                    const float f0 = fv[r * 3], f1 = fv[r * 3 + 1], f2 = fv[r * 3 + 2];
                    const float v0 = fmaxf(bb.x + f0 * w0.x + f1 * w1.x + f2 * w2.x, 0.0f);
                    const float v1 = fmaxf(bb.y + f0 * w0.y + f1 * w1.y + f2 * w2.y, 0.0f);
                    h1w[r * 132 + kp] = pack_bf16x2(v0, v1);
                }
            }
        }

        // prefetch slice 0 (rows 2sk2, 2sk2+1; 8 cols)
        float4 pf[4];
        pf[0] = *(const float4*)(W + (2 * sk2) * 128 + sc0);
        pf[1] = *(const float4*)(W + (2 * sk2) * 128 + sc0 + 4);
        pf[2] = *(const float4*)(W + (2 * sk2 + 1) * 128 + sc0);
        pf[3] = *(const float4*)(W + (2 * sk2 + 1) * 128 + sc0 + 4);

        for (int gs = 0; gs < 4; gs++) {       // 4 slices of 64 k
            __syncthreads();                   // A ready (gs=0) / prev stage consumed
            {
                const float* pe = (const float*)&pf[0];   // pf[0..1] = even row
                const float* po = (const float*)&pf[2];   // pf[2..3] = odd row
                #pragma unroll
                for (int i = 0; i < 8; i++)
                    stageu[sk2 * 136 + sc0 + i] = pack_bf16x2(pe[i], po[i]);
            }
            __syncthreads();
            if (gs < 3) {
                const int kn = (gs + 1) * 64 + 2 * sk2;
                pf[0] = *(const float4*)(W + kn * 128 + sc0);
                pf[1] = *(const float4*)(W + kn * 128 + sc0 + 4);
                pf[2] = *(const float4*)(W + (kn + 1) * 128 + sc0);
                pf[3] = *(const float4*)(W + (kn + 1) * 128 + sc0 + 4);
            }
            #pragma unroll
            for (int ks2 = 0; ks2 < 4; ks2++) {   // 4 k16-steps per slice
                const unsigned b0 = stageu[(ks2 * 8 + tig) * 136 + wb + g];
                const unsigned b1 = stageu[(ks2 * 8 + tig + 4) * 136 + wb + g];
                #pragma unroll
                for (int mt = 0; mt < 4; mt++) {
                    const unsigned* ap = h1w + (mt * 16 + g) * 132 + gs * 32 + ks2 * 8 + tig;
                    unsigned a[4];
                    a[0] = ap[0];
                    a[1] = ap[8 * 132];
                    a[2] = ap[4];
                    a[3] = ap[8 * 132 + 4];
                    mma_bf16(d[mt], a, b0, b1);
                }
            }
        }

        // epilogue: bias + relu -> hf2[64 r][132]  (exact fp32)
        {
            const int col = wb + 2 * tig;
            const float bb0 = bv[col], bb1 = bv[col + 1];
            #pragma unroll
            for (int mt = 0; mt < 4; mt++) {
                const int r = mt * 16 + g;
                *(float2*)(hf2 + r * 132 + col) =
                    make_float2(fmaxf(d[mt][0] + bb0, 0.0f),
                                fmaxf(d[mt][1] + bb1, 0.0f));
                *(float2*)(hf2 + (r + 8) * 132 + col) =
                    make_float2(fmaxf(d[mt][2] + bb0, 0.0f),
                                fmaxf(d[mt][3] + bb1, 0.0f));
            }
        }
        __syncthreads();

        if (stagei == 0) {
            // fold1c: fv[r][q] = hf2[r]·Wf1c[:,q] + bf1c[q]  (exact fp32)
            if (t < 192) {
                const int r = t / 3, q = t - (t / 3) * 3;
                float acc = bf1c[q];
                #pragma unroll 8
                for (int k = 0; k < 128; k++) acc += hf2[r * 132 + k] * Wc1[k * 3 + q];
                fv[t] = acc;
            }
            __syncthreads();
        } else {
            // fold2c + output (exact fp32)
            if (t < 192) {
                const int r = t / 3, q = t - (t / 3) * 3;
                const int p = r >> 5, rr = r & 31;
                float acc = bf2c[q];
                #pragma unroll 8
                for (int k = 0; k < 128; k++) acc += hf2[r * 132 + k] * Wc2[k * 3 + q];
                out[(size_t)(m0 + p) * 96 + rr * 3 + q] = acc * scale + cm[p * 3 + q];
            }
        }
    }
}

// ============================================================================
extern "C" void kernel_launch(void* const* d_in, const int* in_sizes, int n_in,
                              void* d_out, int out_size)
{
    (void)in_sizes; (void)n_in; (void)out_size;
    const float* data = (const float*)d_in[0];
    const int*   perm = (const int*)  d_in[1];
    const float* grid = (const float*)d_in[2];
    const float* We1  = (const float*)d_in[3];
    const float* be1  = (const float*)d_in[4];
    const float* We2  = (const float*)d_in[5];
    const float* be2  = (const float*)d_in[6];
    const float* Wf1a = (const float*)d_in[7];
    const float* bf1a = (const float*)d_in[8];
    const float* Wf1b = (const float*)d_in[9];
    const float* bf1b = (const float*)d_in[10];
    const float* Wf1c = (const float*)d_in[11];
    const float* bf1c = (const float*)d_in[12];
    const float* Wf2a = (const float*)d_in[13];
    const float* bf2a = (const float*)d_in[14];
    const float* Wf2b = (const float*)d_in[15];
    const float* bf2b = (const float*)d_in[16];
    const float* Wf2c = (const float*)d_in[17];
    const float* bf2c = (const float*)d_in[18];
    float* out = (float*)d_out;

    const int fps_smem  = 3 * NN * sizeof(float);      // 98304
    const int knn_smem  = 3 * NN * sizeof(float);      // 98304
    const int enc_smem  = 6656  * sizeof(float);       // 26624
    const int base_smem = 10560 * sizeof(float);       // 42240
    const int fold_smem = 22280 * sizeof(float);       // 89120
    cudaFuncSetAttribute(fps_kernel,  cudaFuncAttributeMaxDynamicSharedMemorySize, fps_smem);
    cudaFuncSetAttribute(knn_kernel,  cudaFuncAttributeMaxDynamicSharedMemorySize, knn_smem);
    cudaFuncSetAttribute(enc_kernel,  cudaFuncAttributeMaxDynamicSharedMemorySize, enc_smem);
    cudaFuncSetAttribute(base_kernel, cudaFuncAttributeMaxDynamicSharedMemorySize, base_smem);
    cudaFuncSetAttribute(fold_kernel, cudaFuncAttributeMaxDynamicSharedMemorySize, fold_smem);

    fps_kernel <<<BB, 1024, fps_smem>>>(data);
    knn_kernel <<<(BB * NC) / 8, 256, knn_smem>>>(data, perm);
    enc_kernel <<<MTOT / 2, 256, enc_smem>>>(We1, be1, We2, be2);
    base_kernel<<<dim3(MTOT / 64, 2), 256, base_smem>>>(Wf1a, bf1a, Wf2a, bf2a);
    fold_kernel<<<MTOT / 2, 512, fold_smem>>>(grid, Wf1a, Wf1b, bf1b, Wf1c, bf1c,
                                              Wf2a, Wf2b, bf2b, Wf2c, bf2c, out);
}

// round 14
// speedup vs baseline: 2.8345x; 1.0515x over previous
#include <cuda_runtime.h>
#include <cuda_bf16.h>
#include <math.h>

#define BB 32
#define NN 8192
#define NC 256
#define NP 32
#define MTOT (BB * NC)          // 8192 patches

// ---------------- scratch (device globals; no allocation allowed) ----------
__device__ float    g_centers[BB * NC * 3];
__device__ float    g_local  [MTOT * NP * 3];
__device__ float    g_cmean  [MTOT * 3];
__device__ unsigned g_scale_bits;
__device__ float    g_codeT [256 * MTOT];      // code transposed [c][m]
__device__ float    g_base1 [MTOT * 256];      // [m][c]
__device__ float    g_base2 [MTOT * 256];      // [m][c]

// ---------------- bf16 mma helpers ------------------------------------------
// pack_bf16x2(lo, hi): lower 16 bits = bf16(lo) (smaller k), upper = bf16(hi)
__device__ __forceinline__ unsigned pack_bf16x2(float lo, float hi) {
    unsigned r;
    asm("cvt.rn.bf16x2.f32 %0, %1, %2;" : "=r"(r) : "f"(hi), "f"(lo));
    return r;
}
// mma.m16n8k16 bf16: A row-major 16x16 (4 .b32 of bf16x2), B col-major 16x8
// (2 .b32), D/C fp32 (4 regs).
__device__ __forceinline__ void mma_bf16(float* d, const unsigned* a,
                                         unsigned b0, unsigned b1) {
    asm volatile(
        "mma.sync.aligned.m16n8k16.row.col.f32.bf16.bf16.f32 "
        "{%0,%1,%2,%3}, {%4,%5,%6,%7}, {%8,%9}, {%0,%1,%2,%3};"
        : "+f"(d[0]), "+f"(d[1]), "+f"(d[2]), "+f"(d[3])
        : "r"(a[0]), "r"(a[1]), "r"(a[2]), "r"(a[3]), "r"(b0), "r"(b1));
}

// ============================================================================
// K1: FPS — round-12 shape (two-barrier warp0 reduce; the round-13 redundant
// all-warp reduce was part of a net regression). Exact jnp.argmax semantics.
// ============================================================================
__global__ __launch_bounds__(1024, 1)
void fps_kernel(const float* __restrict__ data)
{
    extern __shared__ float sm[];
    float* sx = sm;
    float* sy = sm + NN;
    float* sz = sm + 2 * NN;
    __shared__ unsigned long long skeys[32];
    __shared__ unsigned long long sres;

    const int b = blockIdx.x;
    const int t = threadIdx.x;
    const int wid = t >> 5, lane = t & 31;
    if (b == 0 && t == 0) g_scale_bits = 0u;   // reset every launch (graph replay safe)

    const float* dp = data + (size_t)b * 3 * NN;
    for (int n = t; n < NN; n += 1024) {
        sx[n] = dp[n];
        sy[n] = dp[NN + n];
        sz[n] = dp[2 * NN + n];
    }
    __syncthreads();

    float rx[8], ry[8], rz[8], md[8];
    const int base = t * 8;
    #pragma unroll
    for (int j = 0; j < 8; j++) {
        rx[j] = sx[base + j];
        ry[j] = sy[base + j];
        rz[j] = sz[base + j];
        md[j] = 3.4e38f;
    }

    float px = sx[0], py = sy[0], pz = sz[0];
    if (t == 0) {
        float* c = g_centers + (size_t)(b * NC) * 3;
        c[0] = px; c[1] = py; c[2] = pz;
    }

    for (int i = 1; i < NC; i++) {
        float bv = -1.0f; int bi = base;
        #pragma unroll
        for (int j = 0; j < 8; j++) {
            float dx = __fadd_rn(rx[j], -px);
            float dy = __fadd_rn(ry[j], -py);
            float dz = __fadd_rn(rz[j], -pz);
            float d  = __fadd_rn(__fadd_rn(__fmul_rn(dx, dx), __fmul_rn(dy, dy)),
                                 __fmul_rn(dz, dz));
            float m  = fminf(md[j], d);
            md[j] = m;
            if (m > bv) { bv = m; bi = base + j; }
        }
        unsigned long long key =
            ((unsigned long long)__float_as_uint(bv) << 32) | (unsigned)(NN - 1 - bi);
        #pragma unroll
        for (int off = 16; off; off >>= 1) {
            unsigned long long o = __shfl_down_sync(0xFFFFFFFFu, key, off);
            if (o > key) key = o;
        }
        if (lane == 0) skeys[wid] = key;
        __syncthreads();
        if (t < 32) {
            unsigned long long k2 = skeys[t];
            #pragma unroll
            for (int off = 16; off; off >>= 1) {
                unsigned long long o = __shfl_down_sync(0xFFFFFFFFu, k2, off);
                if (o > k2) k2 = o;
            }
            if (t == 0) sres = k2;
        }
        __syncthreads();
        const unsigned long long kk = sres;
        const int sel = NN - 1 - (int)(kk & 0xFFFFFFFFull);
        px = sx[sel]; py = sy[sel]; pz = sz[sel];
        if (t == 0) {
            float* c = g_centers + (size_t)(b * NC + i) * 3;
            c[0] = px; c[1] = py; c[2] = pz;
        }
    }
}

// ============================================================================
// K2: kNN set of 32 — one warp per center, 8 centers/block, points in smem.
// Sorted-insertion top-32 (lane 31 = current max); lax.top_k tie semantics.
// ============================================================================
__global__ __launch_bounds__(256, 2)
void knn_kernel(const float* __restrict__ data, const int* __restrict__ perm)
{
    extern __shared__ float sp[];                    // [3*NN]
    const int warp = threadIdx.x >> 5;
    const int lane = threadIdx.x & 31;
    const int w  = blockIdx.x * 8 + warp;
    const int b  = w >> 8;
    const int ci = w & 255;
    const int p  = perm[ci];

    const float* dp = data + (size_t)b * 3 * NN;
    for (int i = threadIdx.x; i < 3 * NN / 4; i += 256)
        ((float4*)sp)[i] = ((const float4*)dp)[i];
    __syncthreads();
    const float* sx = sp, *sy = sp + NN, *sz = sp + 2 * NN;

    const float* cc = g_centers + (size_t)(b * NC + p) * 3;
    const float cx = cc[0], cy = cc[1], cz = cc[2];
    const float cs = (cx * cx + cy * cy) + cz * cz;

    float kd = 3.4e38f;          // sorted ascending across lanes
    int   ki = -1;
    float cm = 3.4e38f;          // = kd at lane 31

    for (int bse = 0; bse < NN; bse += 32) {
        const int n = bse + lane;
        const float px = sx[n], py = sy[n], pz = sz[n];
        const float ps  = (px * px + py * py) + pz * pz;
        const float dot = (cx * px + cy * py) + cz * pz;
        const float d = (cs + ps) - 2.0f * dot;

        unsigned m = __ballot_sync(0xFFFFFFFFu, d < cm);
        while (m) {
            const int src = __ffs(m) - 1; m &= m - 1;
            const float dc = __shfl_sync(0xFFFFFFFFu, d, src);
            if (dc < cm) {                       // strict: equal-to-max never enters
                const int pos = __popc(__ballot_sync(0xFFFFFFFFu, kd <= dc));
                const float skd = __shfl_up_sync(0xFFFFFFFFu, kd, 1);
                const int   ski = __shfl_up_sync(0xFFFFFFFFu, ki, 1);
                if (lane > pos)       { kd = skd; ki = ski; }
                else if (lane == pos) { kd = dc;  ki = bse + src; }
                cm = __shfl_sync(0xFFFFFFFFu, kd, 31);
            }
        }
    }

    const float nx = sx[ki], ny = sy[ki], nz = sz[ki];
    float sxx = nx, syy = ny, szz = nz;
    #pragma unroll
    for (int off = 16; off; off >>= 1) {
        sxx += __shfl_xor_sync(0xFFFFFFFFu, sxx, off);
        syy += __shfl_xor_sync(0xFFFFFFFFu, syy, off);
        szz += __shfl_xor_sync(0xFFFFFFFFu, szz, off);
    }
    const float mx = sxx * (1.0f / 32.0f);
    const float my = syy * (1.0f / 32.0f);
    const float mz = szz * (1.0f / 32.0f);
    const float lx = nx - mx, ly = ny - my, lz = nz - mz;
    const float ns = (lx * lx + ly * ly) + lz * lz;
    float wm = ns;
    #pragma unroll
    for (int off = 16; off; off >>= 1) wm = fmaxf(wm, __shfl_xor_sync(0xFFFFFFFFu, wm, off));
    if (lane == 0) atomicMax(&g_scale_bits, __float_as_uint(wm));

    float* lp = g_local + ((size_t)w * NP + lane) * 3;
    lp[0] = lx; lp[1] = ly; lp[2] = lz;
    if (lane < 3) g_cmean[(size_t)w * 3 + lane] = (lane == 0) ? mx : ((lane == 1) ? my : mz);
}

// ============================================================================
// K3a enc: 2 patches/block (64 rows), BF16 TENSOR-CORE enc2 (m16n8k16.bf16).
// (round-12 version — passing)
// ============================================================================
__global__ __launch_bounds__(256, 2)
void enc_kernel(const float* __restrict__ We1, const float* __restrict__ be1,
                const float* __restrict__ We2, const float* __restrict__ be2)
{
    extern __shared__ float s[];
    __nv_bfloat16* h1A = (__nv_bfloat16*)s;        // [64][136] bf16 = 4352 fl
    unsigned* stageu   = (unsigned*)(s + 4352);    // [8 k2][264]    = 2112 fl
    float* xs          = s + 4352 + 2112;          // [64][3]        =  192 fl
                                                   // total 6656 fl = 26624 B
    const int t  = threadIdx.x;
    const int m0 = blockIdx.x * 2;
    const float scale = sqrtf(__uint_as_float(g_scale_bits));

    if (t < 192) xs[t] = g_local[(size_t)blockIdx.x * 192 + t] / scale;
    __syncthreads();

    // enc1 (exact fp32): thread handles k-pair (2kp, 2kp+1), rows rh,rh+4,...
    {
        const int kp = t & 63;          // k-pair index, k = 2kp, 2kp+1
        const int rh = t >> 6;          // 0..3
        const float2 w0 = *(const float2*)(We1 + 0 * 128 + 2 * kp);
        const float2 w1 = *(const float2*)(We1 + 1 * 128 + 2 * kp);
        const float2 w2 = *(const float2*)(We1 + 2 * 128 + 2 * kp);
        const float2 bb = *(const float2*)(be1 + 2 * kp);
        unsigned* h1w = (unsigned*)h1A;
        #pragma unroll
        for (int i = 0; i < 16; i++) {
            const int r = i * 4 + rh;
            const float x0 = xs[r * 3], x1 = xs[r * 3 + 1], x2 = xs[r * 3 + 2];
            const float v0 = fmaxf(x0 * w0.x + x1 * w1.x + x2 * w2.x + bb.x, 0.0f);
            const float v1 = fmaxf(x0 * w0.y + x1 * w1.y + x2 * w2.y + bb.y, 0.0f);
            h1w[r * 68 + kp] = pack_bf16x2(v0, v1);
        }
    }

    const int lane = t & 31, g = lane >> 2, tig = lane & 3;
    const int wb = (t >> 5) * 32;              // warp's 32-column strip

    const int sk2 = t >> 5;
    const int sc0 = (t & 31) * 4;

    float d[4][4][4];                          // [m-tile][n-tile][frag]
    #pragma unroll
    for (int mt = 0; mt < 4; mt++)
        #pragma unroll
        for (int nt = 0; nt < 4; nt++)
            #pragma unroll
            for (int j = 0; j < 4; j++) d[mt][nt][j] = 0.0f;

    float4 pf[4];
    pf[0] = *(const float4*)(We2 + (2 * sk2) * 256 + sc0);
    pf[1] = *(const float4*)(We2 + (2 * sk2 + 1) * 256 + sc0);
    pf[2] = *(const float4*)(We2 + (2 * sk2) * 256 + 128 + sc0);
    pf[3] = *(const float4*)(We2 + (2 * sk2 + 1) * 256 + 128 + sc0);

    for (int sl = 0; sl < 8; sl++) {           // 8 slices of 16 k (1 kstep each)
        __syncthreads();
        {
            const float* p0 = (const float*)&pf[0];
            const float* p1 = (const float*)&pf[1];
            const float* p2 = (const float*)&pf[2];
            const float* p3 = (const float*)&pf[3];
            #pragma unroll
            for (int i = 0; i < 4; i++) {
                stageu[sk2 * 264 + sc0 + i]       = pack_bf16x2(p0[i], p1[i]);
                stageu[sk2 * 264 + 128 + sc0 + i] = pack_bf16x2(p2[i], p3[i]);
            }
        }
        __syncthreads();
        if (sl < 7) {
            const int kg = (sl + 1) * 16 + 2 * sk2;
            pf[0] = *(const float4*)(We2 + kg * 256 + sc0);
            pf[1] = *(const float4*)(We2 + (kg + 1) * 256 + sc0);
            pf[2] = *(const float4*)(We2 + kg * 256 + 128 + sc0);
            pf[3] = *(const float4*)(We2 + (kg + 1) * 256 + 128 + sc0);
        }
        unsigned a[4][4];
        #pragma unroll
        for (int mt = 0; mt < 4; mt++) {
            const unsigned* ap = (const unsigned*)h1A + (mt * 16 + g) * 68 + sl * 8 + tig;
            a[mt][0] = ap[0];
            a[mt][1] = ap[8 * 68];
            a[mt][2] = ap[4];
            a[mt][3] = ap[8 * 68 + 4];
        }
        #pragma unroll
        for (int nt = 0; nt < 4; nt++) {
            const unsigned b0 = stageu[tig * 264 + wb + nt * 8 + g];
            const unsigned b1 = stageu[(tig + 4) * 264 + wb + nt * 8 + g];
            #pragma unroll
            for (int mt = 0; mt < 4; mt++) mma_bf16(d[mt][nt], a[mt], b0, b1);
        }
    }

    #pragma unroll
    for (int nt = 0; nt < 4; nt++) {
        const int c0 = wb + nt * 8 + 2 * tig;
        const float bb0 = be2[c0], bb1 = be2[c0 + 1];
        float p00 = fmaxf(fmaxf(fmaxf(d[0][nt][0], d[0][nt][2]),
                                fmaxf(d[1][nt][0], d[1][nt][2])) + bb0, 0.0f);
        float p01 = fmaxf(fmaxf(fmaxf(d[0][nt][1], d[0][nt][3]),
                                fmaxf(d[1][nt][1], d[1][nt][3])) + bb1, 0.0f);
        float p10 = fmaxf(fmaxf(fmaxf(d[2][nt][0], d[2][nt][2]),
                                fmaxf(d[3][nt][0], d[3][nt][2])) + bb0, 0.0f);
        float p11 = fmaxf(fmaxf(fmaxf(d[2][nt][1], d[2][nt][3]),
                                fmaxf(d[3][nt][1], d[3][nt][3])) + bb1, 0.0f);
        #pragma unroll
        for (int off = 4; off <= 16; off <<= 1) {
            p00 = fmaxf(p00, __shfl_xor_sync(0xFFFFFFFFu, p00, off));
            p01 = fmaxf(p01, __shfl_xor_sync(0xFFFFFFFFu, p01, off));
            p10 = fmaxf(p10, __shfl_xor_sync(0xFFFFFFFFu, p10, off));
            p11 = fmaxf(p11, __shfl_xor_sync(0xFFFFFFFFu, p11, off));
        }
        if (g == 0) {
            *(float2*)(g_codeT + (size_t)c0 * MTOT + m0)       = make_float2(p00, p10);
            *(float2*)(g_codeT + (size_t)(c0 + 1) * MTOT + m0) = make_float2(p01, p11);
        }
    }
}

// ============================================================================
// K3b base: BF16 TENSOR-CORE (m16n8k16) — round-13 version, MEASURED 20us
// (was 63 in fp32). A from g_codeT into bf16 words [64 m][132 w].
// ============================================================================
__global__ __launch_bounds__(256, 2)
void base_kernel(const float* __restrict__ Wf1a, const float* __restrict__ bf1a,
                 const float* __restrict__ Wf2a, const float* __restrict__ bf2a)
{
    extern __shared__ float s[];
    unsigned* cAw    = (unsigned*)s;            // [64 m][132 w] = 8448 fl
    unsigned* stageu = (unsigned*)(s + 8448);   // [8 k2][264]   = 2112 fl
                                                // total 10560 fl = 42240 B
    const int t  = threadIdx.x;
    const int m0 = blockIdx.x * 64;
    const int mat = blockIdx.y;
    const float* W  = mat ? Wf2a : Wf1a;
    const float* bv = mat ? bf2a : bf1a;
    float* dst = mat ? g_base2 : g_base1;

    // A build: thread -> mq = t&15 (4 m's), k2 = (t>>4) + 16*i
    {
        const int mq  = t & 15;
        const int k2g = t >> 4;
        #pragma unroll
        for (int i = 0; i < 8; i++) {
            const int k2 = k2g + 16 * i;
            const float4 a = *(const float4*)(g_codeT + (size_t)(2 * k2) * MTOT + m0 + 4 * mq);
            const float4 b = *(const float4*)(g_codeT + (size_t)(2 * k2 + 1) * MTOT + m0 + 4 * mq);
            cAw[(4 * mq + 0) * 132 + k2] = pack_bf16x2(a.x, b.x);
            cAw[(4 * mq + 1) * 132 + k2] = pack_bf16x2(a.y, b.y);
            cAw[(4 * mq + 2) * 132 + k2] = pack_bf16x2(a.z, b.z);
            cAw[(4 * mq + 3) * 132 + k2] = pack_bf16x2(a.w, b.w);
        }
    }

    const int lane = t & 31, g = lane >> 2, tig = lane & 3;
    const int wb = (t >> 5) * 32;              // warp's 32-column strip
    const int sk2 = t >> 5;
    const int sc0 = (t & 31) * 4;

    float d[4][4][4];
    #pragma unroll
    for (int mt = 0; mt < 4; mt++)
        #pragma unroll
        for (int nt = 0; nt < 4; nt++)
            #pragma unroll
            for (int j = 0; j < 4; j++) d[mt][nt][j] = 0.0f;

    float4 pf[4];
    pf[0] = *(const float4*)(W + (2 * sk2) * 256 + sc0);
    pf[1] = *(const float4*)(W + (2 * sk2 + 1) * 256 + sc0);
    pf[2] = *(const float4*)(W + (2 * sk2) * 256 + 128 + sc0);
    pf[3] = *(const float4*)(W + (2 * sk2 + 1) * 256 + 128 + sc0);

    for (int sl = 0; sl < 16; sl++) {          // 16 slices of 16 k
        __syncthreads();
        {
            const float* p0 = (const float*)&pf[0];
            const float* p1 = (const float*)&pf[1];
            const float* p2 = (const float*)&pf[2];
            const float* p3 = (const float*)&pf[3];
            #pragma unroll
            for (int i = 0; i < 4; i++) {
                stageu[sk2 * 264 + sc0 + i]       = pack_bf16x2(p0[i], p1[i]);
                stageu[sk2 * 264 + 128 + sc0 + i] = pack_bf16x2(p2[i], p3[i]);
            }
        }
        __syncthreads();
        if (sl < 15) {
            const int kg = (sl + 1) * 16 + 2 * sk2;
            pf[0] = *(const float4*)(W + kg * 256 + sc0);
            pf[1] = *(const float4*)(W + (kg + 1) * 256 + sc0);
            pf[2] = *(const float4*)(W + kg * 256 + 128 + sc0);
            pf[3] = *(const float4*)(W + (kg + 1) * 256 + 128 + sc0);
        }
        unsigned a[4][4];
        #pragma unroll
        for (int mt = 0; mt < 4; mt++) {
            const unsigned* ap = cAw + (mt * 16 + g) * 132 + sl * 8 + tig;
            a[mt][0] = ap[0];
            a[mt][1] = ap[8 * 132];
            a[mt][2] = ap[4];
            a[mt][3] = ap[8 * 132 + 4];
        }
        #pragma unroll
        for (int nt = 0; nt < 4; nt++) {
            const unsigned b0 = stageu[tig * 264 + wb + nt * 8 + g];
            const unsigned b1 = stageu[(tig + 4) * 264 + wb + nt * 8 + g];
            #pragma unroll
            for (int mt = 0; mt < 4; mt++) mma_bf16(d[mt][nt], a[mt], b0, b1);
        }
    }

    // epilogue: + bias (fp32), float2 stores
    #pragma unroll
    for (int nt = 0; nt < 4; nt++) {
        const int c0 = wb + nt * 8 + 2 * tig;
        const float bb0 = bv[c0], bb1 = bv[c0 + 1];
        #pragma unroll
        for (int mt = 0; mt < 4; mt++) {
            const int r = mt * 16 + g;
            *(float2*)(dst + (size_t)(m0 + r) * 256 + c0) =
                make_float2(d[mt][nt][0] + bb0, d[mt][nt][1] + bb1);
            *(float2*)(dst + (size_t)(m0 + r + 8) * 256 + c0) =
                make_float2(d[mt][nt][2] + bb0, d[mt][nt][3] + bb1);
        }
    }
}

// ============================================================================
// K3c fold: round-12 version (per-half A rebuild, 32-k slices, conflict-free
// 4-word staging) — the round-13 full-A/64k-slice restructure regressed.
// ============================================================================
__global__ __launch_bounds__(512, 2)
void fold_kernel(const float* __restrict__ grid_,
                 const float* __restrict__ Wf1a,
                 const float* __restrict__ Wf1b, const float* __restrict__ bf1b,
                 const float* __restrict__ Wf1c, const float* __restrict__ bf1c,
                 const float* __restrict__ Wf2a,
                 const float* __restrict__ Wf2b, const float* __restrict__ bf2b,
                 const float* __restrict__ Wf2c, const float* __restrict__ bf2c,
                 float* __restrict__ out)
{
    extern __shared__ float s[];
    __nv_bfloat16* hfA = (__nv_bfloat16*)s;        // [64][136] bf16 = 4352 fl
    float* hf2         = s + 4352;                 // [64 r][132] f32 = 8448 fl
    unsigned* stageu   = (unsigned*)(s + 12800);   // [16 k2][136]   = 2176 fl
    float* Wc1         = s + 14976;                // [384]
    float* Wc2         = s + 15360;                // [384]
    float* gx          = s + 15744;                // [32]
    float* gy          = s + 15776;                // [32]
    float* fv          = s + 15808;                // [192]
    float* cm          = s + 16000;                // [8]  -> 16008 fl = 64032 B

    const int t = threadIdx.x;
    const int m0 = blockIdx.x * 2;
    const float scale = sqrtf(__uint_as_float(g_scale_bits));

    const int kp   = t & 63;
    const int rgrp = t >> 6;
    const int pA   = rgrp >> 2;

    if (t < 384) { Wc1[t] = Wf1c[t]; Wc2[t] = Wf2c[t]; }
    if (t < 32) { gx[t] = grid_[2 * t]; gy[t] = grid_[2 * t + 1]; }
    if (t < 6)  cm[t] = g_cmean[(size_t)m0 * 3 + t];
    __syncthreads();

    const int lane = t & 31, g = lane >> 2, tig = lane & 3;
    const int wb = (t >> 5) * 8;               // warp's 8-column strip

    const int sk2 = t >> 5;                    // 0..15
    const int sc0 = (t & 31) * 4;

    unsigned* h1w = (unsigned*)hfA;            // word view, stride 68

    #pragma unroll
    for (int stagei = 0; stagei < 2; stagei++) {
        const float* W  = stagei ? Wf2b : Wf1b;
        const float* bv = stagei ? bf2b : bf1b;

        float d[4][4];
        #pragma unroll
        for (int mt = 0; mt < 4; mt++)
            #pragma unroll
            for (int j = 0; j < 4; j++) d[mt][j] = 0.0f;

        float4 pf0 = *(const float4*)(W + (2 * sk2) * 128 + sc0);
        float4 pf1 = *(const float4*)(W + (2 * sk2 + 1) * 128 + sc0);

        for (int gs = 0; gs < 8; gs++) {       // 8 slices of 32 k (2 halves x 4)
            if ((gs & 3) == 0) {
                const int h = gs >> 2;
                if (gs) __syncthreads();
                const int kg = h * 128 + 2 * kp;
                if (stagei == 0) {
                    const float2 bb = *(const float2*)(g_base1 + (size_t)(m0 + pA) * 256 + kg);
                    const float2 w0 = *(const float2*)(Wf1a + 256 * 256 + kg);
                    const float2 w1 = *(const float2*)(Wf1a + 257 * 256 + kg);
                    #pragma unroll
                    for (int i = 0; i < 8; i++) {
                        const int r  = rgrp * 8 + i;
                        const int rr = r & 31;
                        const float v0 = fmaxf(bb.x + gx[rr] * w0.x + gy[rr] * w1.x, 0.0f);
                        const float v1 = fmaxf(bb.y + gx[rr] * w0.y + gy[rr] * w1.y, 0.0f);
                        h1w[r * 68 + kp] = pack_bf16x2(v0, v1);
                    }
                } else {
                    const float2 bb = *(const float2*)(g_base2 + (size_t)(m0 + pA) * 256 + kg);
                    const float2 w0 = *(const float2*)(Wf2a + 256 * 256 + kg);
                    const float2 w1 = *(const float2*)(Wf2a + 257 * 256 + kg);
                    const float2 w2 = *(const float2*)(Wf2a + 258 * 256 + kg);
                    #pragma unroll
                    for (int i = 0; i < 8; i++) {
                        const int r = rgrp * 8 + i;
                        const float f0 = fv[r * 3], f1 = fv[r * 3 + 1], f2 = fv[r * 3 + 2];
                        const float v0 = fmaxf(bb.x + f0 * w0.x + f1 * w1.x + f2 * w2.x, 0.0f);
                        const float v1 = fmaxf(bb.y + f0 * w0.y + f1 * w1.y + f2 * w2.y, 0.0f);
                        h1w[r * 68 + kp] = pack_bf16x2(v0, v1);
                    }
                }
            }
            __syncthreads();                   // A ready / prev stage consumed
            {
                const float* p0 = (const float*)&pf0;
                const float* p1 = (const float*)&pf1;
                #pragma unroll
                for (int i = 0; i < 4; i++)
                    stageu[sk2 * 136 + sc0 + i] = pack_bf16x2(p0[i], p1[i]);
            }
            __syncthreads();
            if (gs < 7) {
                const int kgn = (gs + 1) * 32 + 2 * sk2;
                pf0 = *(const float4*)(W + kgn * 128 + sc0);
                pf1 = *(const float4*)(W + (kgn + 1) * 128 + sc0);
            }
            const int khw = (gs & 3) * 16;     // within-half k offset (words)
            #pragma unroll
            for (int ks2 = 0; ks2 < 2; ks2++) {   // 2 k16-steps per slice
                const unsigned b0 = stageu[(ks2 * 8 + tig) * 136 + wb + g];
                const unsigned b1 = stageu[(ks2 * 8 + tig + 4) * 136 + wb + g];
                #pragma unroll
                for (int mt = 0; mt < 4; mt++) {
                    const unsigned* ap = h1w + (mt * 16 + g) * 68 + khw + ks2 * 8 + tig;
                    unsigned a[4];
                    a[0] = ap[0];
                    a[1] = ap[8 * 68];
                    a[2] = ap[4];
                    a[3] = ap[8 * 68 + 4];
                    mma_bf16(d[mt], a, b0, b1);
                }
            }
        }

        // epilogue: bias + relu -> hf2[64 r][132]  (exact fp32)
        {
            const int col = wb + 2 * tig;
            const float bb0 = bv[col], bb1 = bv[col + 1];
            #pragma unroll
            for (int mt = 0; mt < 4; mt++) {
                const int r = mt * 16 + g;
                *(float2*)(hf2 + r * 132 + col) =
                    make_float2(fmaxf(d[mt][0] + bb0, 0.0f),
                                fmaxf(d[mt][1] + bb1, 0.0f));
                *(float2*)(hf2 + (r + 8) * 132 + col) =
                    make_float2(fmaxf(d[mt][2] + bb0, 0.0f),
                                fmaxf(d[mt][3] + bb1, 0.0f));
            }
        }
        __syncthreads();

        if (stagei == 0) {
            // fold1c: fv[r][q] = hf2[r]·Wf1c[:,q] + bf1c[q]  (exact fp32)
            if (t < 192) {
                const int r = t / 3, q = t - (t / 3) * 3;
                float acc = bf1c[q];
                #pragma unroll 8
                for (int k = 0; k < 128; k++) acc += hf2[r * 132 + k] * Wc1[k * 3 + q];
                fv[t] = acc;
            }
            __syncthreads();
        } else {
            // fold2c + output (exact fp32)
            if (t < 192) {
                const int r = t / 3, q = t - (t / 3) * 3;
                const int p = r >> 5, rr = r & 31;
                float acc = bf2c[q];
                #pragma unroll 8
                for (int k = 0; k < 128; k++) acc += hf2[r * 132 + k] * Wc2[k * 3 + q];
                out[(size_t)(m0 + p) * 96 + rr * 3 + q] = acc * scale + cm[p * 3 + q];
            }
        }
    }
}

// ============================================================================
extern "C" void kernel_launch(void* const* d_in, const int* in_sizes, int n_in,
                              void* d_out, int out_size)
{
    (void)in_sizes; (void)n_in; (void)out_size;
    const float* data = (const float*)d_in[0];
    const int*   perm = (const int*)  d_in[1];
    const float* grid = (const float*)d_in[2];
    const float* We1  = (const float*)d_in[3];
    const float* be1  = (const float*)d_in[4];
    const float* We2  = (const float*)d_in[5];
    const float* be2  = (const float*)d_in[6];
    const float* Wf1a = (const float*)d_in[7];
    const float* bf1a = (const float*)d_in[8];
    const float* Wf1b = (const float*)d_in[9];
    const float* bf1b = (const float*)d_in[10];
    const float* Wf1c = (const float*)d_in[11];
    const float* bf1c = (const float*)d_in[12];
    const float* Wf2a = (const float*)d_in[13];
    const float* bf2a = (const float*)d_in[14];
    const float* Wf2b = (const float*)d_in[15];
    const float* bf2b = (const float*)d_in[16];
    const float* Wf2c = (const float*)d_in[17];
    const float* bf2c = (const float*)d_in[18];
    float* out = (float*)d_out;

    const int fps_smem  = 3 * NN * sizeof(float);      // 98304
    const int knn_smem  = 3 * NN * sizeof(float);      // 98304
    const int enc_smem  = 6656  * sizeof(float);       // 26624
    const int base_smem = 10560 * sizeof(float);       // 42240
    const int fold_smem = 16008 * sizeof(float);       // 64032
    cudaFuncSetAttribute(fps_kernel,  cudaFuncAttributeMaxDynamicSharedMemorySize, fps_smem);
    cudaFuncSetAttribute(knn_kernel,  cudaFuncAttributeMaxDynamicSharedMemorySize, knn_smem);
    cudaFuncSetAttribute(enc_kernel,  cudaFuncAttributeMaxDynamicSharedMemorySize, enc_smem);
    cudaFuncSetAttribute(base_kernel, cudaFuncAttributeMaxDynamicSharedMemorySize, base_smem);
    cudaFuncSetAttribute(fold_kernel, cudaFuncAttributeMaxDynamicSharedMemorySize, fold_smem);

    fps_kernel <<<BB, 1024, fps_smem>>>(data);
    knn_kernel <<<(BB * NC) / 8, 256, knn_smem>>>(data, perm);
    enc_kernel <<<MTOT / 2, 256, enc_smem>>>(We1, be1, We2, be2);
    base_kernel<<<dim3(MTOT / 64, 2), 256, base_smem>>>(Wf1a, bf1a, Wf2a, bf2a);
    fold_kernel<<<MTOT / 2, 512, fold_smem>>>(grid, Wf1a, Wf1b, bf1b, Wf1c, bf1c,
                                              Wf2a, Wf2b, bf2b, Wf2c, bf2c, out);
}

// round 15
// speedup vs baseline: 2.9659x; 1.0464x over previous
#include <cuda_runtime.h>
#include <cuda_bf16.h>
#include <math.h>

#define BB 32
#define NN 8192
#define NC 256
#define NP 32
#define MTOT (BB * NC)          // 8192 patches

// ---------------- scratch (device globals; no allocation allowed) ----------
__device__ float    g_centers[BB * NC * 3];
__device__ float    g_local  [MTOT * NP * 3];
__device__ float    g_cmean  [MTOT * 3];
__device__ unsigned g_scale_bits;
__device__ float    g_codeT [256 * MTOT];      // code transposed [c][m]
__device__ float    g_base1 [MTOT * 256];      // [m][c]
__device__ float    g_base2 [MTOT * 256];      // [m][c]
// pre-packed bf16x2 weights (word = (bf16(W[2k2][n]), bf16(W[2k2+1][n])))
__device__ unsigned g_We2p[64 * 256];          // We2  [128k][256n]
__device__ unsigned g_W1ap[128 * 256];         // Wf1a [256k][256n] (rows 0..255)
__device__ unsigned g_W2ap[128 * 256];         // Wf2a [256k][256n] (rows 0..255)
__device__ unsigned g_W1bp[128 * 128];         // Wf1b [256k][128n]
__device__ unsigned g_W2bp[128 * 128];         // Wf2b [256k][128n]

// ---------------- bf16 mma helpers ------------------------------------------
// pack_bf16x2(lo, hi): lower 16 bits = bf16(lo) (smaller k), upper = bf16(hi)
__device__ __forceinline__ unsigned pack_bf16x2(float lo, float hi) {
    unsigned r;
    asm("cvt.rn.bf16x2.f32 %0, %1, %2;" : "=r"(r) : "f"(hi), "f"(lo));
    return r;
}
__device__ __forceinline__ void mma_bf16(float* d, const unsigned* a,
                                         unsigned b0, unsigned b1) {
    asm volatile(
        "mma.sync.aligned.m16n8k16.row.col.f32.bf16.bf16.f32 "
        "{%0,%1,%2,%3}, {%4,%5,%6,%7}, {%8,%9}, {%0,%1,%2,%3};"
        : "+f"(d[0]), "+f"(d[1]), "+f"(d[2]), "+f"(d[3])
        : "r"(a[0]), "r"(a[1]), "r"(a[2]), "r"(a[3]), "r"(b0), "r"(b1));
}

// ============================================================================
// K0: pre-pack MMA weights to bf16x2 word layout (once per launch, ~5us).
// ============================================================================
__global__ __launch_bounds__(256)
void pack_kernel(const float* __restrict__ We2,
                 const float* __restrict__ Wf1a, const float* __restrict__ Wf2a,
                 const float* __restrict__ Wf1b, const float* __restrict__ Wf2b)
{
    const int t = blockIdx.x * 256 + threadIdx.x;
    const float* src; unsigned* dst; int k2n, n;
    switch (blockIdx.y) {
        case 0:  src = We2;  dst = g_We2p; k2n = 64;  n = 256; break;
        case 1:  src = Wf1a; dst = g_W1ap; k2n = 128; n = 256; break;
        case 2:  src = Wf2a; dst = g_W2ap; k2n = 128; n = 256; break;
        case 3:  src = Wf1b; dst = g_W1bp; k2n = 128; n = 128; break;
        default: src = Wf2b; dst = g_W2bp; k2n = 128; n = 128; break;
    }
    if (t < k2n * n) {
        const int k2 = t / n, j = t - k2 * n;
        dst[t] = pack_bf16x2(src[(2 * k2) * n + j], src[(2 * k2 + 1) * n + j]);
    }
}

// ============================================================================
// K1: FPS — round-14 proven shape. Exact jnp.argmax semantics; distance
// arithmetic replicates the reference exactly (no FMA contraction).
// ============================================================================
__global__ __launch_bounds__(1024, 1)
void fps_kernel(const float* __restrict__ data)
{
    extern __shared__ float sm[];
    float* sx = sm;
    float* sy = sm + NN;
    float* sz = sm + 2 * NN;
    __shared__ unsigned long long skeys[32];
    __shared__ unsigned long long sres;

    const int b = blockIdx.x;
    const int t = threadIdx.x;
    const int wid = t >> 5, lane = t & 31;
    if (b == 0 && t == 0) g_scale_bits = 0u;   // reset every launch (graph replay safe)

    const float* dp = data + (size_t)b * 3 * NN;
    for (int n = t; n < NN; n += 1024) {
        sx[n] = dp[n];
        sy[n] = dp[NN + n];
        sz[n] = dp[2 * NN + n];
    }
    __syncthreads();

    float rx[8], ry[8], rz[8], md[8];
    const int base = t * 8;
    #pragma unroll
    for (int j = 0; j < 8; j++) {
        rx[j] = sx[base + j];
        ry[j] = sy[base + j];
        rz[j] = sz[base + j];
        md[j] = 3.4e38f;
    }

    float px = sx[0], py = sy[0], pz = sz[0];
    if (t == 0) {
        float* c = g_centers + (size_t)(b * NC) * 3;
        c[0] = px; c[1] = py; c[2] = pz;
    }

    for (int i = 1; i < NC; i++) {
        float bv = -1.0f; int bi = base;
        #pragma unroll
        for (int j = 0; j < 8; j++) {
            float dx = __fadd_rn(rx[j], -px);
            float dy = __fadd_rn(ry[j], -py);
            float dz = __fadd_rn(rz[j], -pz);
            float d  = __fadd_rn(__fadd_rn(__fmul_rn(dx, dx), __fmul_rn(dy, dy)),
                                 __fmul_rn(dz, dz));
            float m  = fminf(md[j], d);
            md[j] = m;
            if (m > bv) { bv = m; bi = base + j; }
        }
        unsigned long long key =
            ((unsigned long long)__float_as_uint(bv) << 32) | (unsigned)(NN - 1 - bi);
        #pragma unroll
        for (int off = 16; off; off >>= 1) {
            unsigned long long o = __shfl_down_sync(0xFFFFFFFFu, key, off);
            if (o > key) key = o;
        }
        if (lane == 0) skeys[wid] = key;
        __syncthreads();
        if (t < 32) {
            unsigned long long k2 = skeys[t];
            #pragma unroll
            for (int off = 16; off; off >>= 1) {
                unsigned long long o = __shfl_down_sync(0xFFFFFFFFu, k2, off);
                if (o > k2) k2 = o;
            }
            if (t == 0) sres = k2;
        }
        __syncthreads();
        const unsigned long long kk = sres;
        const int sel = NN - 1 - (int)(kk & 0xFFFFFFFFull);
        px = sx[sel]; py = sy[sel]; pz = sz[sel];
        if (t == 0) {
            float* c = g_centers + (size_t)(b * NC + i) * 3;
            c[0] = px; c[1] = py; c[2] = pz;
        }
    }
}

// ============================================================================
// K2: kNN set of 32 — one warp per center, 8 centers/block, points in smem.
// Sorted-insertion top-32; lax.top_k tie semantics. (round-14 proven)
// ============================================================================
__global__ __launch_bounds__(256, 2)
void knn_kernel(const float* __restrict__ data, const int* __restrict__ perm)
{
    extern __shared__ float sp[];                    // [3*NN]
    const int warp = threadIdx.x >> 5;
    const int lane = threadIdx.x & 31;
    const int w  = blockIdx.x * 8 + warp;
    const int b  = w >> 8;
    const int ci = w & 255;
    const int p  = perm[ci];

    const float* dp = data + (size_t)b * 3 * NN;
    for (int i = threadIdx.x; i < 3 * NN / 4; i += 256)
        ((float4*)sp)[i] = ((const float4*)dp)[i];
    __syncthreads();
    const float* sx = sp, *sy = sp + NN, *sz = sp + 2 * NN;

    const float* cc = g_centers + (size_t)(b * NC + p) * 3;
    const float cx = cc[0], cy = cc[1], cz = cc[2];
    const float cs = (cx * cx + cy * cy) + cz * cz;

    float kd = 3.4e38f;          // sorted ascending across lanes
    int   ki = -1;
    float cm = 3.4e38f;          // = kd at lane 31

    for (int bse = 0; bse < NN; bse += 32) {
        const int n = bse + lane;
        const float px = sx[n], py = sy[n], pz = sz[n];
        const float ps  = (px * px + py * py) + pz * pz;
        const float dot = (cx * px + cy * py) + cz * pz;
        const float d = (cs + ps) - 2.0f * dot;

        unsigned m = __ballot_sync(0xFFFFFFFFu, d < cm);
        while (m) {
            const int src = __ffs(m) - 1; m &= m - 1;
            const float dc = __shfl_sync(0xFFFFFFFFu, d, src);
            if (dc < cm) {                       // strict: equal-to-max never enters
                const int pos = __popc(__ballot_sync(0xFFFFFFFFu, kd <= dc));
                const float skd = __shfl_up_sync(0xFFFFFFFFu, kd, 1);
                const int   ski = __shfl_up_sync(0xFFFFFFFFu, ki, 1);
                if (lane > pos)       { kd = skd; ki = ski; }
                else if (lane == pos) { kd = dc;  ki = bse + src; }
                cm = __shfl_sync(0xFFFFFFFFu, kd, 31);
            }
        }
    }

    const float nx = sx[ki], ny = sy[ki], nz = sz[ki];
    float sxx = nx, syy = ny, szz = nz;
    #pragma unroll
    for (int off = 16; off; off >>= 1) {
        sxx += __shfl_xor_sync(0xFFFFFFFFu, sxx, off);
        syy += __shfl_xor_sync(0xFFFFFFFFu, syy, off);
        szz += __shfl_xor_sync(0xFFFFFFFFu, szz, off);
    }
    const float mx = sxx * (1.0f / 32.0f);
    const float my = syy * (1.0f / 32.0f);
    const float mz = szz * (1.0f / 32.0f);
    const float lx = nx - mx, ly = ny - my, lz = nz - mz;
    const float ns = (lx * lx + ly * ly) + lz * lz;
    float wm = ns;
    #pragma unroll
    for (int off = 16; off; off >>= 1) wm = fmaxf(wm, __shfl_xor_sync(0xFFFFFFFFu, wm, off));
    if (lane == 0) atomicMax(&g_scale_bits, __float_as_uint(wm));

    float* lp = g_local + ((size_t)w * NP + lane) * 3;
    lp[0] = lx; lp[1] = ly; lp[2] = lz;
    if (lane < 3) g_cmean[(size_t)w * 3 + lane] = (lane == 0) ? mx : ((lane == 1) ? my : mz);
}

// ============================================================================
// K3a enc: 2 patches/block, bf16 MMA, B-fragments loaded DIRECTLY from
// pre-packed global words (no staging, no staging barriers, no packs).
// ============================================================================
__global__ __launch_bounds__(256, 2)
void enc_kernel(const float* __restrict__ We1, const float* __restrict__ be1,
                const float* __restrict__ be2)
{
    extern __shared__ float s[];
    __nv_bfloat16* h1A = (__nv_bfloat16*)s;        // [64][136] bf16 = 4352 fl
    float* xs          = s + 4352;                 // [64][3]        =  192 fl
                                                   // total 4544 fl = 18176 B
    const int t  = threadIdx.x;
    const int m0 = blockIdx.x * 2;
    const float scale = sqrtf(__uint_as_float(g_scale_bits));

    if (t < 192) xs[t] = g_local[(size_t)blockIdx.x * 192 + t] / scale;
    __syncthreads();

    // enc1 (exact fp32): thread handles k-pair (2kp, 2kp+1), rows rh,rh+4,...
    {
        const int kp = t & 63;
        const int rh = t >> 6;
        const float2 w0 = *(const float2*)(We1 + 0 * 128 + 2 * kp);
        const float2 w1 = *(const float2*)(We1 + 1 * 128 + 2 * kp);
        const float2 w2 = *(const float2*)(We1 + 2 * 128 + 2 * kp);
        const float2 bb = *(const float2*)(be1 + 2 * kp);
        unsigned* h1w = (unsigned*)h1A;
        #pragma unroll
        for (int i = 0; i < 16; i++) {
            const int r = i * 4 + rh;
            const float x0 = xs[r * 3], x1 = xs[r * 3 + 1], x2 = xs[r * 3 + 2];
            const float v0 = fmaxf(x0 * w0.x + x1 * w1.x + x2 * w2.x + bb.x, 0.0f);
            const float v1 = fmaxf(x0 * w0.y + x1 * w1.y + x2 * w2.y + bb.y, 0.0f);
            h1w[r * 68 + kp] = pack_bf16x2(v0, v1);
        }
    }
    __syncthreads();

    const int lane = t & 31, g = lane >> 2, tig = lane & 3;
    const int wb = (t >> 5) * 32;              // warp's 32-column strip

    float d[4][4][4];
    #pragma unroll
    for (int mt = 0; mt < 4; mt++)
        #pragma unroll
        for (int nt = 0; nt < 4; nt++)
            #pragma unroll
            for (int j = 0; j < 4; j++) d[mt][nt][j] = 0.0f;

    #pragma unroll 2
    for (int sl = 0; sl < 8; sl++) {           // 8 k16-steps, B direct from L2
        unsigned a[4][4];
        #pragma unroll
        for (int mt = 0; mt < 4; mt++) {
            const unsigned* ap = (const unsigned*)h1A + (mt * 16 + g) * 68 + sl * 8 + tig;
            a[mt][0] = ap[0];
            a[mt][1] = ap[8 * 68];
            a[mt][2] = ap[4];
            a[mt][3] = ap[8 * 68 + 4];
        }
        #pragma unroll
        for (int nt = 0; nt < 4; nt++) {
            const unsigned b0 = g_We2p[(sl * 8 + tig) * 256 + wb + nt * 8 + g];
            const unsigned b1 = g_We2p[(sl * 8 + tig + 4) * 256 + wb + nt * 8 + g];
            #pragma unroll
            for (int mt = 0; mt < 4; mt++) mma_bf16(d[mt][nt], a[mt], b0, b1);
        }
    }

    // epilogue: bias + relu (fp32), maxpool, shfl over g, transposed write
    #pragma unroll
    for (int nt = 0; nt < 4; nt++) {
        const int c0 = wb + nt * 8 + 2 * tig;
        const float bb0 = be2[c0], bb1 = be2[c0 + 1];
        float p00 = fmaxf(fmaxf(fmaxf(d[0][nt][0], d[0][nt][2]),
                                fmaxf(d[1][nt][0], d[1][nt][2])) + bb0, 0.0f);
        float p01 = fmaxf(fmaxf(fmaxf(d[0][nt][1], d[0][nt][3]),
                                fmaxf(d[1][nt][1], d[1][nt][3])) + bb1, 0.0f);
        float p10 = fmaxf(fmaxf(fmaxf(d[2][nt][0], d[2][nt][2]),
                                fmaxf(d[3][nt][0], d[3][nt][2])) + bb0, 0.0f);
        float p11 = fmaxf(fmaxf(fmaxf(d[2][nt][1], d[2][nt][3]),
                                fmaxf(d[3][nt][1], d[3][nt][3])) + bb1, 0.0f);
        #pragma unroll
        for (int off = 4; off <= 16; off <<= 1) {
            p00 = fmaxf(p00, __shfl_xor_sync(0xFFFFFFFFu, p00, off));
            p01 = fmaxf(p01, __shfl_xor_sync(0xFFFFFFFFu, p01, off));
            p10 = fmaxf(p10, __shfl_xor_sync(0xFFFFFFFFu, p10, off));
            p11 = fmaxf(p11, __shfl_xor_sync(0xFFFFFFFFu, p11, off));
        }
        if (g == 0) {
            *(float2*)(g_codeT + (size_t)c0 * MTOT + m0)       = make_float2(p00, p10);
            *(float2*)(g_codeT + (size_t)(c0 + 1) * MTOT + m0) = make_float2(p01, p11);
        }
    }
}

// ============================================================================
// K3b base: bf16 MMA, B direct from pre-packed global (no staging).
// ============================================================================
__global__ __launch_bounds__(256, 2)
void base_kernel(const float* __restrict__ bf1a, const float* __restrict__ bf2a)
{
    extern __shared__ float s[];
    unsigned* cAw = (unsigned*)s;               // [64 m][132 w] = 8448 fl

    const int t  = threadIdx.x;
    const int m0 = blockIdx.x * 64;
    const int mat = blockIdx.y;
    const unsigned* Wp = mat ? g_W2ap : g_W1ap;
    const float* bv = mat ? bf2a : bf1a;
    float* dst = mat ? g_base2 : g_base1;

    // A build from codeT (packed bf16x2 words, stride 132)
    {
        const int mq  = t & 15;
        const int k2g = t >> 4;
        #pragma unroll
        for (int i = 0; i < 8; i++) {
            const int k2 = k2g + 16 * i;
            const float4 a = *(const float4*)(g_codeT + (size_t)(2 * k2) * MTOT + m0 + 4 * mq);
            const float4 b = *(const float4*)(g_codeT + (size_t)(2 * k2 + 1) * MTOT + m0 + 4 * mq);
            cAw[(4 * mq + 0) * 132 + k2] = pack_bf16x2(a.x, b.x);
            cAw[(4 * mq + 1) * 132 + k2] = pack_bf16x2(a.y, b.y);
            cAw[(4 * mq + 2) * 132 + k2] = pack_bf16x2(a.z, b.z);
            cAw[(4 * mq + 3) * 132 + k2] = pack_bf16x2(a.w, b.w);
        }
    }
    __syncthreads();

    const int lane = t & 31, g = lane >> 2, tig = lane & 3;
    const int wb = (t >> 5) * 32;

    float d[4][4][4];
    #pragma unroll
    for (int mt = 0; mt < 4; mt++)
        #pragma unroll
        for (int nt = 0; nt < 4; nt++)
            #pragma unroll
            for (int j = 0; j < 4; j++) d[mt][nt][j] = 0.0f;

    #pragma unroll 2
    for (int sl = 0; sl < 16; sl++) {          // 16 k16-steps, B direct
        unsigned a[4][4];
        #pragma unroll
        for (int mt = 0; mt < 4; mt++) {
            const unsigned* ap = cAw + (mt * 16 + g) * 132 + sl * 8 + tig;
            a[mt][0] = ap[0];
            a[mt][1] = ap[8 * 132];
            a[mt][2] = ap[4];
            a[mt][3] = ap[8 * 132 + 4];
        }
        #pragma unroll
        for (int nt = 0; nt < 4; nt++) {
            const unsigned b0 = Wp[(sl * 8 + tig) * 256 + wb + nt * 8 + g];
            const unsigned b1 = Wp[(sl * 8 + tig + 4) * 256 + wb + nt * 8 + g];
            #pragma unroll
            for (int mt = 0; mt < 4; mt++) mma_bf16(d[mt][nt], a[mt], b0, b1);
        }
    }

    #pragma unroll
    for (int nt = 0; nt < 4; nt++) {
        const int c0 = wb + nt * 8 + 2 * tig;
        const float bb0 = bv[c0], bb1 = bv[c0 + 1];
        #pragma unroll
        for (int mt = 0; mt < 4; mt++) {
            const int r = mt * 16 + g;
            *(float2*)(dst + (size_t)(m0 + r) * 256 + c0) =
                make_float2(d[mt][nt][0] + bb0, d[mt][nt][1] + bb1);
            *(float2*)(dst + (size_t)(m0 + r + 8) * 256 + c0) =
                make_float2(d[mt][nt][2] + bb0, d[mt][nt][3] + bb1);
        }
    }
}

// ============================================================================
// K3c fold: 2 patches/block, 512 threads, occ 2, bf16 MMA with B direct from
// pre-packed global — staging + its barriers removed (~10 barriers/block).
// A per-half rebuild kept (r12-proven). fold1c/2c + epilogue exact fp32.
// ============================================================================
__global__ __launch_bounds__(512, 2)
void fold_kernel(const float* __restrict__ grid_,
                 const float* __restrict__ Wf1a,
                 const float* __restrict__ bf1b,
                 const float* __restrict__ Wf1c, const float* __restrict__ bf1c,
                 const float* __restrict__ Wf2a,
                 const float* __restrict__ bf2b,
                 const float* __restrict__ Wf2c, const float* __restrict__ bf2c,
                 float* __restrict__ out)
{
    extern __shared__ float s[];
    __nv_bfloat16* hfA = (__nv_bfloat16*)s;        // [64][136] bf16 = 4352 fl
    float* hf2         = s + 4352;                 // [64 r][132] f32 = 8448 fl
    float* Wc1         = s + 12800;                // [384]
    float* Wc2         = s + 13184;                // [384]
    float* gx          = s + 13568;                // [32]
    float* gy          = s + 13600;                // [32]
    float* fv          = s + 13632;                // [192]
    float* cm          = s + 13824;                // [8] -> 13832 fl = 55328 B

    const int t = threadIdx.x;
    const int m0 = blockIdx.x * 2;
    const float scale = sqrtf(__uint_as_float(g_scale_bits));

    const int kp   = t & 63;       // k-pair within half
    const int rgrp = t >> 6;       // rows rgrp*8..+7
    const int pA   = rgrp >> 2;    // patch

    if (t < 384) { Wc1[t] = Wf1c[t]; Wc2[t] = Wf2c[t]; }
    if (t < 32) { gx[t] = grid_[2 * t]; gy[t] = grid_[2 * t + 1]; }
    if (t < 6)  cm[t] = g_cmean[(size_t)m0 * 3 + t];
    __syncthreads();

    const int lane = t & 31, g = lane >> 2, tig = lane & 3;
    const int wb = (t >> 5) * 8;               // warp's 8-column strip

    unsigned* h1w = (unsigned*)hfA;            // word view, stride 68

    #pragma unroll
    for (int stagei = 0; stagei < 2; stagei++) {
        const unsigned* Wp = stagei ? g_W2bp : g_W1bp;
        const float* bv = stagei ? bf2b : bf1b;

        float d[4][4];
        #pragma unroll
        for (int mt = 0; mt < 4; mt++)
            #pragma unroll
            for (int j = 0; j < 4; j++) d[mt][j] = 0.0f;

        #pragma unroll
        for (int h = 0; h < 2; h++) {
            // rebuild A for half h (packed bf16x2 stores)
            if (h) __syncthreads();            // prior half's MMA reads done
            {
                const int kg = h * 128 + 2 * kp;
                if (stagei == 0) {
                    const float2 bb = *(const float2*)(g_base1 + (size_t)(m0 + pA) * 256 + kg);
                    const float2 w0 = *(const float2*)(Wf1a + 256 * 256 + kg);
                    const float2 w1 = *(const float2*)(Wf1a + 257 * 256 + kg);
                    #pragma unroll
                    for (int i = 0; i < 8; i++) {
                        const int r  = rgrp * 8 + i;
                        const int rr = r & 31;
                        const float v0 = fmaxf(bb.x + gx[rr] * w0.x + gy[rr] * w1.x, 0.0f);
                        const float v1 = fmaxf(bb.y + gx[rr] * w0.y + gy[rr] * w1.y, 0.0f);
                        h1w[r * 68 + kp] = pack_bf16x2(v0, v1);
                    }
                } else {
                    const float2 bb = *(const float2*)(g_base2 + (size_t)(m0 + pA) * 256 + kg);
                    const float2 w0 = *(const float2*)(Wf2a + 256 * 256 + kg);
                    const float2 w1 = *(const float2*)(Wf2a + 257 * 256 + kg);
                    const float2 w2 = *(const float2*)(Wf2a + 258 * 256 + kg);
                    #pragma unroll
                    for (int i = 0; i < 8; i++) {
                        const int r = rgrp * 8 + i;
                        const float f0 = fv[r * 3], f1 = fv[r * 3 + 1], f2 = fv[r * 3 + 2];
                        const float v0 = fmaxf(bb.x + f0 * w0.x + f1 * w1.x + f2 * w2.x, 0.0f);
                        const float v1 = fmaxf(bb.y + f0 * w0.y + f1 * w1.y + f2 * w2.y, 0.0f);
                        h1w[r * 68 + kp] = pack_bf16x2(v0, v1);
                    }
                }
            }
            __syncthreads();                   // A ready

            // 8 k16-steps over this half; B direct from L2 (no barriers)
            #pragma unroll 2
            for (int ks = 0; ks < 8; ks++) {
                const int k2r = h * 64 + ks * 8;       // global k2 row base
                const unsigned b0 = Wp[(k2r + tig) * 128 + wb + g];
                const unsigned b1 = Wp[(k2r + tig + 4) * 128 + wb + g];
                #pragma unroll
                for (int mt = 0; mt < 4; mt++) {
                    const unsigned* ap = h1w + (mt * 16 + g) * 68 + ks * 8 + tig;
                    unsigned a[4];
                    a[0] = ap[0];
                    a[1] = ap[8 * 68];
                    a[2] = ap[4];
                    a[3] = ap[8 * 68 + 4];
                    mma_bf16(d[mt], a, b0, b1);
                }
            }
        }

        // epilogue: bias + relu -> hf2[64 r][132]  (exact fp32)
        {
            const int col = wb + 2 * tig;
            const float bb0 = bv[col], bb1 = bv[col + 1];
            #pragma unroll
            for (int mt = 0; mt < 4; mt++) {
                const int r = mt * 16 + g;
                *(float2*)(hf2 + r * 132 + col) =
                    make_float2(fmaxf(d[mt][0] + bb0, 0.0f),
                                fmaxf(d[mt][1] + bb1, 0.0f));
                *(float2*)(hf2 + (r + 8) * 132 + col) =
                    make_float2(fmaxf(d[mt][2] + bb0, 0.0f),
                                fmaxf(d[mt][3] + bb1, 0.0f));
            }
        }
        __syncthreads();

        if (stagei == 0) {
            // fold1c: fv[r][q] = hf2[r]·Wf1c[:,q] + bf1c[q]  (exact fp32)
            if (t < 192) {
                const int r = t / 3, q = t - (t / 3) * 3;
                float acc = bf1c[q];
                #pragma unroll 8
                for (int k = 0; k < 128; k++) acc += hf2[r * 132 + k] * Wc1[k * 3 + q];
                fv[t] = acc;
            }
            __syncthreads();
        } else {
            // fold2c + output (exact fp32)
            if (t < 192) {
                const int r = t / 3, q = t - (t / 3) * 3;
                const int p = r >> 5, rr = r & 31;
                float acc = bf2c[q];
                #pragma unroll 8
                for (int k = 0; k < 128; k++) acc += hf2[r * 132 + k] * Wc2[k * 3 + q];
                out[(size_t)(m0 + p) * 96 + rr * 3 + q] = acc * scale + cm[p * 3 + q];
            }
        }
    }
}

// ============================================================================
extern "C" void kernel_launch(void* const* d_in, const int* in_sizes, int n_in,
                              void* d_out, int out_size)
{
    (void)in_sizes; (void)n_in; (void)out_size;
    const float* data = (const float*)d_in[0];
    const int*   perm = (const int*)  d_in[1];
    const float* grid = (const float*)d_in[2];
    const float* We1  = (const float*)d_in[3];
    const float* be1  = (const float*)d_in[4];
    const float* We2  = (const float*)d_in[5];
    const float* be2  = (const float*)d_in[6];
    const float* Wf1a = (const float*)d_in[7];
    const float* bf1a = (const float*)d_in[8];
    const float* Wf1b = (const float*)d_in[9];
    const float* bf1b = (const float*)d_in[10];
    const float* Wf1c = (const float*)d_in[11];
    const float* bf1c = (const float*)d_in[12];
    const float* Wf2a = (const float*)d_in[13];
    const float* bf2a = (const float*)d_in[14];
    const float* Wf2b = (const float*)d_in[15];
    const float* bf2b = (const float*)d_in[16];
    const float* Wf2c = (const float*)d_in[17];
    const float* bf2c = (const float*)d_in[18];
    float* out = (float*)d_out;

    const int fps_smem  = 3 * NN * sizeof(float);      // 98304
    const int knn_smem  = 3 * NN * sizeof(float);      // 98304
    const int enc_smem  = 4544  * sizeof(float);       // 18176
    const int base_smem = 8448  * sizeof(float);       // 33792
    const int fold_smem = 13832 * sizeof(float);       // 55328
    cudaFuncSetAttribute(fps_kernel,  cudaFuncAttributeMaxDynamicSharedMemorySize, fps_smem);
    cudaFuncSetAttribute(knn_kernel,  cudaFuncAttributeMaxDynamicSharedMemorySize, knn_smem);
    cudaFuncSetAttribute(enc_kernel,  cudaFuncAttributeMaxDynamicSharedMemorySize, enc_smem);
    cudaFuncSetAttribute(base_kernel, cudaFuncAttributeMaxDynamicSharedMemorySize, base_smem);
    cudaFuncSetAttribute(fold_kernel, cudaFuncAttributeMaxDynamicSharedMemorySize, fold_smem);

    pack_kernel<<<dim3(128, 5), 256>>>(We2, Wf1a, Wf2a, Wf1b, Wf2b);
    fps_kernel <<<BB, 1024, fps_smem>>>(data);
    knn_kernel <<<(BB * NC) / 8, 256, knn_smem>>>(data, perm);
    enc_kernel <<<MTOT / 2, 256, enc_smem>>>(We1, be1, be2);
    base_kernel<<<dim3(MTOT / 64, 2), 256, base_smem>>>(bf1a, bf2a);
    fold_kernel<<<MTOT / 2, 512, fold_smem>>>(grid, Wf1a, bf1b, Wf1c, bf1c,
                                              Wf2a, bf2b, Wf2c, bf2c, out);
}